// round 1
// baseline (speedup 1.0000x reference)
#include <cuda_runtime.h>
#include <cuda_bf16.h>
#include <math.h>

// ---------------------------------------------------------------------------
// Problem constants (fixed-shape problem)
// ---------------------------------------------------------------------------
#define NMAX 50000
#define EMAX 800000
#define DIM  128
#define HEADS 4
#define CH   32
#define EDIM 16

// ---------------------------------------------------------------------------
// Scratch (static __device__ globals; allocation inside kernel_launch is banned)
// ---------------------------------------------------------------------------
__device__ float g_q[NMAX * DIM];
__device__ float g_k[NMAX * DIM];
__device__ float g_v[NMAX * DIM];
__device__ float g_xr[NMAX * DIM];
__device__ float g_out[NMAX * DIM];   // attention aggregation
__device__ float g_h[NMAX * DIM];     // post-LN1 hidden
__device__ float g_ff1[NMAX * 4 * DIM];
__device__ float g_alpha[EMAX * HEADS];
__device__ float g_m[NMAX * HEADS];
__device__ float g_den[NMAX * HEADS];
__device__ int   g_src[EMAX];
__device__ int   g_dst[EMAX];
__device__ int   g_idx64;

// ---------------------------------------------------------------------------
// Helpers
// ---------------------------------------------------------------------------
__device__ __forceinline__ void atomicMaxFloat(float* addr, float val) {
    if (val >= 0.0f)
        atomicMax((int*)addr, __float_as_int(val));
    else
        atomicMin((unsigned int*)addr, (unsigned int)__float_as_int(val));
}

__device__ __forceinline__ float warpSum(float v) {
#pragma unroll
    for (int off = 16; off; off >>= 1)
        v += __shfl_xor_sync(0xffffffffu, v, off);
    return v;
}

// Block-wide sum for 128 threads, result broadcast to all.
__device__ __forceinline__ float blockSum128(float v, float* sbuf) {
    v = warpSum(v);
    int w = threadIdx.x >> 5;
    if ((threadIdx.x & 31) == 0) sbuf[w] = v;
    __syncthreads();
    float r = sbuf[0] + sbuf[1] + sbuf[2] + sbuf[3];
    __syncthreads();
    return r;
}

// ---------------------------------------------------------------------------
// Index dtype detection + conversion (int64 vs int32 edge_index)
// ---------------------------------------------------------------------------
__global__ void detect_idx_kernel(const int* raw) {
    if (threadIdx.x == 0) {
        int all_hi_zero = 1, any_lo_nonzero = 0;
        for (int i = 0; i < 256; i++) {
            if (raw[2 * i + 1] != 0) all_hi_zero = 0;
            if (raw[2 * i] != 0) any_lo_nonzero = 1;
        }
        g_idx64 = (all_hi_zero && any_lo_nonzero) ? 1 : 0;
    }
}

__global__ void convert_idx_kernel(const void* raw, int E) {
    int i = blockIdx.x * blockDim.x + threadIdx.x;
    if (i >= E) return;
    if (g_idx64) {
        const long long* p = (const long long*)raw;
        g_src[i] = (int)p[i];
        g_dst[i] = (int)p[E + i];
    } else {
        const int* p = (const int*)raw;
        g_src[i] = p[i];
        g_dst[i] = p[E + i];
    }
}

// init m = -inf, den = 0, out = 0
__global__ void init_kernel(int N) {
    int i = blockIdx.x * blockDim.x + threadIdx.x;
    if (i < N * DIM) g_out[i] = 0.0f;
    if (i < N * HEADS) {
        g_m[i] = -INFINITY;
        g_den[i] = 0.0f;
    }
}

// ---------------------------------------------------------------------------
// Tiled SGEMM: C[M,Nout] = A[M,K] @ B[K,Nout] (+ bias / relu / residual+LN)
// BM=64, BN=128, BK=16, 256 threads, 8 rows x 4 cols per thread.
// MODE 0: bias. MODE 1: bias+relu. MODE 2: bias + res + LayerNorm(gamma,beta).
// ---------------------------------------------------------------------------
template <int MODE>
__global__ void __launch_bounds__(256)
sgemm_kernel(const float* __restrict__ A, const float* __restrict__ B,
             const float* __restrict__ bias, float* __restrict__ C,
             int M, int K, int Nout,
             const float* __restrict__ res,
             const float* __restrict__ gamma, const float* __restrict__ betap)
{
    __shared__ float As[16][64];
    __shared__ float Bs[16][128];

    const int m0 = blockIdx.x * 64;
    const int n0 = blockIdx.y * 128;
    const int tid = threadIdx.x;
    const int r = tid >> 5;    // 0..7
    const int c = tid & 31;    // 0..31

    float acc[8][4];
#pragma unroll
    for (int i = 0; i < 8; i++)
#pragma unroll
        for (int j = 0; j < 4; j++) acc[i][j] = 0.0f;

    const int am = tid >> 2;   // 0..63
    const int kg = tid & 3;    // 0..3

    for (int k0 = 0; k0 < K; k0 += 16) {
        // load A tile (transposed into As[k][m])
        float4 av = make_float4(0.f, 0.f, 0.f, 0.f);
        if (m0 + am < M)
            av = *(const float4*)&A[(size_t)(m0 + am) * K + k0 + kg * 4];
        As[kg * 4 + 0][am] = av.x;
        As[kg * 4 + 1][am] = av.y;
        As[kg * 4 + 2][am] = av.z;
        As[kg * 4 + 3][am] = av.w;
        // load B tile
#pragma unroll
        for (int t = 0; t < 8; t++) {
            int i = tid + t * 256;
            int br = i >> 7, bc = i & 127;
            Bs[br][bc] = B[(size_t)(k0 + br) * Nout + n0 + bc];
        }
        __syncthreads();
#pragma unroll
        for (int kk = 0; kk < 16; kk++) {
            float4 bv4 = *(const float4*)&Bs[kk][c * 4];
#pragma unroll
            for (int i = 0; i < 8; i++) {
                float a = As[kk][r * 8 + i];
                acc[i][0] = fmaf(a, bv4.x, acc[i][0]);
                acc[i][1] = fmaf(a, bv4.y, acc[i][1]);
                acc[i][2] = fmaf(a, bv4.z, acc[i][2]);
                acc[i][3] = fmaf(a, bv4.w, acc[i][3]);
            }
        }
        __syncthreads();
    }

    // epilogue
    float bia[4];
#pragma unroll
    for (int j = 0; j < 4; j++) bia[j] = bias[n0 + c * 4 + j];

#pragma unroll
    for (int i = 0; i < 8; i++) {
        int m = m0 + r * 8 + i;
        if (m >= M) continue;   // uniform across warp (r constant within warp)
        if (MODE == 0 || MODE == 1) {
            float4 st;
            st.x = acc[i][0] + bia[0];
            st.y = acc[i][1] + bia[1];
            st.z = acc[i][2] + bia[2];
            st.w = acc[i][3] + bia[3];
            if (MODE == 1) {
                st.x = fmaxf(st.x, 0.f); st.y = fmaxf(st.y, 0.f);
                st.z = fmaxf(st.z, 0.f); st.w = fmaxf(st.w, 0.f);
            }
            *(float4*)&C[(size_t)m * Nout + n0 + c * 4] = st;
        } else {
            // MODE 2: Nout == 128, n0 == 0. Warp (fixed r) owns the full row.
            float tv[4];
            float s = 0.f;
#pragma unroll
            for (int j = 0; j < 4; j++) {
                int n = c * 4 + j;
                tv[j] = acc[i][j] + bia[j] + res[(size_t)m * 128 + n];
                s += tv[j];
            }
            s = warpSum(s);
            float mu = s * (1.0f / 128.0f);
            float vs = 0.f;
#pragma unroll
            for (int j = 0; j < 4; j++) { tv[j] -= mu; vs += tv[j] * tv[j]; }
            vs = warpSum(vs);
            float inv = rsqrtf(vs * (1.0f / 128.0f) + 1e-5f);
#pragma unroll
            for (int j = 0; j < 4; j++) {
                int n = c * 4 + j;
                C[(size_t)m * 128 + n] = tv[j] * inv * gamma[n] + betap[n];
            }
        }
    }
}

// ---------------------------------------------------------------------------
// Edge pass 1: alpha[e,h] = q[dst]·(k[src] + e_proj) / sqrt(C); segment max.
// One warp per edge. We (16x128) + be in smem.
// ---------------------------------------------------------------------------
__global__ void __launch_bounds__(256)
edge_alpha_kernel(const float* __restrict__ eattr,
                  const float* __restrict__ We, const float* __restrict__ be,
                  int E)
{
    __shared__ float sWe[EDIM * DIM];
    __shared__ float sbe[DIM];
    for (int i = threadIdx.x; i < EDIM * DIM; i += 256) sWe[i] = We[i];
    if (threadIdx.x < DIM) sbe[threadIdx.x] = be[threadIdx.x];
    __syncthreads();

    int e = blockIdx.x * 8 + (threadIdx.x >> 5);
    if (e >= E) return;
    int lane = threadIdx.x & 31;
    int s = g_src[e], d = g_dst[e];

    float at[EDIM];
    const float* ap = eattr + (size_t)e * EDIM;
#pragma unroll
    for (int i = 0; i < EDIM; i++) at[i] = __ldg(&ap[i]);

#pragma unroll
    for (int h = 0; h < HEADS; h++) {
        int hc = h * CH + lane;
        float ev = sbe[hc];
#pragma unroll
        for (int i = 0; i < EDIM; i++) ev = fmaf(at[i], sWe[i * DIM + hc], ev);
        float p = g_q[(size_t)d * DIM + hc] * (g_k[(size_t)s * DIM + hc] + ev);
        p = warpSum(p);
        if (lane == 0) {
            p *= 0.17677669529663687f;   // 1/sqrt(32)
            g_alpha[e * HEADS + h] = p;
            atomicMaxFloat(&g_m[d * HEADS + h], p);
        }
    }
}

// ---------------------------------------------------------------------------
// Edge pass 2: a = exp(alpha - m[dst]); segment-sum denom.
// ---------------------------------------------------------------------------
__global__ void edge_exp_kernel(int E) {
    int i = blockIdx.x * blockDim.x + threadIdx.x;
    if (i >= E * HEADS) return;
    int e = i >> 2, h = i & 3;
    int d = g_dst[e];
    float a = expf(g_alpha[i] - g_m[d * HEADS + h]);
    g_alpha[i] = a;
    atomicAdd(&g_den[d * HEADS + h], a);
}

// ---------------------------------------------------------------------------
// Edge pass 3: out[dst] += (a/denom) * (v[src] + e_proj). One warp per edge.
// ---------------------------------------------------------------------------
__global__ void __launch_bounds__(256)
edge_agg_kernel(const float* __restrict__ eattr,
                const float* __restrict__ We, const float* __restrict__ be,
                int E)
{
    __shared__ float sWe[EDIM * DIM];
    __shared__ float sbe[DIM];
    for (int i = threadIdx.x; i < EDIM * DIM; i += 256) sWe[i] = We[i];
    if (threadIdx.x < DIM) sbe[threadIdx.x] = be[threadIdx.x];
    __syncthreads();

    int e = blockIdx.x * 8 + (threadIdx.x >> 5);
    if (e >= E) return;
    int lane = threadIdx.x & 31;
    int s = g_src[e], d = g_dst[e];

    float at[EDIM];
    const float* ap = eattr + (size_t)e * EDIM;
#pragma unroll
    for (int i = 0; i < EDIM; i++) at[i] = __ldg(&ap[i]);

#pragma unroll
    for (int h = 0; h < HEADS; h++) {
        float w = g_alpha[e * HEADS + h] / (g_den[d * HEADS + h] + 1e-16f);
        int hc = h * CH + lane;
        float ev = sbe[hc];
#pragma unroll
        for (int i = 0; i < EDIM; i++) ev = fmaf(at[i], sWe[i * DIM + hc], ev);
        float vj = g_v[(size_t)s * DIM + hc] + ev;
        atomicAdd(&g_out[(size_t)d * DIM + hc], w * vj);
    }
}

// ---------------------------------------------------------------------------
// Node kernel: beta-gated skip + residual + LayerNorm1 -> g_h
// One 128-thread block per node.
// ---------------------------------------------------------------------------
__global__ void __launch_bounds__(128)
node_beta_ln_kernel(const float* __restrict__ x, const float* __restrict__ Wbeta,
                    const float* __restrict__ g1, const float* __restrict__ b1,
                    int N)
{
    __shared__ float sbuf[4];
    int n = blockIdx.x;
    if (n >= N) return;
    int t = threadIdx.x;

    float o  = g_out[(size_t)n * DIM + t];
    float xr = g_xr[(size_t)n * DIM + t];
    // beta logit: [out, xr, out - xr] @ Wbeta[384]
    float z = Wbeta[t] * o + Wbeta[DIM + t] * xr + Wbeta[2 * DIM + t] * (o - xr);
    z = blockSum128(z, sbuf);
    float beta = 1.0f / (1.0f + expf(-z));
    float xs = beta * xr + (1.0f - beta) * o;
    float tv = x[(size_t)n * DIM + t] + xs;

    float mu = blockSum128(tv, sbuf) * (1.0f / 128.0f);
    float dv = tv - mu;
    float var = blockSum128(dv * dv, sbuf) * (1.0f / 128.0f);
    g_h[(size_t)n * DIM + t] = dv * rsqrtf(var + 1e-5f) * g1[t] + b1[t];
}

// ---------------------------------------------------------------------------
// Launch
// ---------------------------------------------------------------------------
extern "C" void kernel_launch(void* const* d_in, const int* in_sizes, int n_in,
                              void* d_out, int out_size)
{
    // inputs per setup_inputs() order
    const float* x      = (const float*)d_in[0];
    const void*  eidx   = d_in[1];
    const float* eattr  = (const float*)d_in[2];
    const float* Wq     = (const float*)d_in[3];
    const float* bq     = (const float*)d_in[4];
    const float* Wk     = (const float*)d_in[5];
    const float* bk     = (const float*)d_in[6];
    const float* Wv     = (const float*)d_in[7];
    const float* bv     = (const float*)d_in[8];
    const float* We     = (const float*)d_in[9];
    const float* be     = (const float*)d_in[10];
    const float* Ws     = (const float*)d_in[11];
    const float* bs     = (const float*)d_in[12];
    const float* Wbeta  = (const float*)d_in[13];
    const float* g1     = (const float*)d_in[14];
    const float* b1     = (const float*)d_in[15];
    const float* Wf1    = (const float*)d_in[16];
    const float* bf1    = (const float*)d_in[17];
    const float* Wf2    = (const float*)d_in[18];
    const float* bf2    = (const float*)d_in[19];
    const float* g2     = (const float*)d_in[20];
    const float* b2     = (const float*)d_in[21];

    const int N = in_sizes[0] / DIM;
    const int E = in_sizes[1] / 2;

    // device-scratch pointers
    float *q, *k, *v, *xr, *h, *ff1;
    cudaGetSymbolAddress((void**)&q,   g_q);
    cudaGetSymbolAddress((void**)&k,   g_k);
    cudaGetSymbolAddress((void**)&v,   g_v);
    cudaGetSymbolAddress((void**)&xr,  g_xr);
    cudaGetSymbolAddress((void**)&h,   g_h);
    cudaGetSymbolAddress((void**)&ff1, g_ff1);

    // 0) index conversion + init
    detect_idx_kernel<<<1, 32>>>((const int*)eidx);
    convert_idx_kernel<<<(E + 255) / 256, 256>>>(eidx, E);
    init_kernel<<<(N * DIM + 255) / 256, 256>>>(N);

    // 1) projections q/k/v/skip
    dim3 gproj((N + 63) / 64, 1);
    sgemm_kernel<0><<<gproj, 256>>>(x, Wq, bq, q,  N, DIM, DIM, nullptr, nullptr, nullptr);
    sgemm_kernel<0><<<gproj, 256>>>(x, Wk, bk, k,  N, DIM, DIM, nullptr, nullptr, nullptr);
    sgemm_kernel<0><<<gproj, 256>>>(x, Wv, bv, v,  N, DIM, DIM, nullptr, nullptr, nullptr);
    sgemm_kernel<0><<<gproj, 256>>>(x, Ws, bs, xr, N, DIM, DIM, nullptr, nullptr, nullptr);

    // 2) edge attention
    edge_alpha_kernel<<<(E + 7) / 8, 256>>>(eattr, We, be, E);
    edge_exp_kernel<<<(E * HEADS + 255) / 256, 256>>>(E);
    edge_agg_kernel<<<(E + 7) / 8, 256>>>(eattr, We, be, E);

    // 3) beta gate + residual + LN1
    node_beta_ln_kernel<<<N, 128>>>(x, Wbeta, g1, b1, N);

    // 4) FFN + residual + LN2 (fused into FF2 epilogue)
    dim3 gff1((N + 63) / 64, 4);
    sgemm_kernel<1><<<gff1, 256>>>(h, Wf1, bf1, ff1, N, DIM, 4 * DIM, nullptr, nullptr, nullptr);
    dim3 gff2((N + 63) / 64, 1);
    sgemm_kernel<2><<<gff2, 256>>>(ff1, Wf2, bf2, (float*)d_out, N, 4 * DIM, DIM, h, g2, b2);
}

// round 2
// speedup vs baseline: 1.0141x; 1.0141x over previous
#include <cuda_runtime.h>
#include <cuda_bf16.h>
#include <math.h>

#define NMAX 50000
#define EMAX 800000
#define DIM  128
#define HEADS 4
#define CH   32
#define EDIM 16

// ---------------------------------------------------------------------------
// Scratch
// ---------------------------------------------------------------------------
__device__ float g_q[NMAX * DIM];
__device__ float g_k[NMAX * DIM];
__device__ float g_v[NMAX * DIM];
__device__ float g_xr[NMAX * DIM];
__device__ float g_h[NMAX * DIM];
__device__ float g_ff1[NMAX * 4 * DIM];
__device__ int   g_src[EMAX];
__device__ int   g_dst[EMAX];
__device__ int2  g_sorted[EMAX];      // (src, edge_id) sorted by dst
__device__ int   g_cnt[NMAX];
__device__ int   g_rowptr[NMAX + 1];
__device__ int   g_woff[NMAX];
__device__ int   g_idx64;

// ---------------------------------------------------------------------------
// Helpers
// ---------------------------------------------------------------------------
__device__ __forceinline__ float warpSum(float v) {
#pragma unroll
    for (int off = 16; off; off >>= 1)
        v += __shfl_xor_sync(0xffffffffu, v, off);
    return v;
}

// ---------------------------------------------------------------------------
// Index dtype detection + conversion + cnt zeroing
// ---------------------------------------------------------------------------
__global__ void detect_idx_kernel(const int* raw) {
    if (threadIdx.x == 0) {
        int all_hi_zero = 1, any_lo_nonzero = 0;
        for (int i = 0; i < 256; i++) {
            if (raw[2 * i + 1] != 0) all_hi_zero = 0;
            if (raw[2 * i] != 0) any_lo_nonzero = 1;
        }
        g_idx64 = (all_hi_zero && any_lo_nonzero) ? 1 : 0;
    }
}

__global__ void convert_idx_kernel(const void* raw, int E, int N) {
    int i = blockIdx.x * blockDim.x + threadIdx.x;
    if (i < N) g_cnt[i] = 0;
    if (i >= E) return;
    if (g_idx64) {
        const long long* p = (const long long*)raw;
        g_src[i] = (int)p[i];
        g_dst[i] = (int)p[E + i];
    } else {
        const int* p = (const int*)raw;
        g_src[i] = p[i];
        g_dst[i] = p[E + i];
    }
}

__global__ void hist_kernel(int E) {
    int i = blockIdx.x * blockDim.x + threadIdx.x;
    if (i < E) atomicAdd(&g_cnt[g_dst[i]], 1);
}

// single-block exclusive scan over g_cnt -> g_rowptr / g_woff
__global__ void __launch_bounds__(1024)
scan_kernel(int N) {
    __shared__ int part[1024];
    int t = threadIdx.x;
    int chunk = (N + 1023) >> 10;
    int lo = t * chunk;
    int hi = min(lo + chunk, N);
    int s = 0;
    for (int i = lo; i < hi; i++) s += g_cnt[i];
    part[t] = s;
    __syncthreads();
    for (int off = 1; off < 1024; off <<= 1) {
        int v = (t >= off) ? part[t - off] : 0;
        __syncthreads();
        part[t] += v;
        __syncthreads();
    }
    int run = (t == 0) ? 0 : part[t - 1];
    for (int i = lo; i < hi; i++) {
        g_rowptr[i] = run;
        g_woff[i] = run;
        run += g_cnt[i];
    }
    if (t == 1023) g_rowptr[N] = part[1023];
}

__global__ void scatter_kernel(int E) {
    int i = blockIdx.x * blockDim.x + threadIdx.x;
    if (i >= E) return;
    int d = g_dst[i];
    int pos = atomicAdd(&g_woff[d], 1);
    g_sorted[pos] = make_int2(g_src[i], i);
}

// ---------------------------------------------------------------------------
// Tiled SGEMM (BM=64,BN=128,BK=16, 256 thr). MODE 0 bias, 1 bias+relu,
// 2 bias+residual+LN.
// ---------------------------------------------------------------------------
template <int MODE>
__global__ void __launch_bounds__(256)
sgemm_kernel(const float* __restrict__ A, const float* __restrict__ B,
             const float* __restrict__ bias, float* __restrict__ C,
             int M, int K, int Nout,
             const float* __restrict__ res,
             const float* __restrict__ gamma, const float* __restrict__ betap)
{
    __shared__ float As[16][64];
    __shared__ float Bs[16][128];

    const int m0 = blockIdx.x * 64;
    const int n0 = blockIdx.y * 128;
    const int tid = threadIdx.x;
    const int r = tid >> 5;
    const int c = tid & 31;

    float acc[8][4];
#pragma unroll
    for (int i = 0; i < 8; i++)
#pragma unroll
        for (int j = 0; j < 4; j++) acc[i][j] = 0.0f;

    const int am = tid >> 2;
    const int kg = tid & 3;

    for (int k0 = 0; k0 < K; k0 += 16) {
        float4 av = make_float4(0.f, 0.f, 0.f, 0.f);
        if (m0 + am < M)
            av = *(const float4*)&A[(size_t)(m0 + am) * K + k0 + kg * 4];
        As[kg * 4 + 0][am] = av.x;
        As[kg * 4 + 1][am] = av.y;
        As[kg * 4 + 2][am] = av.z;
        As[kg * 4 + 3][am] = av.w;
#pragma unroll
        for (int t = 0; t < 8; t++) {
            int i = tid + t * 256;
            int br = i >> 7, bc = i & 127;
            Bs[br][bc] = B[(size_t)(k0 + br) * Nout + n0 + bc];
        }
        __syncthreads();
#pragma unroll
        for (int kk = 0; kk < 16; kk++) {
            float4 bv4 = *(const float4*)&Bs[kk][c * 4];
#pragma unroll
            for (int i = 0; i < 8; i++) {
                float a = As[kk][r * 8 + i];
                acc[i][0] = fmaf(a, bv4.x, acc[i][0]);
                acc[i][1] = fmaf(a, bv4.y, acc[i][1]);
                acc[i][2] = fmaf(a, bv4.z, acc[i][2]);
                acc[i][3] = fmaf(a, bv4.w, acc[i][3]);
            }
        }
        __syncthreads();
    }

    float bia[4];
#pragma unroll
    for (int j = 0; j < 4; j++) bia[j] = bias[n0 + c * 4 + j];

#pragma unroll
    for (int i = 0; i < 8; i++) {
        int m = m0 + r * 8 + i;
        if (m >= M) continue;
        if (MODE == 0 || MODE == 1) {
            float4 st;
            st.x = acc[i][0] + bia[0];
            st.y = acc[i][1] + bia[1];
            st.z = acc[i][2] + bia[2];
            st.w = acc[i][3] + bia[3];
            if (MODE == 1) {
                st.x = fmaxf(st.x, 0.f); st.y = fmaxf(st.y, 0.f);
                st.z = fmaxf(st.z, 0.f); st.w = fmaxf(st.w, 0.f);
            }
            *(float4*)&C[(size_t)m * Nout + n0 + c * 4] = st;
        } else {
            float tv[4];
            float s = 0.f;
#pragma unroll
            for (int j = 0; j < 4; j++) {
                int n = c * 4 + j;
                tv[j] = acc[i][j] + bia[j] + res[(size_t)m * 128 + n];
                s += tv[j];
            }
            s = warpSum(s);
            float mu = s * (1.0f / 128.0f);
            float vs = 0.f;
#pragma unroll
            for (int j = 0; j < 4; j++) { tv[j] -= mu; vs += tv[j] * tv[j]; }
            vs = warpSum(vs);
            float inv = rsqrtf(vs * (1.0f / 128.0f) + 1e-5f);
#pragma unroll
            for (int j = 0; j < 4; j++) {
                int n = c * 4 + j;
                C[(size_t)m * 128 + n] = tv[j] * inv * gamma[n] + betap[n];
            }
        }
    }
}

// Fused q/k/v/skip projections: blockIdx.y selects weight/output.
__global__ void __launch_bounds__(256)
proj4_kernel(const float* __restrict__ A,
             const float* __restrict__ Wq, const float* __restrict__ bq,
             const float* __restrict__ Wk, const float* __restrict__ bk,
             const float* __restrict__ Wv, const float* __restrict__ bv,
             const float* __restrict__ Ws, const float* __restrict__ bs,
             int M)
{
    const float* B;  const float* bias;  float* C;
    switch (blockIdx.y) {
        case 0: B = Wq; bias = bq; C = g_q;  break;
        case 1: B = Wk; bias = bk; C = g_k;  break;
        case 2: B = Wv; bias = bv; C = g_v;  break;
        default: B = Ws; bias = bs; C = g_xr; break;
    }
    __shared__ float As[16][64];
    __shared__ float Bs[16][128];

    const int m0 = blockIdx.x * 64;
    const int tid = threadIdx.x;
    const int r = tid >> 5;
    const int c = tid & 31;

    float acc[8][4];
#pragma unroll
    for (int i = 0; i < 8; i++)
#pragma unroll
        for (int j = 0; j < 4; j++) acc[i][j] = 0.0f;

    const int am = tid >> 2;
    const int kg = tid & 3;

#pragma unroll 1
    for (int k0 = 0; k0 < DIM; k0 += 16) {
        float4 av = make_float4(0.f, 0.f, 0.f, 0.f);
        if (m0 + am < M)
            av = *(const float4*)&A[(size_t)(m0 + am) * DIM + k0 + kg * 4];
        As[kg * 4 + 0][am] = av.x;
        As[kg * 4 + 1][am] = av.y;
        As[kg * 4 + 2][am] = av.z;
        As[kg * 4 + 3][am] = av.w;
#pragma unroll
        for (int t = 0; t < 8; t++) {
            int i = tid + t * 256;
            int br = i >> 7, bc = i & 127;
            Bs[br][bc] = B[(size_t)(k0 + br) * DIM + bc];
        }
        __syncthreads();
#pragma unroll
        for (int kk = 0; kk < 16; kk++) {
            float4 bv4 = *(const float4*)&Bs[kk][c * 4];
#pragma unroll
            for (int i = 0; i < 8; i++) {
                float a = As[kk][r * 8 + i];
                acc[i][0] = fmaf(a, bv4.x, acc[i][0]);
                acc[i][1] = fmaf(a, bv4.y, acc[i][1]);
                acc[i][2] = fmaf(a, bv4.z, acc[i][2]);
                acc[i][3] = fmaf(a, bv4.w, acc[i][3]);
            }
        }
        __syncthreads();
    }

    float bia[4];
#pragma unroll
    for (int j = 0; j < 4; j++) bia[j] = bias[c * 4 + j];
#pragma unroll
    for (int i = 0; i < 8; i++) {
        int m = m0 + r * 8 + i;
        if (m >= M) continue;
        float4 st;
        st.x = acc[i][0] + bia[0];
        st.y = acc[i][1] + bia[1];
        st.z = acc[i][2] + bia[2];
        st.w = acc[i][3] + bia[3];
        *(float4*)&C[(size_t)m * DIM + c * 4] = st;
    }
}

// ---------------------------------------------------------------------------
// Fused attention (single pass, no max-subtraction) + beta gate + LN1.
// 256-thread block = 2 groups of 128; each group handles one node per iter,
// 4 iterations => 8 nodes per block. We/be staged once per block.
// ---------------------------------------------------------------------------
#define NODES_PER_BLK 8
__global__ void __launch_bounds__(256)
node_attn_kernel(const float* __restrict__ eattr,
                 const float* __restrict__ We, const float* __restrict__ be,
                 const float* __restrict__ x,  const float* __restrict__ Wbeta,
                 const float* __restrict__ g1, const float* __restrict__ b1,
                 int N)
{
    __shared__ float sWe[EDIM * DIM];
    __shared__ float sbe[DIM];
    __shared__ float sred[2][4];

    for (int i = threadIdx.x; i < EDIM * DIM; i += 256) sWe[i] = We[i];
    if (threadIdx.x < DIM) sbe[threadIdx.x] = be[threadIdx.x];
    __syncthreads();

    const int group = threadIdx.x >> 7;   // 0..1
    const int t = threadIdx.x & 127;      // channel within row
    const int lane = t & 31;

#pragma unroll 1
    for (int it = 0; it < NODES_PER_BLK / 2; it++) {
        int n = blockIdx.x * NODES_PER_BLK + it * 2 + group;
        bool active = (n < N);

        float acc = 0.f, den = 0.f, qv = 0.f;
        if (active) {
            qv = g_q[(size_t)n * DIM + t];
            int beg = g_rowptr[n], end = g_rowptr[n + 1];
            for (int p = beg; p < end; p++) {
                int2 se = g_sorted[p];
                const float4* ap = (const float4*)(eattr + (size_t)se.y * EDIM);
                float4 a0 = __ldg(ap + 0);
                float4 a1 = __ldg(ap + 1);
                float4 a2 = __ldg(ap + 2);
                float4 a3 = __ldg(ap + 3);
                float ev = sbe[t];
                ev = fmaf(a0.x, sWe[0 * DIM + t], ev);
                ev = fmaf(a0.y, sWe[1 * DIM + t], ev);
                ev = fmaf(a0.z, sWe[2 * DIM + t], ev);
                ev = fmaf(a0.w, sWe[3 * DIM + t], ev);
                ev = fmaf(a1.x, sWe[4 * DIM + t], ev);
                ev = fmaf(a1.y, sWe[5 * DIM + t], ev);
                ev = fmaf(a1.z, sWe[6 * DIM + t], ev);
                ev = fmaf(a1.w, sWe[7 * DIM + t], ev);
                ev = fmaf(a2.x, sWe[8 * DIM + t], ev);
                ev = fmaf(a2.y, sWe[9 * DIM + t], ev);
                ev = fmaf(a2.z, sWe[10 * DIM + t], ev);
                ev = fmaf(a2.w, sWe[11 * DIM + t], ev);
                ev = fmaf(a3.x, sWe[12 * DIM + t], ev);
                ev = fmaf(a3.y, sWe[13 * DIM + t], ev);
                ev = fmaf(a3.z, sWe[14 * DIM + t], ev);
                ev = fmaf(a3.w, sWe[15 * DIM + t], ev);

                float kv = g_k[(size_t)se.x * DIM + t] + ev;
                float alpha = warpSum(qv * kv) * 0.17677669529663687f; // /sqrt(32)
                float a = __expf(alpha);
                den += a;
                acc = fmaf(a, g_v[(size_t)se.x * DIM + t] + ev, acc);
            }
        }

        float o = acc / (den + 1e-16f);
        float xr = active ? g_xr[(size_t)n * DIM + t] : 0.f;
        float z = active
            ? (Wbeta[t] * o + Wbeta[DIM + t] * xr + Wbeta[2 * DIM + t] * (o - xr))
            : 0.f;
        // group-local sum over 128 threads (uniform __syncthreads)
        z = warpSum(z);
        if (lane == 0) sred[group][t >> 5] = z;
        __syncthreads();
        z = sred[group][0] + sred[group][1] + sred[group][2] + sred[group][3];
        __syncthreads();

        float beta = 1.0f / (1.0f + __expf(-z));
        float xs = beta * xr + (1.0f - beta) * o;
        float tv = (active ? x[(size_t)n * DIM + t] : 0.f) + xs;

        float s = warpSum(tv);
        if (lane == 0) sred[group][t >> 5] = s;
        __syncthreads();
        float mu = (sred[group][0] + sred[group][1] + sred[group][2] + sred[group][3])
                   * (1.0f / 128.0f);
        __syncthreads();

        float dv = tv - mu;
        float vs = warpSum(dv * dv);
        if (lane == 0) sred[group][t >> 5] = vs;
        __syncthreads();
        float var = (sred[group][0] + sred[group][1] + sred[group][2] + sred[group][3])
                    * (1.0f / 128.0f);
        __syncthreads();

        if (active)
            g_h[(size_t)n * DIM + t] = dv * rsqrtf(var + 1e-5f) * g1[t] + b1[t];
    }
}

// ---------------------------------------------------------------------------
// Launch
// ---------------------------------------------------------------------------
extern "C" void kernel_launch(void* const* d_in, const int* in_sizes, int n_in,
                              void* d_out, int out_size)
{
    const float* x      = (const float*)d_in[0];
    const void*  eidx   = d_in[1];
    const float* eattr  = (const float*)d_in[2];
    const float* Wq     = (const float*)d_in[3];
    const float* bq     = (const float*)d_in[4];
    const float* Wk     = (const float*)d_in[5];
    const float* bk     = (const float*)d_in[6];
    const float* Wv     = (const float*)d_in[7];
    const float* bv     = (const float*)d_in[8];
    const float* We     = (const float*)d_in[9];
    const float* be     = (const float*)d_in[10];
    const float* Ws     = (const float*)d_in[11];
    const float* bs     = (const float*)d_in[12];
    const float* Wbeta  = (const float*)d_in[13];
    const float* g1     = (const float*)d_in[14];
    const float* b1     = (const float*)d_in[15];
    const float* Wf1    = (const float*)d_in[16];
    const float* bf1    = (const float*)d_in[17];
    const float* Wf2    = (const float*)d_in[18];
    const float* bf2    = (const float*)d_in[19];
    const float* g2     = (const float*)d_in[20];
    const float* b2     = (const float*)d_in[21];

    const int N = in_sizes[0] / DIM;
    const int E = in_sizes[1] / 2;

    float *h, *ff1;
    cudaGetSymbolAddress((void**)&h,   g_h);
    cudaGetSymbolAddress((void**)&ff1, g_ff1);

    // 0) index conversion + CSR build
    detect_idx_kernel<<<1, 32>>>((const int*)eidx);
    convert_idx_kernel<<<(E + 255) / 256, 256>>>(eidx, E, N);
    hist_kernel<<<(E + 255) / 256, 256>>>(E);
    scan_kernel<<<1, 1024>>>(N);
    scatter_kernel<<<(E + 255) / 256, 256>>>(E);

    // 1) projections q/k/v/skip (single fused launch)
    dim3 gproj((N + 63) / 64, 4);
    proj4_kernel<<<gproj, 256>>>(x, Wq, bq, Wk, bk, Wv, bv, Ws, bs, N);

    // 2) fused attention + beta gate + LN1
    node_attn_kernel<<<(N + NODES_PER_BLK - 1) / NODES_PER_BLK, 256>>>(
        eattr, We, be, x, Wbeta, g1, b1, N);

    // 3) FFN + residual + LN2
    dim3 gff1((N + 63) / 64, 4);
    sgemm_kernel<1><<<gff1, 256>>>(h, Wf1, bf1, ff1, N, DIM, 4 * DIM,
                                   nullptr, nullptr, nullptr);
    dim3 gff2((N + 63) / 64, 1);
    sgemm_kernel<2><<<gff2, 256>>>(ff1, Wf2, bf2, (float*)d_out, N, 4 * DIM, DIM,
                                   h, g2, b2);
}

// round 3
// speedup vs baseline: 1.4354x; 1.4154x over previous
#include <cuda_runtime.h>
#include <cuda_bf16.h>
#include <math.h>

#define NMAX 50000
#define EMAX 800000
#define DIM  128
#define HEADS 4
#define CH   32
#define EDIM 16
#define QSCALE 0.17677669529663687f   // 1/sqrt(32)

// ---------------------------------------------------------------------------
// Scratch
// ---------------------------------------------------------------------------
__device__ float g_q[NMAX * DIM];
__device__ float g_k[NMAX * DIM];
__device__ float g_v[NMAX * DIM];
__device__ float g_xr[NMAX * DIM];
__device__ float g_h[NMAX * DIM];
__device__ float g_ff1[NMAX * 4 * DIM];
__device__ float g_qwe[(size_t)NMAX * 64];   // per node, per head, 16 (pre-scaled 0.5)
__device__ float g_qbe[NMAX * 4];
__device__ int   g_src[EMAX];
__device__ int   g_dst[EMAX];
__device__ int2  g_sorted[EMAX];
__device__ int   g_cnt[NMAX];
__device__ int   g_rowptr[NMAX + 1];
__device__ int   g_woff[NMAX];
__device__ int   g_bsum[64];
__device__ int   g_boff[64];
__device__ int   g_idx64;

// ---------------------------------------------------------------------------
// Helpers
// ---------------------------------------------------------------------------
__device__ __forceinline__ float warpSum(float v) {
#pragma unroll
    for (int off = 16; off; off >>= 1)
        v += __shfl_xor_sync(0xffffffffu, v, off);
    return v;
}

// ---------------------------------------------------------------------------
// Index detect / convert (+fused histogram)
// ---------------------------------------------------------------------------
__global__ void detect_idx_kernel(const int* raw) {
    if (threadIdx.x == 0) {
        int all_hi_zero = 1, any_lo_nonzero = 0;
        for (int i = 0; i < 256; i++) {
            if (raw[2 * i + 1] != 0) all_hi_zero = 0;
            if (raw[2 * i] != 0) any_lo_nonzero = 1;
        }
        g_idx64 = (all_hi_zero && any_lo_nonzero) ? 1 : 0;
    }
}

__global__ void zero_cnt_kernel(int N) {
    int i = blockIdx.x * blockDim.x + threadIdx.x;
    if (i < N) g_cnt[i] = 0;
}

__global__ void convert_idx_kernel(const void* raw, int E) {
    int i = blockIdx.x * blockDim.x + threadIdx.x;
    if (i >= E) return;
    int s, d;
    if (g_idx64) {
        const long long* p = (const long long*)raw;
        s = (int)p[i];
        d = (int)p[E + i];
    } else {
        const int* p = (const int*)raw;
        s = p[i];
        d = p[E + i];
    }
    g_src[i] = s;
    g_dst[i] = d;
    atomicAdd(&g_cnt[d], 1);
}

// ---------------------------------------------------------------------------
// 3-phase exclusive scan of g_cnt -> g_rowptr/g_woff
// ---------------------------------------------------------------------------
__global__ void __launch_bounds__(1024)
scanA_kernel(int N) {
    __shared__ int wsum[32];
    int t = threadIdx.x;
    int i = blockIdx.x * 1024 + t;
    int v = (i < N) ? g_cnt[i] : 0;
    int inc = v;
#pragma unroll
    for (int off = 1; off < 32; off <<= 1) {
        int u = __shfl_up_sync(0xffffffffu, inc, off);
        if ((t & 31) >= off) inc += u;
    }
    if ((t & 31) == 31) wsum[t >> 5] = inc;
    __syncthreads();
    if (t < 32) {
        int w = wsum[t];
        int wi = w;
#pragma unroll
        for (int off = 1; off < 32; off <<= 1) {
            int u = __shfl_up_sync(0xffffffffu, wi, off);
            if (t >= off) wi += u;
        }
        wsum[t] = wi - w;   // exclusive warp offset
    }
    __syncthreads();
    int exc = inc - v + wsum[t >> 5];
    if (i < N) g_rowptr[i] = exc;
    if (t == 1023) g_bsum[blockIdx.x] = exc + v;
}

__global__ void scanB_kernel(int nb, int N, int E) {
    int lane = threadIdx.x;   // 32 threads
    int v0 = (lane < nb) ? g_bsum[lane] : 0;
    int v1 = (32 + lane < nb) ? g_bsum[32 + lane] : 0;
    int i0 = v0, i1 = v1;
#pragma unroll
    for (int off = 1; off < 32; off <<= 1) {
        int u = __shfl_up_sync(0xffffffffu, i0, off);
        if (lane >= off) i0 += u;
        int u2 = __shfl_up_sync(0xffffffffu, i1, off);
        if (lane >= off) i1 += u2;
    }
    int tot0 = __shfl_sync(0xffffffffu, i0, 31);
    i1 += tot0;
    g_boff[lane] = i0 - v0;
    g_boff[32 + lane] = i1 - v1;
    if (lane == 0) g_rowptr[N] = E;
}

__global__ void __launch_bounds__(1024)
scanC_kernel(int N) {
    int i = blockIdx.x * 1024 + threadIdx.x;
    if (i < N) {
        int r = g_rowptr[i] + g_boff[blockIdx.x];
        g_rowptr[i] = r;
        g_woff[i] = r;
    }
}

__global__ void scatter_kernel(int E) {
    int i = blockIdx.x * blockDim.x + threadIdx.x;
    if (i >= E) return;
    int d = g_dst[i];
    int pos = atomicAdd(&g_woff[d], 1);
    g_sorted[pos] = make_int2(g_src[i], i);
}

// ---------------------------------------------------------------------------
// 128x128x16 SGEMM, 256 threads, 8x8 microtile.
// MODE 0: (acc+bias)*scale. MODE 1: relu(acc+bias). MODE 2: bias+res+LN.
// ---------------------------------------------------------------------------
template <int MODE>
__global__ void __launch_bounds__(256)
sgemm128(const float* __restrict__ A, const float* __restrict__ B,
         const float* __restrict__ bias, float* __restrict__ C,
         int M, int K, int Nout,
         const float* __restrict__ res, const float* __restrict__ gamma,
         const float* __restrict__ betap, float scale)
{
    __shared__ float As[16][128];
    __shared__ float Bs[16][128];
    const int tid = threadIdx.x;
    const int m0 = blockIdx.x * 128;
    const int n0 = blockIdx.y * 128;
    const int tx = tid & 15, ty = tid >> 4;

    float acc[8][8];
#pragma unroll
    for (int i = 0; i < 8; i++)
#pragma unroll
        for (int j = 0; j < 8; j++) acc[i][j] = 0.f;

    for (int k0 = 0; k0 < K; k0 += 16) {
#pragma unroll
        for (int t = 0; t < 2; t++) {
            int idx = tid + t * 256;
            int ar = idx >> 2, kq = idx & 3;
            float4 av = make_float4(0.f, 0.f, 0.f, 0.f);
            if (m0 + ar < M)
                av = *(const float4*)&A[(size_t)(m0 + ar) * K + k0 + kq * 4];
            As[kq * 4 + 0][ar] = av.x;
            As[kq * 4 + 1][ar] = av.y;
            As[kq * 4 + 2][ar] = av.z;
            As[kq * 4 + 3][ar] = av.w;
            int br = idx >> 5, c4 = idx & 31;
            *(float4*)&Bs[br][c4 * 4] =
                *(const float4*)&B[(size_t)(k0 + br) * Nout + n0 + c4 * 4];
        }
        __syncthreads();
#pragma unroll
        for (int kk = 0; kk < 16; kk++) {
            float4 a0 = *(float4*)&As[kk][ty * 8];
            float4 a1 = *(float4*)&As[kk][ty * 8 + 4];
            float4 b0 = *(float4*)&Bs[kk][tx * 8];
            float4 b1 = *(float4*)&Bs[kk][tx * 8 + 4];
            float ar_[8] = {a0.x, a0.y, a0.z, a0.w, a1.x, a1.y, a1.z, a1.w};
            float br_[8] = {b0.x, b0.y, b0.z, b0.w, b1.x, b1.y, b1.z, b1.w};
#pragma unroll
            for (int i = 0; i < 8; i++)
#pragma unroll
                for (int j = 0; j < 8; j++)
                    acc[i][j] = fmaf(ar_[i], br_[j], acc[i][j]);
        }
        __syncthreads();
    }

    float bia[8];
#pragma unroll
    for (int j = 0; j < 8; j++) bia[j] = bias[n0 + tx * 8 + j];

    if (MODE == 0 || MODE == 1) {
#pragma unroll
        for (int i = 0; i < 8; i++) {
            int m = m0 + ty * 8 + i;
            if (m >= M) continue;
            float st[8];
#pragma unroll
            for (int j = 0; j < 8; j++) {
                float v = acc[i][j] + bia[j];
                if (MODE == 1) v = fmaxf(v, 0.f);
                st[j] = v * scale;
            }
            *(float4*)&C[(size_t)m * Nout + n0 + tx * 8]     = *(float4*)&st[0];
            *(float4*)&C[(size_t)m * Nout + n0 + tx * 8 + 4] = *(float4*)&st[4];
        }
    } else {
        // MODE 2: Nout==128, n0==0. Row owned by 16 lanes (same ty) = half warp.
        unsigned hmask = 0xFFFFu << (((tid >> 4) & 1) * 16);
#pragma unroll
        for (int i = 0; i < 8; i++) {
            int m = m0 + ty * 8 + i;
            if (m < M) {
                float tv[8];
                float s = 0.f;
#pragma unroll
                for (int j = 0; j < 8; j++) {
                    tv[j] = acc[i][j] + bia[j] + res[(size_t)m * 128 + tx * 8 + j];
                    s += tv[j];
                }
#pragma unroll
                for (int off = 1; off < 16; off <<= 1)
                    s += __shfl_xor_sync(hmask, s, off);
                float mu = s * (1.0f / 128.0f);
                float vs = 0.f;
#pragma unroll
                for (int j = 0; j < 8; j++) { tv[j] -= mu; vs += tv[j] * tv[j]; }
#pragma unroll
                for (int off = 1; off < 16; off <<= 1)
                    vs += __shfl_xor_sync(hmask, vs, off);
                float inv = rsqrtf(vs * (1.0f / 128.0f) + 1e-5f);
                float st[8];
#pragma unroll
                for (int j = 0; j < 8; j++) {
                    int n = tx * 8 + j;
                    st[j] = tv[j] * inv * gamma[n] + betap[n];
                }
                *(float4*)&C[(size_t)m * 128 + tx * 8]     = *(float4*)&st[0];
                *(float4*)&C[(size_t)m * 128 + tx * 8 + 4] = *(float4*)&st[4];
            }
        }
    }
}

// Fused q/k/v/skip projections (q scaled by 1/sqrt(C) at store).
__global__ void __launch_bounds__(256)
proj4_kernel(const float* __restrict__ A,
             const float* __restrict__ Wq, const float* __restrict__ bq,
             const float* __restrict__ Wk, const float* __restrict__ bk,
             const float* __restrict__ Wv, const float* __restrict__ bv,
             const float* __restrict__ Ws, const float* __restrict__ bs,
             int M)
{
    const float* B; const float* bias; float* C; float scale;
    switch (blockIdx.y) {
        case 0: B = Wq; bias = bq; C = g_q;  scale = QSCALE; break;
        case 1: B = Wk; bias = bk; C = g_k;  scale = 1.f;    break;
        case 2: B = Wv; bias = bv; C = g_v;  scale = 1.f;    break;
        default: B = Ws; bias = bs; C = g_xr; scale = 1.f;   break;
    }
    __shared__ float As[16][128];
    __shared__ float Bs[16][128];
    const int tid = threadIdx.x;
    const int m0 = blockIdx.x * 128;
    const int tx = tid & 15, ty = tid >> 4;

    float acc[8][8];
#pragma unroll
    for (int i = 0; i < 8; i++)
#pragma unroll
        for (int j = 0; j < 8; j++) acc[i][j] = 0.f;

#pragma unroll 1
    for (int k0 = 0; k0 < DIM; k0 += 16) {
#pragma unroll
        for (int t = 0; t < 2; t++) {
            int idx = tid + t * 256;
            int ar = idx >> 2, kq = idx & 3;
            float4 av = make_float4(0.f, 0.f, 0.f, 0.f);
            if (m0 + ar < M)
                av = *(const float4*)&A[(size_t)(m0 + ar) * DIM + k0 + kq * 4];
            As[kq * 4 + 0][ar] = av.x;
            As[kq * 4 + 1][ar] = av.y;
            As[kq * 4 + 2][ar] = av.z;
            As[kq * 4 + 3][ar] = av.w;
            int br = idx >> 5, c4 = idx & 31;
            *(float4*)&Bs[br][c4 * 4] =
                *(const float4*)&B[(size_t)(k0 + br) * DIM + c4 * 4];
        }
        __syncthreads();
#pragma unroll
        for (int kk = 0; kk < 16; kk++) {
            float4 a0 = *(float4*)&As[kk][ty * 8];
            float4 a1 = *(float4*)&As[kk][ty * 8 + 4];
            float4 b0 = *(float4*)&Bs[kk][tx * 8];
            float4 b1 = *(float4*)&Bs[kk][tx * 8 + 4];
            float ar_[8] = {a0.x, a0.y, a0.z, a0.w, a1.x, a1.y, a1.z, a1.w};
            float br_[8] = {b0.x, b0.y, b0.z, b0.w, b1.x, b1.y, b1.z, b1.w};
#pragma unroll
            for (int i = 0; i < 8; i++)
#pragma unroll
                for (int j = 0; j < 8; j++)
                    acc[i][j] = fmaf(ar_[i], br_[j], acc[i][j]);
        }
        __syncthreads();
    }

    float bia[8];
#pragma unroll
    for (int j = 0; j < 8; j++) bia[j] = bias[tx * 8 + j];
#pragma unroll
    for (int i = 0; i < 8; i++) {
        int m = m0 + ty * 8 + i;
        if (m >= M) continue;
        float st[8];
#pragma unroll
        for (int j = 0; j < 8; j++) st[j] = (acc[i][j] + bia[j]) * scale;
        *(float4*)&C[(size_t)m * DIM + tx * 8]     = *(float4*)&st[0];
        *(float4*)&C[(size_t)m * DIM + tx * 8 + 4] = *(float4*)&st[4];
    }
}

// ---------------------------------------------------------------------------
// qwe[n,h,i] = 0.5 * sum_c q[n,h*32+c] * We[i, h*32+c]   (q already q-scaled)
// qbe[n,h]   =       sum_c q[n,h*32+c] * be[h*32+c]
// ---------------------------------------------------------------------------
__global__ void __launch_bounds__(256)
qwe_kernel(const float* __restrict__ We, const float* __restrict__ be, int N)
{
    __shared__ float sWe[EDIM * DIM];
    __shared__ float sq[4][DIM];
    __shared__ float sbe[DIM];
    int tid = threadIdx.x;
    for (int i = tid; i < EDIM * DIM; i += 256) sWe[i] = We[i];
    if (tid < DIM) sbe[tid] = be[tid];
    int n0 = blockIdx.x * 4;
    for (int i = tid; i < 4 * DIM; i += 256) {
        int nn = i >> 7, c = i & 127;
        sq[nn][c] = (n0 + nn < N) ? g_q[(size_t)(n0 + nn) * DIM + c] : 0.f;
    }
    __syncthreads();
    int nn = tid >> 6, r = tid & 63, h = r >> 4, i = r & 15;
    int n = n0 + nn;
    if (n >= N) return;
    float a = 0.f;
#pragma unroll
    for (int c = 0; c < 32; c++)
        a = fmaf(sq[nn][h * 32 + c], sWe[i * DIM + h * 32 + c], a);
    g_qwe[(size_t)n * 64 + h * 16 + i] = 0.5f * a;
    if (i == 0) {
        float qb = 0.f;
#pragma unroll
        for (int c = 0; c < 32; c++)
            qb = fmaf(sq[nn][h * 32 + c], sbe[h * 32 + c], qb);
        g_qbe[n * 4 + h] = qb;
    }
}

// ---------------------------------------------------------------------------
// Warp-per-node fused attention + beta gate + LN1 (factorized edge proj).
// Thread holds channels {lane, 32+lane, 64+lane, 96+lane} (one per head).
// ---------------------------------------------------------------------------
__global__ void __launch_bounds__(128)
node_attn_kernel(const float* __restrict__ eattr,
                 const float* __restrict__ We, const float* __restrict__ be,
                 const float* __restrict__ x,  const float* __restrict__ Wbeta,
                 const float* __restrict__ g1, const float* __restrict__ b1,
                 int N)
{
    const int lane = threadIdx.x & 31;
    const int warp = blockIdx.x * (blockDim.x >> 5) + (threadIdx.x >> 5);
    const int nwarps = gridDim.x * (blockDim.x >> 5);
    const int j = lane & 15;

    // persistent We column registers (channel = h*32+lane fixed per thread)
    float rWe[16][4];
#pragma unroll
    for (int i = 0; i < 16; i++)
#pragma unroll
        for (int h = 0; h < 4; h++)
            rWe[i][h] = We[i * DIM + h * 32 + lane];
    float rbe[4];
#pragma unroll
    for (int h = 0; h < 4; h++) rbe[h] = be[h * 32 + lane];

    for (int n = warp; n < N; n += nwarps) {
        float q4[4], qwe4[4], qbe4[4];
        float acc[4] = {0.f, 0.f, 0.f, 0.f};
        float s4[4]  = {0.f, 0.f, 0.f, 0.f};
        float den[4] = {0.f, 0.f, 0.f, 0.f};
#pragma unroll
        for (int h = 0; h < 4; h++) {
            q4[h]   = g_q[(size_t)n * DIM + h * 32 + lane];
            qwe4[h] = g_qwe[(size_t)n * 64 + h * 16 + j];
            qbe4[h] = g_qbe[n * 4 + h];
        }
        int beg = g_rowptr[n], end = g_rowptr[n + 1];
        for (int p = beg; p < end; p++) {
            int2 se = g_sorted[p];
            const float* kp = g_k + (size_t)se.x * DIM + lane;
            const float* vp = g_v + (size_t)se.x * DIM + lane;
            float at = __ldg(&eattr[(size_t)se.y * EDIM + j]);
            float k0 = kp[0], k1 = kp[32], k2 = kp[64], k3 = kp[96];
            float v0 = vp[0], v1 = vp[32], v2 = vp[64], v3 = vp[96];
            float p0 = fmaf(q4[0], k0, at * qwe4[0]);
            float p1 = fmaf(q4[1], k1, at * qwe4[1]);
            float p2 = fmaf(q4[2], k2, at * qwe4[2]);
            float p3 = fmaf(q4[3], k3, at * qwe4[3]);
#pragma unroll
            for (int off = 16; off; off >>= 1) {
                p0 += __shfl_xor_sync(0xffffffffu, p0, off);
                p1 += __shfl_xor_sync(0xffffffffu, p1, off);
                p2 += __shfl_xor_sync(0xffffffffu, p2, off);
                p3 += __shfl_xor_sync(0xffffffffu, p3, off);
            }
            float a0 = __expf(p0 + qbe4[0]);
            float a1 = __expf(p1 + qbe4[1]);
            float a2 = __expf(p2 + qbe4[2]);
            float a3 = __expf(p3 + qbe4[3]);
            den[0] += a0; den[1] += a1; den[2] += a2; den[3] += a3;
            acc[0] = fmaf(a0, v0, acc[0]);
            acc[1] = fmaf(a1, v1, acc[1]);
            acc[2] = fmaf(a2, v2, acc[2]);
            acc[3] = fmaf(a3, v3, acc[3]);
            s4[0] = fmaf(a0, at, s4[0]);
            s4[1] = fmaf(a1, at, s4[1]);
            s4[2] = fmaf(a2, at, s4[2]);
            s4[3] = fmaf(a3, at, s4[3]);
        }

        // unfactor edge projection + finish softmax-weighted mean
        float o[4];
#pragma unroll
        for (int h = 0; h < 4; h++) {
            float ev = den[h] * rbe[h];
#pragma unroll
            for (int i = 0; i < 16; i++)
                ev = fmaf(__shfl_sync(0xffffffffu, s4[h], i), rWe[i][h], ev);
            o[h] = (acc[h] + ev) / (den[h] + 1e-16f);
        }

        // beta gate
        float xr4[4], z = 0.f;
#pragma unroll
        for (int h = 0; h < 4; h++) {
            int c = h * 32 + lane;
            xr4[h] = g_xr[(size_t)n * DIM + c];
            z += Wbeta[c] * o[h] + Wbeta[DIM + c] * xr4[h]
               + Wbeta[2 * DIM + c] * (o[h] - xr4[h]);
        }
        z = warpSum(z);
        float beta = 1.0f / (1.0f + __expf(-z));

        float tv[4], ts = 0.f;
#pragma unroll
        for (int h = 0; h < 4; h++) {
            int c = h * 32 + lane;
            tv[h] = x[(size_t)n * DIM + c] + beta * xr4[h] + (1.0f - beta) * o[h];
            ts += tv[h];
        }
        float mu = warpSum(ts) * (1.0f / 128.0f);
        float vs = 0.f;
#pragma unroll
        for (int h = 0; h < 4; h++) { tv[h] -= mu; vs += tv[h] * tv[h]; }
        float var = warpSum(vs) * (1.0f / 128.0f);
        float inv = rsqrtf(var + 1e-5f);
#pragma unroll
        for (int h = 0; h < 4; h++) {
            int c = h * 32 + lane;
            g_h[(size_t)n * DIM + c] = tv[h] * inv * g1[c] + b1[c];
        }
    }
}

// ---------------------------------------------------------------------------
// Launch
// ---------------------------------------------------------------------------
extern "C" void kernel_launch(void* const* d_in, const int* in_sizes, int n_in,
                              void* d_out, int out_size)
{
    const float* x      = (const float*)d_in[0];
    const void*  eidx   = d_in[1];
    const float* eattr  = (const float*)d_in[2];
    const float* Wq     = (const float*)d_in[3];
    const float* bq     = (const float*)d_in[4];
    const float* Wk     = (const float*)d_in[5];
    const float* bk     = (const float*)d_in[6];
    const float* Wv     = (const float*)d_in[7];
    const float* bv     = (const float*)d_in[8];
    const float* We     = (const float*)d_in[9];
    const float* be     = (const float*)d_in[10];
    const float* Ws     = (const float*)d_in[11];
    const float* bs     = (const float*)d_in[12];
    const float* Wbeta  = (const float*)d_in[13];
    const float* g1     = (const float*)d_in[14];
    const float* b1     = (const float*)d_in[15];
    const float* Wf1    = (const float*)d_in[16];
    const float* bf1    = (const float*)d_in[17];
    const float* Wf2    = (const float*)d_in[18];
    const float* bf2    = (const float*)d_in[19];
    const float* g2     = (const float*)d_in[20];
    const float* b2     = (const float*)d_in[21];

    const int N = in_sizes[0] / DIM;
    const int E = in_sizes[1] / 2;

    float *h, *ff1;
    cudaGetSymbolAddress((void**)&h,   g_h);
    cudaGetSymbolAddress((void**)&ff1, g_ff1);

    const int nb = (N + 1023) / 1024;

    // 0) CSR build
    detect_idx_kernel<<<1, 32>>>((const int*)eidx);
    zero_cnt_kernel<<<(N + 255) / 256, 256>>>(N);
    convert_idx_kernel<<<(E + 255) / 256, 256>>>(eidx, E);
    scanA_kernel<<<nb, 1024>>>(N);
    scanB_kernel<<<1, 32>>>(nb, N, E);
    scanC_kernel<<<nb, 1024>>>(N);
    scatter_kernel<<<(E + 255) / 256, 256>>>(E);

    // 1) projections (q scaled by 1/sqrt(C))
    dim3 gproj((N + 127) / 128, 4);
    proj4_kernel<<<gproj, 256>>>(x, Wq, bq, Wk, bk, Wv, bv, Ws, bs, N);

    // 2) per-node q@We^T precompute
    qwe_kernel<<<(N + 3) / 4, 256>>>(We, be, N);

    // 3) fused attention + beta + LN1
    node_attn_kernel<<<1184, 128>>>(eattr, We, be, x, Wbeta, g1, b1, N);

    // 4) FFN + residual + LN2
    dim3 gff1((N + 127) / 128, 4);
    sgemm128<1><<<gff1, 256>>>(h, Wf1, bf1, ff1, N, DIM, 4 * DIM,
                               nullptr, nullptr, nullptr, 1.f);
    dim3 gff2((N + 127) / 128, 1);
    sgemm128<2><<<gff2, 256>>>(ff1, Wf2, bf2, (float*)d_out, N, 4 * DIM, DIM,
                               h, g2, b2, 1.f);
}

// round 4
// speedup vs baseline: 2.1070x; 1.4679x over previous
#include <cuda_runtime.h>
#include <cuda_bf16.h>
#include <math.h>

#define NMAX 50000
#define EMAX 800000
#define DIM  128
#define HEADS 4
#define CH   32
#define EDIM 16
#define QSCALE 0.17677669529663687f   // 1/sqrt(32)

// ---------------------------------------------------------------------------
// Scratch
// ---------------------------------------------------------------------------
__device__ float g_q[NMAX * DIM];
__device__ float g_k[NMAX * DIM];
__device__ float g_v[NMAX * DIM];
__device__ float g_xr[NMAX * DIM];
__device__ float g_h[NMAX * DIM];
__device__ float g_ff1[NMAX * 4 * DIM];
__device__ float g_qwe[(size_t)NMAX * 64];
__device__ float g_qbe[NMAX * 4];
__device__ int   g_src[EMAX];
__device__ int   g_dst[EMAX];
__device__ int2  g_sorted[EMAX];
__device__ int   g_cnt[NMAX];
__device__ int   g_rowptr[NMAX + 1];
__device__ int   g_woff[NMAX];
__device__ int   g_bsum[64];
__device__ int   g_boff[64];
__device__ int   g_idx64;

// ---------------------------------------------------------------------------
// Helpers
// ---------------------------------------------------------------------------
__device__ __forceinline__ float warpSum(float v) {
#pragma unroll
    for (int off = 16; off; off >>= 1)
        v += __shfl_xor_sync(0xffffffffu, v, off);
    return v;
}

__device__ __forceinline__ float to_tf32(float x) {
    float r;
    asm("cvt.rna.tf32.f32 %0, %1;" : "=f"(r) : "f"(x));
    return r;
}

__device__ __forceinline__ void mma_tf32(float c[4],
                                         unsigned a0, unsigned a1, unsigned a2, unsigned a3,
                                         unsigned b0, unsigned b1) {
    asm volatile(
        "mma.sync.aligned.m16n8k8.row.col.f32.tf32.tf32.f32 "
        "{%0,%1,%2,%3},{%4,%5,%6,%7},{%8,%9},{%0,%1,%2,%3};"
        : "+f"(c[0]), "+f"(c[1]), "+f"(c[2]), "+f"(c[3])
        : "r"(a0), "r"(a1), "r"(a2), "r"(a3), "r"(b0), "r"(b1));
}

// ---------------------------------------------------------------------------
// Index detect / convert (+fused histogram)
// ---------------------------------------------------------------------------
__global__ void detect_idx_kernel(const int* raw) {
    if (threadIdx.x == 0) {
        int all_hi_zero = 1, any_lo_nonzero = 0;
        for (int i = 0; i < 256; i++) {
            if (raw[2 * i + 1] != 0) all_hi_zero = 0;
            if (raw[2 * i] != 0) any_lo_nonzero = 1;
        }
        g_idx64 = (all_hi_zero && any_lo_nonzero) ? 1 : 0;
    }
}

__global__ void zero_cnt_kernel(int N) {
    int i = blockIdx.x * blockDim.x + threadIdx.x;
    if (i < N) g_cnt[i] = 0;
}

__global__ void convert_idx_kernel(const void* raw, int E) {
    int i = blockIdx.x * blockDim.x + threadIdx.x;
    if (i >= E) return;
    int s, d;
    if (g_idx64) {
        const long long* p = (const long long*)raw;
        s = (int)p[i];
        d = (int)p[E + i];
    } else {
        const int* p = (const int*)raw;
        s = p[i];
        d = p[E + i];
    }
    g_src[i] = s;
    g_dst[i] = d;
    atomicAdd(&g_cnt[d], 1);
}

// ---------------------------------------------------------------------------
// 3-phase exclusive scan of g_cnt -> g_rowptr/g_woff
// ---------------------------------------------------------------------------
__global__ void __launch_bounds__(1024)
scanA_kernel(int N) {
    __shared__ int wsum[32];
    int t = threadIdx.x;
    int i = blockIdx.x * 1024 + t;
    int v = (i < N) ? g_cnt[i] : 0;
    int inc = v;
#pragma unroll
    for (int off = 1; off < 32; off <<= 1) {
        int u = __shfl_up_sync(0xffffffffu, inc, off);
        if ((t & 31) >= off) inc += u;
    }
    if ((t & 31) == 31) wsum[t >> 5] = inc;
    __syncthreads();
    if (t < 32) {
        int w = wsum[t];
        int wi = w;
#pragma unroll
        for (int off = 1; off < 32; off <<= 1) {
            int u = __shfl_up_sync(0xffffffffu, wi, off);
            if (t >= off) wi += u;
        }
        wsum[t] = wi - w;
    }
    __syncthreads();
    int exc = inc - v + wsum[t >> 5];
    if (i < N) g_rowptr[i] = exc;
    if (t == 1023) g_bsum[blockIdx.x] = exc + v;
}

__global__ void scanB_kernel(int nb, int N, int E) {
    int lane = threadIdx.x;
    int v0 = (lane < nb) ? g_bsum[lane] : 0;
    int v1 = (32 + lane < nb) ? g_bsum[32 + lane] : 0;
    int i0 = v0, i1 = v1;
#pragma unroll
    for (int off = 1; off < 32; off <<= 1) {
        int u = __shfl_up_sync(0xffffffffu, i0, off);
        if (lane >= off) i0 += u;
        int u2 = __shfl_up_sync(0xffffffffu, i1, off);
        if (lane >= off) i1 += u2;
    }
    int tot0 = __shfl_sync(0xffffffffu, i0, 31);
    i1 += tot0;
    g_boff[lane] = i0 - v0;
    g_boff[32 + lane] = i1 - v1;
    if (lane == 0) g_rowptr[N] = E;
}

__global__ void __launch_bounds__(1024)
scanC_kernel(int N) {
    int i = blockIdx.x * 1024 + threadIdx.x;
    if (i < N) {
        int r = g_rowptr[i] + g_boff[blockIdx.x];
        g_rowptr[i] = r;
        g_woff[i] = r;
    }
}

__global__ void scatter_kernel(int E) {
    int i = blockIdx.x * blockDim.x + threadIdx.x;
    if (i >= E) return;
    int d = g_dst[i];
    int pos = atomicAdd(&g_woff[d], 1);
    g_sorted[pos] = make_int2(g_src[i], i);
}

// ---------------------------------------------------------------------------
// TF32 MMA core: 128x128 block tile, BK=32, 8 warps (4x2), warp tile 32x64.
// acc[mt][nt][c]: mt in 0..1 (16 rows each), nt in 0..7 (8 cols each).
// ---------------------------------------------------------------------------
__device__ __forceinline__ void mma_core(
    const float* __restrict__ A, const float* __restrict__ B,
    int M, int K, int Nout, int n_base, int m0,
    float (&acc)[2][8][4], float (*As)[36], float (*Bs)[136])
{
    const int tid = threadIdx.x;
    const int lane = tid & 31;
    const int wid = tid >> 5;
    const int warp_m = wid & 3;
    const int warp_n = wid >> 2;

#pragma unroll
    for (int i = 0; i < 2; i++)
#pragma unroll
        for (int j = 0; j < 8; j++)
#pragma unroll
            for (int c = 0; c < 4; c++) acc[i][j][c] = 0.f;

#pragma unroll 1
    for (int k0 = 0; k0 < K; k0 += 32) {
        // stage A (128x32) with tf32 rounding
#pragma unroll
        for (int j = 0; j < 4; j++) {
            int idx = tid + j * 256;
            int r = idx >> 3, q = (idx & 7) * 4;
            float4 v = make_float4(0.f, 0.f, 0.f, 0.f);
            if (m0 + r < M)
                v = *(const float4*)&A[(size_t)(m0 + r) * K + k0 + q];
            As[r][q + 0] = to_tf32(v.x);
            As[r][q + 1] = to_tf32(v.y);
            As[r][q + 2] = to_tf32(v.z);
            As[r][q + 3] = to_tf32(v.w);
        }
        // stage B (32x128)
#pragma unroll
        for (int j = 0; j < 4; j++) {
            int idx = tid + j * 256;
            int kr = idx >> 5, q = (idx & 31) * 4;
            float4 v = *(const float4*)&B[(size_t)(k0 + kr) * Nout + n_base + q];
            Bs[kr][q + 0] = to_tf32(v.x);
            Bs[kr][q + 1] = to_tf32(v.y);
            Bs[kr][q + 2] = to_tf32(v.z);
            Bs[kr][q + 3] = to_tf32(v.w);
        }
        __syncthreads();
#pragma unroll
        for (int kk = 0; kk < 32; kk += 8) {
            unsigned bf[8][2];
#pragma unroll
            for (int nt = 0; nt < 8; nt++) {
                int n = warp_n * 64 + nt * 8 + (lane >> 2);
                bf[nt][0] = __float_as_uint(Bs[kk + (lane & 3)][n]);
                bf[nt][1] = __float_as_uint(Bs[kk + 4 + (lane & 3)][n]);
            }
#pragma unroll
            for (int mt = 0; mt < 2; mt++) {
                int r0 = warp_m * 32 + mt * 16 + (lane >> 2);
                unsigned a0 = __float_as_uint(As[r0][kk + (lane & 3)]);
                unsigned a1 = __float_as_uint(As[r0 + 8][kk + (lane & 3)]);
                unsigned a2 = __float_as_uint(As[r0][kk + 4 + (lane & 3)]);
                unsigned a3 = __float_as_uint(As[r0 + 8][kk + 4 + (lane & 3)]);
#pragma unroll
                for (int nt = 0; nt < 8; nt++)
                    mma_tf32(acc[mt][nt], a0, a1, a2, a3, bf[nt][0], bf[nt][1]);
            }
        }
        __syncthreads();
    }
}

// ---------------------------------------------------------------------------
// proj4 (q/k/v/skip) via tensor cores; q scaled at store.
// ---------------------------------------------------------------------------
__global__ void __launch_bounds__(256)
proj_mma_kernel(const float* __restrict__ A,
                const float* __restrict__ Wq, const float* __restrict__ bq,
                const float* __restrict__ Wk, const float* __restrict__ bk,
                const float* __restrict__ Wv, const float* __restrict__ bv,
                const float* __restrict__ Ws, const float* __restrict__ bs,
                int M)
{
    const float* B; const float* bias; float* C; float scale;
    switch (blockIdx.y) {
        case 0: B = Wq; bias = bq; C = g_q;  scale = QSCALE; break;
        case 1: B = Wk; bias = bk; C = g_k;  scale = 1.f;    break;
        case 2: B = Wv; bias = bv; C = g_v;  scale = 1.f;    break;
        default: B = Ws; bias = bs; C = g_xr; scale = 1.f;   break;
    }
    __shared__ float As[128][36];
    __shared__ float Bs[32][136];
    float acc[2][8][4];
    const int m0 = blockIdx.x * 128;
    mma_core(A, B, M, DIM, DIM, 0, m0, acc, As, Bs);

    const int lane = threadIdx.x & 31;
    const int wid = threadIdx.x >> 5;
    const int warp_m = wid & 3, warp_n = wid >> 2;
#pragma unroll
    for (int mt = 0; mt < 2; mt++)
#pragma unroll
        for (int h2 = 0; h2 < 2; h2++) {
            int m = m0 + warp_m * 32 + mt * 16 + (lane >> 2) + h2 * 8;
            if (m >= M) continue;
#pragma unroll
            for (int nt = 0; nt < 8; nt++) {
                int col = warp_n * 64 + nt * 8 + (lane & 3) * 2;
                float2 st;
                st.x = (acc[mt][nt][h2 * 2]     + __ldg(&bias[col]))     * scale;
                st.y = (acc[mt][nt][h2 * 2 + 1] + __ldg(&bias[col + 1])) * scale;
                *(float2*)&C[(size_t)m * DIM + col] = st;
            }
        }
}

// ---------------------------------------------------------------------------
// FF1: h @ Wf1 + bf1, relu. Nout=512, grid.y = 4.
// ---------------------------------------------------------------------------
__global__ void __launch_bounds__(256)
ff1_mma_kernel(const float* __restrict__ A, const float* __restrict__ B,
               const float* __restrict__ bias, float* __restrict__ C, int M)
{
    __shared__ float As[128][36];
    __shared__ float Bs[32][136];
    float acc[2][8][4];
    const int m0 = blockIdx.x * 128;
    const int n_base = blockIdx.y * 128;
    mma_core(A, B, M, DIM, 4 * DIM, n_base, m0, acc, As, Bs);

    const int lane = threadIdx.x & 31;
    const int wid = threadIdx.x >> 5;
    const int warp_m = wid & 3, warp_n = wid >> 2;
#pragma unroll
    for (int mt = 0; mt < 2; mt++)
#pragma unroll
        for (int h2 = 0; h2 < 2; h2++) {
            int m = m0 + warp_m * 32 + mt * 16 + (lane >> 2) + h2 * 8;
            if (m >= M) continue;
#pragma unroll
            for (int nt = 0; nt < 8; nt++) {
                int col = n_base + warp_n * 64 + nt * 8 + (lane & 3) * 2;
                float2 st;
                st.x = fmaxf(acc[mt][nt][h2 * 2]     + __ldg(&bias[col]), 0.f);
                st.y = fmaxf(acc[mt][nt][h2 * 2 + 1] + __ldg(&bias[col + 1]), 0.f);
                *(float2*)&C[(size_t)m * 4 * DIM + col] = st;
            }
        }
}

// ---------------------------------------------------------------------------
// FF2: ff1 @ Wf2 + bf2 + res, then LayerNorm(g2,b2). Nout=128.
// ---------------------------------------------------------------------------
__global__ void __launch_bounds__(256)
ff2_mma_kernel(const float* __restrict__ A, const float* __restrict__ B,
               const float* __restrict__ bias, float* __restrict__ C,
               const float* __restrict__ res,
               const float* __restrict__ gamma, const float* __restrict__ betap,
               int M)
{
    __shared__ float As[128][36];
    __shared__ float Bs[32][136];
    __shared__ float pr[128][2];
    float acc[2][8][4];
    const int m0 = blockIdx.x * 128;
    mma_core(A, B, M, 4 * DIM, DIM, 0, m0, acc, As, Bs);

    const int lane = threadIdx.x & 31;
    const int wid = threadIdx.x >> 5;
    const int warp_m = wid & 3, warp_n = wid >> 2;

    // tv = acc + bias + res (in place); quad partial sums -> pr
    float mysum[2][2];
#pragma unroll
    for (int mt = 0; mt < 2; mt++)
#pragma unroll
        for (int h2 = 0; h2 < 2; h2++) {
            int row = warp_m * 32 + mt * 16 + (lane >> 2) + h2 * 8;
            int m = m0 + row;
            float s = 0.f;
#pragma unroll
            for (int nt = 0; nt < 8; nt++) {
                int col = warp_n * 64 + nt * 8 + (lane & 3) * 2;
                float r0 = (m < M) ? res[(size_t)m * DIM + col]     : 0.f;
                float r1 = (m < M) ? res[(size_t)m * DIM + col + 1] : 0.f;
                float t0 = acc[mt][nt][h2 * 2]     + __ldg(&bias[col])     + r0;
                float t1 = acc[mt][nt][h2 * 2 + 1] + __ldg(&bias[col + 1]) + r1;
                acc[mt][nt][h2 * 2] = t0;
                acc[mt][nt][h2 * 2 + 1] = t1;
                s += t0 + t1;
            }
            s += __shfl_xor_sync(0xffffffffu, s, 1);
            s += __shfl_xor_sync(0xffffffffu, s, 2);
            mysum[mt][h2] = s;
            if ((lane & 3) == 0) pr[row][warp_n] = s;
        }
    __syncthreads();
    float mu[2][2];
#pragma unroll
    for (int mt = 0; mt < 2; mt++)
#pragma unroll
        for (int h2 = 0; h2 < 2; h2++) {
            int row = warp_m * 32 + mt * 16 + (lane >> 2) + h2 * 8;
            mu[mt][h2] = (pr[row][0] + pr[row][1]) * (1.0f / 128.0f);
        }
    __syncthreads();
    // variance partials
#pragma unroll
    for (int mt = 0; mt < 2; mt++)
#pragma unroll
        for (int h2 = 0; h2 < 2; h2++) {
            int row = warp_m * 32 + mt * 16 + (lane >> 2) + h2 * 8;
            float vs = 0.f;
#pragma unroll
            for (int nt = 0; nt < 8; nt++) {
                float d0 = acc[mt][nt][h2 * 2]     - mu[mt][h2];
                float d1 = acc[mt][nt][h2 * 2 + 1] - mu[mt][h2];
                vs += d0 * d0 + d1 * d1;
            }
            vs += __shfl_xor_sync(0xffffffffu, vs, 1);
            vs += __shfl_xor_sync(0xffffffffu, vs, 2);
            if ((lane & 3) == 0) pr[row][warp_n] = vs;
        }
    __syncthreads();
#pragma unroll
    for (int mt = 0; mt < 2; mt++)
#pragma unroll
        for (int h2 = 0; h2 < 2; h2++) {
            int row = warp_m * 32 + mt * 16 + (lane >> 2) + h2 * 8;
            int m = m0 + row;
            if (m >= M) continue;
            float var = (pr[row][0] + pr[row][1]) * (1.0f / 128.0f);
            float inv = rsqrtf(var + 1e-5f);
#pragma unroll
            for (int nt = 0; nt < 8; nt++) {
                int col = warp_n * 64 + nt * 8 + (lane & 3) * 2;
                float2 st;
                st.x = (acc[mt][nt][h2 * 2]     - mu[mt][h2]) * inv * __ldg(&gamma[col])     + __ldg(&betap[col]);
                st.y = (acc[mt][nt][h2 * 2 + 1] - mu[mt][h2]) * inv * __ldg(&gamma[col + 1]) + __ldg(&betap[col + 1]);
                *(float2*)&C[(size_t)m * DIM + col] = st;
            }
        }
}

// ---------------------------------------------------------------------------
// qwe[n,h,i] = 0.5 * sum_c q[n,h*32+c] * We[i, h*32+c]
// ---------------------------------------------------------------------------
__global__ void __launch_bounds__(256)
qwe_kernel(const float* __restrict__ We, const float* __restrict__ be, int N)
{
    __shared__ float sWe[EDIM * DIM];
    __shared__ float sq[4][DIM];
    __shared__ float sbe[DIM];
    int tid = threadIdx.x;
    for (int i = tid; i < EDIM * DIM; i += 256) sWe[i] = We[i];
    if (tid < DIM) sbe[tid] = be[tid];
    int n0 = blockIdx.x * 4;
    for (int i = tid; i < 4 * DIM; i += 256) {
        int nn = i >> 7, c = i & 127;
        sq[nn][c] = (n0 + nn < N) ? g_q[(size_t)(n0 + nn) * DIM + c] : 0.f;
    }
    __syncthreads();
    int nn = tid >> 6, r = tid & 63, h = r >> 4, i = r & 15;
    int n = n0 + nn;
    if (n >= N) return;
    float a = 0.f;
#pragma unroll
    for (int c = 0; c < 32; c++)
        a = fmaf(sq[nn][h * 32 + c], sWe[i * DIM + h * 32 + c], a);
    g_qwe[(size_t)n * 64 + h * 16 + i] = 0.5f * a;
    if (i == 0) {
        float qb = 0.f;
#pragma unroll
        for (int c = 0; c < 32; c++)
            qb = fmaf(sq[nn][h * 32 + c], sbe[h * 32 + c], qb);
        g_qbe[n * 4 + h] = qb;
    }
}

// ---------------------------------------------------------------------------
// Warp-per-node fused attention + beta gate + LN1 (factorized edge proj).
// ---------------------------------------------------------------------------
__global__ void __launch_bounds__(128)
node_attn_kernel(const float* __restrict__ eattr,
                 const float* __restrict__ We, const float* __restrict__ be,
                 const float* __restrict__ x,  const float* __restrict__ Wbeta,
                 const float* __restrict__ g1, const float* __restrict__ b1,
                 int N)
{
    const int lane = threadIdx.x & 31;
    const int warp = blockIdx.x * (blockDim.x >> 5) + (threadIdx.x >> 5);
    const int nwarps = gridDim.x * (blockDim.x >> 5);
    const int j = lane & 15;

    float rWe[16][4];
#pragma unroll
    for (int i = 0; i < 16; i++)
#pragma unroll
        for (int h = 0; h < 4; h++)
            rWe[i][h] = We[i * DIM + h * 32 + lane];
    float rbe[4];
#pragma unroll
    for (int h = 0; h < 4; h++) rbe[h] = be[h * 32 + lane];

    for (int n = warp; n < N; n += nwarps) {
        float q4[4], qwe4[4], qbe4[4];
        float acc[4] = {0.f, 0.f, 0.f, 0.f};
        float s4[4]  = {0.f, 0.f, 0.f, 0.f};
        float den[4] = {0.f, 0.f, 0.f, 0.f};
#pragma unroll
        for (int h = 0; h < 4; h++) {
            q4[h]   = g_q[(size_t)n * DIM + h * 32 + lane];
            qwe4[h] = g_qwe[(size_t)n * 64 + h * 16 + j];
            qbe4[h] = g_qbe[n * 4 + h];
        }
        int beg = g_rowptr[n], end = g_rowptr[n + 1];
        for (int p = beg; p < end; p++) {
            int2 se = g_sorted[p];
            const float* kp = g_k + (size_t)se.x * DIM + lane;
            const float* vp = g_v + (size_t)se.x * DIM + lane;
            float at = __ldg(&eattr[(size_t)se.y * EDIM + j]);
            float k0 = kp[0], k1 = kp[32], k2 = kp[64], k3 = kp[96];
            float v0 = vp[0], v1 = vp[32], v2 = vp[64], v3 = vp[96];
            float p0 = fmaf(q4[0], k0, at * qwe4[0]);
            float p1 = fmaf(q4[1], k1, at * qwe4[1]);
            float p2 = fmaf(q4[2], k2, at * qwe4[2]);
            float p3 = fmaf(q4[3], k3, at * qwe4[3]);
#pragma unroll
            for (int off = 16; off; off >>= 1) {
                p0 += __shfl_xor_sync(0xffffffffu, p0, off);
                p1 += __shfl_xor_sync(0xffffffffu, p1, off);
                p2 += __shfl_xor_sync(0xffffffffu, p2, off);
                p3 += __shfl_xor_sync(0xffffffffu, p3, off);
            }
            float a0 = __expf(p0 + qbe4[0]);
            float a1 = __expf(p1 + qbe4[1]);
            float a2 = __expf(p2 + qbe4[2]);
            float a3 = __expf(p3 + qbe4[3]);
            den[0] += a0; den[1] += a1; den[2] += a2; den[3] += a3;
            acc[0] = fmaf(a0, v0, acc[0]);
            acc[1] = fmaf(a1, v1, acc[1]);
            acc[2] = fmaf(a2, v2, acc[2]);
            acc[3] = fmaf(a3, v3, acc[3]);
            s4[0] = fmaf(a0, at, s4[0]);
            s4[1] = fmaf(a1, at, s4[1]);
            s4[2] = fmaf(a2, at, s4[2]);
            s4[3] = fmaf(a3, at, s4[3]);
        }

        float o[4];
#pragma unroll
        for (int h = 0; h < 4; h++) {
            float ev = den[h] * rbe[h];
#pragma unroll
            for (int i = 0; i < 16; i++)
                ev = fmaf(__shfl_sync(0xffffffffu, s4[h], i), rWe[i][h], ev);
            o[h] = (acc[h] + ev) / (den[h] + 1e-16f);
        }

        float xr4[4], z = 0.f;
#pragma unroll
        for (int h = 0; h < 4; h++) {
            int c = h * 32 + lane;
            xr4[h] = g_xr[(size_t)n * DIM + c];
            z += Wbeta[c] * o[h] + Wbeta[DIM + c] * xr4[h]
               + Wbeta[2 * DIM + c] * (o[h] - xr4[h]);
        }
        z = warpSum(z);
        float beta = 1.0f / (1.0f + __expf(-z));

        float tv[4], ts = 0.f;
#pragma unroll
        for (int h = 0; h < 4; h++) {
            int c = h * 32 + lane;
            tv[h] = x[(size_t)n * DIM + c] + beta * xr4[h] + (1.0f - beta) * o[h];
            ts += tv[h];
        }
        float mu = warpSum(ts) * (1.0f / 128.0f);
        float vs = 0.f;
#pragma unroll
        for (int h = 0; h < 4; h++) { tv[h] -= mu; vs += tv[h] * tv[h]; }
        float var = warpSum(vs) * (1.0f / 128.0f);
        float inv = rsqrtf(var + 1e-5f);
#pragma unroll
        for (int h = 0; h < 4; h++) {
            int c = h * 32 + lane;
            g_h[(size_t)n * DIM + c] = tv[h] * inv * g1[c] + b1[c];
        }
    }
}

// ---------------------------------------------------------------------------
// Launch
// ---------------------------------------------------------------------------
extern "C" void kernel_launch(void* const* d_in, const int* in_sizes, int n_in,
                              void* d_out, int out_size)
{
    const float* x      = (const float*)d_in[0];
    const void*  eidx   = d_in[1];
    const float* eattr  = (const float*)d_in[2];
    const float* Wq     = (const float*)d_in[3];
    const float* bq     = (const float*)d_in[4];
    const float* Wk     = (const float*)d_in[5];
    const float* bk     = (const float*)d_in[6];
    const float* Wv     = (const float*)d_in[7];
    const float* bv     = (const float*)d_in[8];
    const float* We     = (const float*)d_in[9];
    const float* be     = (const float*)d_in[10];
    const float* Ws     = (const float*)d_in[11];
    const float* bs     = (const float*)d_in[12];
    const float* Wbeta  = (const float*)d_in[13];
    const float* g1     = (const float*)d_in[14];
    const float* b1     = (const float*)d_in[15];
    const float* Wf1    = (const float*)d_in[16];
    const float* bf1    = (const float*)d_in[17];
    const float* Wf2    = (const float*)d_in[18];
    const float* bf2    = (const float*)d_in[19];
    const float* g2     = (const float*)d_in[20];
    const float* b2     = (const float*)d_in[21];

    const int N = in_sizes[0] / DIM;
    const int E = in_sizes[1] / 2;

    float *h, *ff1;
    cudaGetSymbolAddress((void**)&h,   g_h);
    cudaGetSymbolAddress((void**)&ff1, g_ff1);

    const int nb = (N + 1023) / 1024;
    const int gm = (N + 127) / 128;

    // 0) CSR build
    detect_idx_kernel<<<1, 32>>>((const int*)eidx);
    zero_cnt_kernel<<<(N + 255) / 256, 256>>>(N);
    convert_idx_kernel<<<(E + 255) / 256, 256>>>(eidx, E);
    scanA_kernel<<<nb, 1024>>>(N);
    scanB_kernel<<<1, 32>>>(nb, N, E);
    scanC_kernel<<<nb, 1024>>>(N);
    scatter_kernel<<<(E + 255) / 256, 256>>>(E);

    // 1) projections (tensor cores)
    dim3 gproj(gm, 4);
    proj_mma_kernel<<<gproj, 256>>>(x, Wq, bq, Wk, bk, Wv, bv, Ws, bs, N);

    // 2) per-node q@We^T precompute
    qwe_kernel<<<(N + 3) / 4, 256>>>(We, be, N);

    // 3) fused attention + beta + LN1
    node_attn_kernel<<<1184, 128>>>(eattr, We, be, x, Wbeta, g1, b1, N);

    // 4) FFN (tensor cores) + residual + LN2
    dim3 gff1(gm, 4);
    ff1_mma_kernel<<<gff1, 256>>>(h, Wf1, bf1, ff1, N);
    ff2_mma_kernel<<<gm, 256>>>(ff1, Wf2, bf2, (float*)d_out, h, g2, b2, N);
}

// round 5
// speedup vs baseline: 2.3597x; 1.1199x over previous
#include <cuda_runtime.h>
#include <cuda_bf16.h>
#include <math.h>

#define NMAX 50000
#define EMAX 800000
#define DIM  128
#define HEADS 4
#define CH   32
#define EDIM 16
#define QSCALE 0.17677669529663687f   // 1/sqrt(32)

// ---------------------------------------------------------------------------
// Scratch
// ---------------------------------------------------------------------------
__device__ float g_q[NMAX * DIM];
__device__ float g_k[NMAX * DIM];
__device__ float g_v[NMAX * DIM];
__device__ float g_xr[NMAX * DIM];
__device__ float g_h[NMAX * DIM];
__device__ float g_ff1[NMAX * 4 * DIM];
__device__ float g_qwe[(size_t)NMAX * 64];
__device__ float g_qbe[NMAX * 4];
__device__ int   g_src[EMAX];
__device__ int   g_dst[EMAX];
__device__ int2  g_sorted[EMAX];
__device__ int   g_cnt[NMAX];
__device__ int   g_rowptr[NMAX + 1];
__device__ int   g_woff[NMAX];
__device__ int   g_bsum[64];
__device__ int   g_boff[64];
__device__ int   g_idx64;

// ---------------------------------------------------------------------------
// Helpers
// ---------------------------------------------------------------------------
__device__ __forceinline__ float warpSum(float v) {
#pragma unroll
    for (int off = 16; off; off >>= 1)
        v += __shfl_xor_sync(0xffffffffu, v, off);
    return v;
}

__device__ __forceinline__ float to_tf32(float x) {
    float r;
    asm("cvt.rna.tf32.f32 %0, %1;" : "=f"(r) : "f"(x));
    return r;
}

__device__ __forceinline__ void mma_tf32(float c[4],
                                         unsigned a0, unsigned a1, unsigned a2, unsigned a3,
                                         unsigned b0, unsigned b1) {
    asm volatile(
        "mma.sync.aligned.m16n8k8.row.col.f32.tf32.tf32.f32 "
        "{%0,%1,%2,%3},{%4,%5,%6,%7},{%8,%9},{%0,%1,%2,%3};"
        : "+f"(c[0]), "+f"(c[1]), "+f"(c[2]), "+f"(c[3])
        : "r"(a0), "r"(a1), "r"(a2), "r"(a3), "r"(b0), "r"(b1));
}

// ---------------------------------------------------------------------------
// Index detect / convert (+fused histogram)
// ---------------------------------------------------------------------------
__global__ void detect_idx_kernel(const int* raw) {
    if (threadIdx.x == 0) {
        int all_hi_zero = 1, any_lo_nonzero = 0;
        for (int i = 0; i < 256; i++) {
            if (raw[2 * i + 1] != 0) all_hi_zero = 0;
            if (raw[2 * i] != 0) any_lo_nonzero = 1;
        }
        g_idx64 = (all_hi_zero && any_lo_nonzero) ? 1 : 0;
    }
}

__global__ void zero_cnt_kernel(int N) {
    int i = blockIdx.x * blockDim.x + threadIdx.x;
    if (i < N) g_cnt[i] = 0;
}

__global__ void convert_idx_kernel(const void* raw, int E) {
    int i = blockIdx.x * blockDim.x + threadIdx.x;
    if (i >= E) return;
    int s, d;
    if (g_idx64) {
        const long long* p = (const long long*)raw;
        s = (int)p[i];
        d = (int)p[E + i];
    } else {
        const int* p = (const int*)raw;
        s = p[i];
        d = p[E + i];
    }
    g_src[i] = s;
    g_dst[i] = d;
    atomicAdd(&g_cnt[d], 1);
}

// ---------------------------------------------------------------------------
// 3-phase exclusive scan of g_cnt -> g_rowptr/g_woff
// ---------------------------------------------------------------------------
__global__ void __launch_bounds__(1024)
scanA_kernel(int N) {
    __shared__ int wsum[32];
    int t = threadIdx.x;
    int i = blockIdx.x * 1024 + t;
    int v = (i < N) ? g_cnt[i] : 0;
    int inc = v;
#pragma unroll
    for (int off = 1; off < 32; off <<= 1) {
        int u = __shfl_up_sync(0xffffffffu, inc, off);
        if ((t & 31) >= off) inc += u;
    }
    if ((t & 31) == 31) wsum[t >> 5] = inc;
    __syncthreads();
    if (t < 32) {
        int w = wsum[t];
        int wi = w;
#pragma unroll
        for (int off = 1; off < 32; off <<= 1) {
            int u = __shfl_up_sync(0xffffffffu, wi, off);
            if (t >= off) wi += u;
        }
        wsum[t] = wi - w;
    }
    __syncthreads();
    int exc = inc - v + wsum[t >> 5];
    if (i < N) g_rowptr[i] = exc;
    if (t == 1023) g_bsum[blockIdx.x] = exc + v;
}

__global__ void scanB_kernel(int nb, int N, int E) {
    int lane = threadIdx.x;
    int v0 = (lane < nb) ? g_bsum[lane] : 0;
    int v1 = (32 + lane < nb) ? g_bsum[32 + lane] : 0;
    int i0 = v0, i1 = v1;
#pragma unroll
    for (int off = 1; off < 32; off <<= 1) {
        int u = __shfl_up_sync(0xffffffffu, i0, off);
        if (lane >= off) i0 += u;
        int u2 = __shfl_up_sync(0xffffffffu, i1, off);
        if (lane >= off) i1 += u2;
    }
    int tot0 = __shfl_sync(0xffffffffu, i0, 31);
    i1 += tot0;
    g_boff[lane] = i0 - v0;
    g_boff[32 + lane] = i1 - v1;
    if (lane == 0) g_rowptr[N] = E;
}

__global__ void __launch_bounds__(1024)
scanC_kernel(int N) {
    int i = blockIdx.x * 1024 + threadIdx.x;
    if (i < N) {
        int r = g_rowptr[i] + g_boff[blockIdx.x];
        g_rowptr[i] = r;
        g_woff[i] = r;
    }
}

__global__ void scatter_kernel(int E) {
    int i = blockIdx.x * blockDim.x + threadIdx.x;
    if (i >= E) return;
    int d = g_dst[i];
    int pos = atomicAdd(&g_woff[d], 1);
    g_sorted[pos] = make_int2(g_src[i], i);
}

// ---------------------------------------------------------------------------
// TF32 MMA core with register prefetch pipeline.
// 128x128 block tile, BK=32, 8 warps (4x2), warp tile 32x64.
// ---------------------------------------------------------------------------
__device__ __forceinline__ void mma_core(
    const float* __restrict__ A, const float* __restrict__ B,
    int M, int K, int Nout, int n_base, int m0,
    float (&acc)[2][8][4], float (*As)[36], float (*Bs)[136])
{
    const int tid = threadIdx.x;
    const int lane = tid & 31;
    const int wid = tid >> 5;
    const int warp_m = wid & 3;
    const int warp_n = wid >> 2;

    const int ar = tid >> 1;            // A row 0..127 (2 thr/row)
    const int aq = (tid & 1) * 16;      // A col quad base: 0 or 16
    const int br_ = tid >> 3;           // B k-row 0..31 (8 thr/row)
    const int bq = (tid & 7) * 16;      // B col base

#pragma unroll
    for (int i = 0; i < 2; i++)
#pragma unroll
        for (int j = 0; j < 8; j++)
#pragma unroll
            for (int c = 0; c < 4; c++) acc[i][j][c] = 0.f;

    float4 pa[4], pb[4];
    // prefetch tile 0
    {
        bool mok = (m0 + ar < M);
#pragma unroll
        for (int j = 0; j < 4; j++)
            pa[j] = mok ? *(const float4*)&A[(size_t)(m0 + ar) * K + aq + j * 4]
                        : make_float4(0.f, 0.f, 0.f, 0.f);
#pragma unroll
        for (int j = 0; j < 4; j++)
            pb[j] = *(const float4*)&B[(size_t)br_ * Nout + n_base + bq + j * 4];
    }

#pragma unroll 1
    for (int k0 = 0; k0 < K; k0 += 32) {
        // store staged tile to smem (tf32 rounding)
#pragma unroll
        for (int j = 0; j < 4; j++) {
            As[ar][aq + j * 4 + 0] = to_tf32(pa[j].x);
            As[ar][aq + j * 4 + 1] = to_tf32(pa[j].y);
            As[ar][aq + j * 4 + 2] = to_tf32(pa[j].z);
            As[ar][aq + j * 4 + 3] = to_tf32(pa[j].w);
            Bs[br_][bq + j * 4 + 0] = to_tf32(pb[j].x);
            Bs[br_][bq + j * 4 + 1] = to_tf32(pb[j].y);
            Bs[br_][bq + j * 4 + 2] = to_tf32(pb[j].z);
            Bs[br_][bq + j * 4 + 3] = to_tf32(pb[j].w);
        }
        __syncthreads();
        // prefetch next tile (overlaps with MMA below)
        if (k0 + 32 < K) {
            bool mok = (m0 + ar < M);
#pragma unroll
            for (int j = 0; j < 4; j++)
                pa[j] = mok ? *(const float4*)&A[(size_t)(m0 + ar) * K + k0 + 32 + aq + j * 4]
                            : make_float4(0.f, 0.f, 0.f, 0.f);
#pragma unroll
            for (int j = 0; j < 4; j++)
                pb[j] = *(const float4*)&B[(size_t)(k0 + 32 + br_) * Nout + n_base + bq + j * 4];
        }
#pragma unroll
        for (int kk = 0; kk < 32; kk += 8) {
            unsigned bf[8][2];
#pragma unroll
            for (int nt = 0; nt < 8; nt++) {
                int n = warp_n * 64 + nt * 8 + (lane >> 2);
                bf[nt][0] = __float_as_uint(Bs[kk + (lane & 3)][n]);
                bf[nt][1] = __float_as_uint(Bs[kk + 4 + (lane & 3)][n]);
            }
#pragma unroll
            for (int mt = 0; mt < 2; mt++) {
                int r0 = warp_m * 32 + mt * 16 + (lane >> 2);
                unsigned a0 = __float_as_uint(As[r0][kk + (lane & 3)]);
                unsigned a1 = __float_as_uint(As[r0 + 8][kk + (lane & 3)]);
                unsigned a2 = __float_as_uint(As[r0][kk + 4 + (lane & 3)]);
                unsigned a3 = __float_as_uint(As[r0 + 8][kk + 4 + (lane & 3)]);
#pragma unroll
                for (int nt = 0; nt < 8; nt++)
                    mma_tf32(acc[mt][nt], a0, a1, a2, a3, bf[nt][0], bf[nt][1]);
            }
        }
        __syncthreads();
    }
}

// ---------------------------------------------------------------------------
// proj4 (q/k/v/skip) via tensor cores; q scaled at store.
// ---------------------------------------------------------------------------
__global__ void __launch_bounds__(256)
proj_mma_kernel(const float* __restrict__ A,
                const float* __restrict__ Wq, const float* __restrict__ bq,
                const float* __restrict__ Wk, const float* __restrict__ bk,
                const float* __restrict__ Wv, const float* __restrict__ bv,
                const float* __restrict__ Ws, const float* __restrict__ bs,
                int M)
{
    const float* B; const float* bias; float* C; float scale;
    switch (blockIdx.y) {
        case 0: B = Wq; bias = bq; C = g_q;  scale = QSCALE; break;
        case 1: B = Wk; bias = bk; C = g_k;  scale = 1.f;    break;
        case 2: B = Wv; bias = bv; C = g_v;  scale = 1.f;    break;
        default: B = Ws; bias = bs; C = g_xr; scale = 1.f;   break;
    }
    __shared__ float As[128][36];
    __shared__ float Bs[32][136];
    float acc[2][8][4];
    const int m0 = blockIdx.x * 128;
    mma_core(A, B, M, DIM, DIM, 0, m0, acc, As, Bs);

    const int lane = threadIdx.x & 31;
    const int wid = threadIdx.x >> 5;
    const int warp_m = wid & 3, warp_n = wid >> 2;
#pragma unroll
    for (int mt = 0; mt < 2; mt++)
#pragma unroll
        for (int h2 = 0; h2 < 2; h2++) {
            int m = m0 + warp_m * 32 + mt * 16 + (lane >> 2) + h2 * 8;
            if (m >= M) continue;
#pragma unroll
            for (int nt = 0; nt < 8; nt++) {
                int col = warp_n * 64 + nt * 8 + (lane & 3) * 2;
                float2 st;
                st.x = (acc[mt][nt][h2 * 2]     + __ldg(&bias[col]))     * scale;
                st.y = (acc[mt][nt][h2 * 2 + 1] + __ldg(&bias[col + 1])) * scale;
                *(float2*)&C[(size_t)m * DIM + col] = st;
            }
        }
}

// ---------------------------------------------------------------------------
// FF1: h @ Wf1 + bf1, relu. Nout=512, grid.y = 4.
// ---------------------------------------------------------------------------
__global__ void __launch_bounds__(256)
ff1_mma_kernel(const float* __restrict__ A, const float* __restrict__ B,
               const float* __restrict__ bias, float* __restrict__ C, int M)
{
    __shared__ float As[128][36];
    __shared__ float Bs[32][136];
    float acc[2][8][4];
    const int m0 = blockIdx.x * 128;
    const int n_base = blockIdx.y * 128;
    mma_core(A, B, M, DIM, 4 * DIM, n_base, m0, acc, As, Bs);

    const int lane = threadIdx.x & 31;
    const int wid = threadIdx.x >> 5;
    const int warp_m = wid & 3, warp_n = wid >> 2;
#pragma unroll
    for (int mt = 0; mt < 2; mt++)
#pragma unroll
        for (int h2 = 0; h2 < 2; h2++) {
            int m = m0 + warp_m * 32 + mt * 16 + (lane >> 2) + h2 * 8;
            if (m >= M) continue;
#pragma unroll
            for (int nt = 0; nt < 8; nt++) {
                int col = n_base + warp_n * 64 + nt * 8 + (lane & 3) * 2;
                float2 st;
                st.x = fmaxf(acc[mt][nt][h2 * 2]     + __ldg(&bias[col]), 0.f);
                st.y = fmaxf(acc[mt][nt][h2 * 2 + 1] + __ldg(&bias[col + 1]), 0.f);
                *(float2*)&C[(size_t)m * 4 * DIM + col] = st;
            }
        }
}

// ---------------------------------------------------------------------------
// FF2: ff1 @ Wf2 + bf2 + res, then LayerNorm(g2,b2). Nout=128.
// ---------------------------------------------------------------------------
__global__ void __launch_bounds__(256)
ff2_mma_kernel(const float* __restrict__ A, const float* __restrict__ B,
               const float* __restrict__ bias, float* __restrict__ C,
               const float* __restrict__ res,
               const float* __restrict__ gamma, const float* __restrict__ betap,
               int M)
{
    __shared__ float As[128][36];
    __shared__ float Bs[32][136];
    __shared__ float pr[128][2];
    float acc[2][8][4];
    const int m0 = blockIdx.x * 128;
    mma_core(A, B, M, 4 * DIM, DIM, 0, m0, acc, As, Bs);

    const int lane = threadIdx.x & 31;
    const int wid = threadIdx.x >> 5;
    const int warp_m = wid & 3, warp_n = wid >> 2;

    float mu[2][2];
#pragma unroll
    for (int mt = 0; mt < 2; mt++)
#pragma unroll
        for (int h2 = 0; h2 < 2; h2++) {
            int row = warp_m * 32 + mt * 16 + (lane >> 2) + h2 * 8;
            int m = m0 + row;
            float s = 0.f;
#pragma unroll
            for (int nt = 0; nt < 8; nt++) {
                int col = warp_n * 64 + nt * 8 + (lane & 3) * 2;
                float r0 = (m < M) ? res[(size_t)m * DIM + col]     : 0.f;
                float r1 = (m < M) ? res[(size_t)m * DIM + col + 1] : 0.f;
                float t0 = acc[mt][nt][h2 * 2]     + __ldg(&bias[col])     + r0;
                float t1 = acc[mt][nt][h2 * 2 + 1] + __ldg(&bias[col + 1]) + r1;
                acc[mt][nt][h2 * 2] = t0;
                acc[mt][nt][h2 * 2 + 1] = t1;
                s += t0 + t1;
            }
            s += __shfl_xor_sync(0xffffffffu, s, 1);
            s += __shfl_xor_sync(0xffffffffu, s, 2);
            if ((lane & 3) == 0) pr[row][warp_n] = s;
        }
    __syncthreads();
#pragma unroll
    for (int mt = 0; mt < 2; mt++)
#pragma unroll
        for (int h2 = 0; h2 < 2; h2++) {
            int row = warp_m * 32 + mt * 16 + (lane >> 2) + h2 * 8;
            mu[mt][h2] = (pr[row][0] + pr[row][1]) * (1.0f / 128.0f);
        }
    __syncthreads();
#pragma unroll
    for (int mt = 0; mt < 2; mt++)
#pragma unroll
        for (int h2 = 0; h2 < 2; h2++) {
            int row = warp_m * 32 + mt * 16 + (lane >> 2) + h2 * 8;
            float vs = 0.f;
#pragma unroll
            for (int nt = 0; nt < 8; nt++) {
                float d0 = acc[mt][nt][h2 * 2]     - mu[mt][h2];
                float d1 = acc[mt][nt][h2 * 2 + 1] - mu[mt][h2];
                vs += d0 * d0 + d1 * d1;
            }
            vs += __shfl_xor_sync(0xffffffffu, vs, 1);
            vs += __shfl_xor_sync(0xffffffffu, vs, 2);
            if ((lane & 3) == 0) pr[row][warp_n] = vs;
        }
    __syncthreads();
#pragma unroll
    for (int mt = 0; mt < 2; mt++)
#pragma unroll
        for (int h2 = 0; h2 < 2; h2++) {
            int row = warp_m * 32 + mt * 16 + (lane >> 2) + h2 * 8;
            int m = m0 + row;
            if (m >= M) continue;
            float var = (pr[row][0] + pr[row][1]) * (1.0f / 128.0f);
            float inv = rsqrtf(var + 1e-5f);
#pragma unroll
            for (int nt = 0; nt < 8; nt++) {
                int col = warp_n * 64 + nt * 8 + (lane & 3) * 2;
                float2 st;
                st.x = (acc[mt][nt][h2 * 2]     - mu[mt][h2]) * inv * __ldg(&gamma[col])     + __ldg(&betap[col]);
                st.y = (acc[mt][nt][h2 * 2 + 1] - mu[mt][h2]) * inv * __ldg(&gamma[col + 1]) + __ldg(&betap[col + 1]);
                *(float2*)&C[(size_t)m * DIM + col] = st;
            }
        }
}

// ---------------------------------------------------------------------------
// qwe[n,h,j] = sum_c q[n,h*32+c] * We[j, h*32+c]   (q pre-scaled; NO 0.5)
// qbe[n,h]   = sum_c q[n,h*32+c] * be[h*32+c]
// ---------------------------------------------------------------------------
__global__ void __launch_bounds__(256)
qwe_kernel(const float* __restrict__ We, const float* __restrict__ be, int N)
{
    __shared__ float sWe[EDIM * DIM];
    __shared__ float sq[4][DIM];
    __shared__ float sbe[DIM];
    int tid = threadIdx.x;
    for (int i = tid; i < EDIM * DIM; i += 256) sWe[i] = We[i];
    if (tid < DIM) sbe[tid] = be[tid];
    int n0 = blockIdx.x * 4;
    for (int i = tid; i < 4 * DIM; i += 256) {
        int nn = i >> 7, c = i & 127;
        sq[nn][c] = (n0 + nn < N) ? g_q[(size_t)(n0 + nn) * DIM + c] : 0.f;
    }
    __syncthreads();
    int nn = tid >> 6, r = tid & 63, h = r >> 4, i = r & 15;
    int n = n0 + nn;
    if (n >= N) return;
    float a = 0.f;
#pragma unroll
    for (int c = 0; c < 32; c++)
        a = fmaf(sq[nn][h * 32 + c], sWe[i * DIM + h * 32 + c], a);
    g_qwe[(size_t)n * 64 + h * 16 + i] = a;
    if (i == 0) {
        float qb = 0.f;
#pragma unroll
        for (int c = 0; c < 32; c++)
            qb = fmaf(sq[nn][h * 32 + c], sbe[h * 32 + c], qb);
        g_qbe[n * 4 + h] = qb;
    }
}

// ---------------------------------------------------------------------------
// Warp-per-node attention, 8-lane head groups, float4 channel ownership.
// Group g (lanes 8g..8g+7) owns head g; lane owns channels g*32 + l8*4 .. +3.
// ---------------------------------------------------------------------------
__global__ void __launch_bounds__(256)
node_attn_kernel(const float* __restrict__ eattr,
                 const float* __restrict__ We, const float* __restrict__ be,
                 const float* __restrict__ x,  const float* __restrict__ Wbeta,
                 const float* __restrict__ g1, const float* __restrict__ b1,
                 int N)
{
    __shared__ float sWe[EDIM][DIM];
    __shared__ float sbe[DIM];
    for (int i = threadIdx.x; i < EDIM * DIM; i += 256)
        ((float*)sWe)[i] = We[i];
    if (threadIdx.x < DIM) sbe[threadIdx.x] = be[threadIdx.x];
    __syncthreads();

    const int lane = threadIdx.x & 31;
    const int g = lane >> 3;          // head
    const int l8 = lane & 7;
    const int ch0 = g * 32 + l8 * 4;  // 4 consecutive channels
    const int warp = blockIdx.x * (blockDim.x >> 5) + (threadIdx.x >> 5);
    const int nwarps = gridDim.x * (blockDim.x >> 5);

    for (int n = warp; n < N; n += nwarps) {
        float4 q4 = *(const float4*)&g_q[(size_t)n * DIM + ch0];
        float2 qwe2 = *(const float2*)&g_qwe[(size_t)n * 64 + g * 16 + 2 * l8];
        float qbe = g_qbe[n * 4 + g];

        float4 acc = make_float4(0.f, 0.f, 0.f, 0.f);
        float s0 = 0.f, s1 = 0.f, den = 0.f;

        int beg = g_rowptr[n], end = g_rowptr[n + 1];
#pragma unroll 2
        for (int p = beg; p < end; p++) {
            int2 se = g_sorted[p];
            float4 k4 = *(const float4*)&g_k[(size_t)se.x * DIM + ch0];
            float4 v4 = *(const float4*)&g_v[(size_t)se.x * DIM + ch0];
            float2 at = *(const float2*)&eattr[(size_t)se.y * EDIM + 2 * l8];

            float pp = q4.x * k4.x + q4.y * k4.y + q4.z * k4.z + q4.w * k4.w
                     + at.x * qwe2.x + at.y * qwe2.y;
            pp += __shfl_xor_sync(0xffffffffu, pp, 1);
            pp += __shfl_xor_sync(0xffffffffu, pp, 2);
            pp += __shfl_xor_sync(0xffffffffu, pp, 4);
            float ea = __expf(pp + qbe);
            den += ea;
            acc.x = fmaf(ea, v4.x, acc.x);
            acc.y = fmaf(ea, v4.y, acc.y);
            acc.z = fmaf(ea, v4.z, acc.z);
            acc.w = fmaf(ea, v4.w, acc.w);
            s0 = fmaf(ea, at.x, s0);
            s1 = fmaf(ea, at.y, s1);
        }

        // unfactor edge projection: ev = den*be + sum_j s_j * We[j]
        float4 ev;
        ev.x = den * sbe[ch0];
        ev.y = den * sbe[ch0 + 1];
        ev.z = den * sbe[ch0 + 2];
        ev.w = den * sbe[ch0 + 3];
#pragma unroll
        for (int jj = 0; jj < 8; jj++) {
            int srcl = (g << 3) | jj;
            float sj0 = __shfl_sync(0xffffffffu, s0, srcl);
            float sj1 = __shfl_sync(0xffffffffu, s1, srcl);
            float4 w0 = *(const float4*)&sWe[2 * jj][ch0];
            float4 w1 = *(const float4*)&sWe[2 * jj + 1][ch0];
            ev.x += sj0 * w0.x + sj1 * w1.x;
            ev.y += sj0 * w0.y + sj1 * w1.y;
            ev.z += sj0 * w0.z + sj1 * w1.z;
            ev.w += sj0 * w0.w + sj1 * w1.w;
        }
        float rden = 1.0f / (den + 1e-16f);
        float o[4] = {(acc.x + ev.x) * rden, (acc.y + ev.y) * rden,
                      (acc.z + ev.z) * rden, (acc.w + ev.w) * rden};

        // beta gate
        float4 xr4 = *(const float4*)&g_xr[(size_t)n * DIM + ch0];
        float4 wb0 = *(const float4*)&Wbeta[ch0];
        float4 wb1 = *(const float4*)&Wbeta[DIM + ch0];
        float4 wb2 = *(const float4*)&Wbeta[2 * DIM + ch0];
        float xr[4] = {xr4.x, xr4.y, xr4.z, xr4.w};
        float z = wb0.x * o[0] + wb1.x * xr[0] + wb2.x * (o[0] - xr[0])
                + wb0.y * o[1] + wb1.y * xr[1] + wb2.y * (o[1] - xr[1])
                + wb0.z * o[2] + wb1.z * xr[2] + wb2.z * (o[2] - xr[2])
                + wb0.w * o[3] + wb1.w * xr[3] + wb2.w * (o[3] - xr[3]);
        z = warpSum(z);
        float beta = 1.0f / (1.0f + __expf(-z));

        float4 xv = *(const float4*)&x[(size_t)n * DIM + ch0];
        float xx[4] = {xv.x, xv.y, xv.z, xv.w};
        float tv[4], ts = 0.f;
#pragma unroll
        for (int c = 0; c < 4; c++) {
            tv[c] = xx[c] + beta * xr[c] + (1.0f - beta) * o[c];
            ts += tv[c];
        }
        float mu = warpSum(ts) * (1.0f / 128.0f);
        float vs = 0.f;
#pragma unroll
        for (int c = 0; c < 4; c++) { tv[c] -= mu; vs += tv[c] * tv[c]; }
        float var = warpSum(vs) * (1.0f / 128.0f);
        float inv = rsqrtf(var + 1e-5f);

        float4 gg = *(const float4*)&g1[ch0];
        float4 bb = *(const float4*)&b1[ch0];
        float4 st;
        st.x = tv[0] * inv * gg.x + bb.x;
        st.y = tv[1] * inv * gg.y + bb.y;
        st.z = tv[2] * inv * gg.z + bb.z;
        st.w = tv[3] * inv * gg.w + bb.w;
        *(float4*)&g_h[(size_t)n * DIM + ch0] = st;
    }
}

// ---------------------------------------------------------------------------
// Launch
// ---------------------------------------------------------------------------
extern "C" void kernel_launch(void* const* d_in, const int* in_sizes, int n_in,
                              void* d_out, int out_size)
{
    const float* x      = (const float*)d_in[0];
    const void*  eidx   = d_in[1];
    const float* eattr  = (const float*)d_in[2];
    const float* Wq     = (const float*)d_in[3];
    const float* bq     = (const float*)d_in[4];
    const float* Wk     = (const float*)d_in[5];
    const float* bk     = (const float*)d_in[6];
    const float* Wv     = (const float*)d_in[7];
    const float* bv     = (const float*)d_in[8];
    const float* We     = (const float*)d_in[9];
    const float* be     = (const float*)d_in[10];
    const float* Ws     = (const float*)d_in[11];
    const float* bs     = (const float*)d_in[12];
    const float* Wbeta  = (const float*)d_in[13];
    const float* g1     = (const float*)d_in[14];
    const float* b1     = (const float*)d_in[15];
    const float* Wf1    = (const float*)d_in[16];
    const float* bf1    = (const float*)d_in[17];
    const float* Wf2    = (const float*)d_in[18];
    const float* bf2    = (const float*)d_in[19];
    const float* g2     = (const float*)d_in[20];
    const float* b2     = (const float*)d_in[21];

    const int N = in_sizes[0] / DIM;
    const int E = in_sizes[1] / 2;

    float *h, *ff1;
    cudaGetSymbolAddress((void**)&h,   g_h);
    cudaGetSymbolAddress((void**)&ff1, g_ff1);

    const int nb = (N + 1023) / 1024;
    const int gm = (N + 127) / 128;

    // 0) CSR build
    detect_idx_kernel<<<1, 32>>>((const int*)eidx);
    zero_cnt_kernel<<<(N + 255) / 256, 256>>>(N);
    convert_idx_kernel<<<(E + 255) / 256, 256>>>(eidx, E);
    scanA_kernel<<<nb, 1024>>>(N);
    scanB_kernel<<<1, 32>>>(nb, N, E);
    scanC_kernel<<<nb, 1024>>>(N);
    scatter_kernel<<<(E + 255) / 256, 256>>>(E);

    // 1) projections (tensor cores)
    dim3 gproj(gm, 4);
    proj_mma_kernel<<<gproj, 256>>>(x, Wq, bq, Wk, bk, Wv, bv, Ws, bs, N);

    // 2) per-node q@We^T precompute
    qwe_kernel<<<(N + 3) / 4, 256>>>(We, be, N);

    // 3) fused attention + beta + LN1
    node_attn_kernel<<<1184, 256>>>(eattr, We, be, x, Wbeta, g1, b1, N);

    // 4) FFN (tensor cores) + residual + LN2
    dim3 gff1(gm, 4);
    ff1_mma_kernel<<<gff1, 256>>>(h, Wf1, bf1, ff1, N);
    ff2_mma_kernel<<<gm, 256>>>(ff1, Wf2, bf2, (float*)d_out, h, g2, b2, N);
}

// round 6
// speedup vs baseline: 2.5874x; 1.0965x over previous
#include <cuda_runtime.h>
#include <cuda_bf16.h>
#include <math.h>

#define NMAX 50000
#define EMAX 800000
#define DIM  128
#define HEADS 4
#define CH   32
#define EDIM 16
#define QSCALE 0.17677669529663687f   // 1/sqrt(32)

// ---------------------------------------------------------------------------
// Scratch
// ---------------------------------------------------------------------------
__device__ float g_q[NMAX * DIM];
__device__ float g_k[NMAX * DIM];
__device__ float g_v[NMAX * DIM];
__device__ float g_xr[NMAX * DIM];
__device__ float g_h[NMAX * DIM];
__device__ float g_ff1[NMAX * 4 * DIM];
__device__ float g_qwe[(size_t)NMAX * 64];
__device__ float g_qbe[NMAX * 4];
__device__ float g_eperm[(size_t)EMAX * EDIM];   // eattr permuted to CSR order
__device__ int   g_src[EMAX];
__device__ int   g_dst[EMAX];
__device__ int   g_ssrc[EMAX];                   // src in CSR order
__device__ int   g_eid[EMAX];                    // edge id in CSR order
__device__ int   g_cnt[NMAX];
__device__ int   g_rowptr[NMAX + 1];
__device__ int   g_woff[NMAX];
__device__ int   g_bsum[64];
__device__ int   g_boff[64];
__device__ int   g_idx64;

// ---------------------------------------------------------------------------
// Helpers
// ---------------------------------------------------------------------------
__device__ __forceinline__ float warpSum(float v) {
#pragma unroll
    for (int off = 16; off; off >>= 1)
        v += __shfl_xor_sync(0xffffffffu, v, off);
    return v;
}

__device__ __forceinline__ float to_tf32(float x) {
    float r;
    asm("cvt.rna.tf32.f32 %0, %1;" : "=f"(r) : "f"(x));
    return r;
}

__device__ __forceinline__ void mma_tf32(float c[4],
                                         unsigned a0, unsigned a1, unsigned a2, unsigned a3,
                                         unsigned b0, unsigned b1) {
    asm volatile(
        "mma.sync.aligned.m16n8k8.row.col.f32.tf32.tf32.f32 "
        "{%0,%1,%2,%3},{%4,%5,%6,%7},{%8,%9},{%0,%1,%2,%3};"
        : "+f"(c[0]), "+f"(c[1]), "+f"(c[2]), "+f"(c[3])
        : "r"(a0), "r"(a1), "r"(a2), "r"(a3), "r"(b0), "r"(b1));
}

// ---------------------------------------------------------------------------
// Index detect / convert (+fused histogram)
// ---------------------------------------------------------------------------
__global__ void detect_idx_kernel(const int* raw) {
    if (threadIdx.x == 0) {
        int all_hi_zero = 1, any_lo_nonzero = 0;
        for (int i = 0; i < 256; i++) {
            if (raw[2 * i + 1] != 0) all_hi_zero = 0;
            if (raw[2 * i] != 0) any_lo_nonzero = 1;
        }
        g_idx64 = (all_hi_zero && any_lo_nonzero) ? 1 : 0;
    }
}

__global__ void zero_cnt_kernel(int N) {
    int i = blockIdx.x * blockDim.x + threadIdx.x;
    if (i < N) g_cnt[i] = 0;
}

__global__ void convert_idx_kernel(const void* raw, int E) {
    int i = blockIdx.x * blockDim.x + threadIdx.x;
    if (i >= E) return;
    int s, d;
    if (g_idx64) {
        const long long* p = (const long long*)raw;
        s = (int)p[i];
        d = (int)p[E + i];
    } else {
        const int* p = (const int*)raw;
        s = p[i];
        d = p[E + i];
    }
    g_src[i] = s;
    g_dst[i] = d;
    atomicAdd(&g_cnt[d], 1);
}

// ---------------------------------------------------------------------------
// 3-phase exclusive scan of g_cnt -> g_rowptr/g_woff
// ---------------------------------------------------------------------------
__global__ void __launch_bounds__(1024)
scanA_kernel(int N) {
    __shared__ int wsum[32];
    int t = threadIdx.x;
    int i = blockIdx.x * 1024 + t;
    int v = (i < N) ? g_cnt[i] : 0;
    int inc = v;
#pragma unroll
    for (int off = 1; off < 32; off <<= 1) {
        int u = __shfl_up_sync(0xffffffffu, inc, off);
        if ((t & 31) >= off) inc += u;
    }
    if ((t & 31) == 31) wsum[t >> 5] = inc;
    __syncthreads();
    if (t < 32) {
        int w = wsum[t];
        int wi = w;
#pragma unroll
        for (int off = 1; off < 32; off <<= 1) {
            int u = __shfl_up_sync(0xffffffffu, wi, off);
            if (t >= off) wi += u;
        }
        wsum[t] = wi - w;
    }
    __syncthreads();
    int exc = inc - v + wsum[t >> 5];
    if (i < N) g_rowptr[i] = exc;
    if (t == 1023) g_bsum[blockIdx.x] = exc + v;
}

__global__ void scanB_kernel(int nb, int N, int E) {
    int lane = threadIdx.x;
    int v0 = (lane < nb) ? g_bsum[lane] : 0;
    int v1 = (32 + lane < nb) ? g_bsum[32 + lane] : 0;
    int i0 = v0, i1 = v1;
#pragma unroll
    for (int off = 1; off < 32; off <<= 1) {
        int u = __shfl_up_sync(0xffffffffu, i0, off);
        if (lane >= off) i0 += u;
        int u2 = __shfl_up_sync(0xffffffffu, i1, off);
        if (lane >= off) i1 += u2;
    }
    int tot0 = __shfl_sync(0xffffffffu, i0, 31);
    i1 += tot0;
    g_boff[lane] = i0 - v0;
    g_boff[32 + lane] = i1 - v1;
    if (lane == 0) g_rowptr[N] = E;
}

__global__ void __launch_bounds__(1024)
scanC_kernel(int N) {
    int i = blockIdx.x * 1024 + threadIdx.x;
    if (i < N) {
        int r = g_rowptr[i] + g_boff[blockIdx.x];
        g_rowptr[i] = r;
        g_woff[i] = r;
    }
}

__global__ void scatter_kernel(int E) {
    int i = blockIdx.x * blockDim.x + threadIdx.x;
    if (i >= E) return;
    int d = g_dst[i];
    int pos = atomicAdd(&g_woff[d], 1);
    g_ssrc[pos] = g_src[i];
    g_eid[pos] = i;
}

// permute eattr into CSR order
__global__ void __launch_bounds__(256)
permute_eattr_kernel(const float* __restrict__ eattr, int E) {
    int i = blockIdx.x * blockDim.x + threadIdx.x;
    if (i >= E * 4) return;
    int p = i >> 2, q = (i & 3) * 4;
    int e = g_eid[p];
    *(float4*)&g_eperm[(size_t)p * EDIM + q] =
        *(const float4*)&eattr[(size_t)e * EDIM + q];
}

// ---------------------------------------------------------------------------
// TF32 MMA core with register prefetch pipeline.
// ---------------------------------------------------------------------------
__device__ __forceinline__ void mma_core(
    const float* __restrict__ A, const float* __restrict__ B,
    int M, int K, int Nout, int n_base, int m0,
    float (&acc)[2][8][4], float (*As)[36], float (*Bs)[136])
{
    const int tid = threadIdx.x;
    const int lane = tid & 31;
    const int wid = tid >> 5;
    const int warp_m = wid & 3;
    const int warp_n = wid >> 2;

    const int ar = tid >> 1;
    const int aq = (tid & 1) * 16;
    const int br_ = tid >> 3;
    const int bq = (tid & 7) * 16;

#pragma unroll
    for (int i = 0; i < 2; i++)
#pragma unroll
        for (int j = 0; j < 8; j++)
#pragma unroll
            for (int c = 0; c < 4; c++) acc[i][j][c] = 0.f;

    float4 pa[4], pb[4];
    {
        bool mok = (m0 + ar < M);
#pragma unroll
        for (int j = 0; j < 4; j++)
            pa[j] = mok ? *(const float4*)&A[(size_t)(m0 + ar) * K + aq + j * 4]
                        : make_float4(0.f, 0.f, 0.f, 0.f);
#pragma unroll
        for (int j = 0; j < 4; j++)
            pb[j] = *(const float4*)&B[(size_t)br_ * Nout + n_base + bq + j * 4];
    }

#pragma unroll 1
    for (int k0 = 0; k0 < K; k0 += 32) {
#pragma unroll
        for (int j = 0; j < 4; j++) {
            As[ar][aq + j * 4 + 0] = to_tf32(pa[j].x);
            As[ar][aq + j * 4 + 1] = to_tf32(pa[j].y);
            As[ar][aq + j * 4 + 2] = to_tf32(pa[j].z);
            As[ar][aq + j * 4 + 3] = to_tf32(pa[j].w);
            Bs[br_][bq + j * 4 + 0] = to_tf32(pb[j].x);
            Bs[br_][bq + j * 4 + 1] = to_tf32(pb[j].y);
            Bs[br_][bq + j * 4 + 2] = to_tf32(pb[j].z);
            Bs[br_][bq + j * 4 + 3] = to_tf32(pb[j].w);
        }
        __syncthreads();
        if (k0 + 32 < K) {
            bool mok = (m0 + ar < M);
#pragma unroll
            for (int j = 0; j < 4; j++)
                pa[j] = mok ? *(const float4*)&A[(size_t)(m0 + ar) * K + k0 + 32 + aq + j * 4]
                            : make_float4(0.f, 0.f, 0.f, 0.f);
#pragma unroll
            for (int j = 0; j < 4; j++)
                pb[j] = *(const float4*)&B[(size_t)(k0 + 32 + br_) * Nout + n_base + bq + j * 4];
        }
#pragma unroll
        for (int kk = 0; kk < 32; kk += 8) {
            unsigned bf[8][2];
#pragma unroll
            for (int nt = 0; nt < 8; nt++) {
                int n = warp_n * 64 + nt * 8 + (lane >> 2);
                bf[nt][0] = __float_as_uint(Bs[kk + (lane & 3)][n]);
                bf[nt][1] = __float_as_uint(Bs[kk + 4 + (lane & 3)][n]);
            }
#pragma unroll
            for (int mt = 0; mt < 2; mt++) {
                int r0 = warp_m * 32 + mt * 16 + (lane >> 2);
                unsigned a0 = __float_as_uint(As[r0][kk + (lane & 3)]);
                unsigned a1 = __float_as_uint(As[r0 + 8][kk + (lane & 3)]);
                unsigned a2 = __float_as_uint(As[r0][kk + 4 + (lane & 3)]);
                unsigned a3 = __float_as_uint(As[r0 + 8][kk + 4 + (lane & 3)]);
#pragma unroll
                for (int nt = 0; nt < 8; nt++)
                    mma_tf32(acc[mt][nt], a0, a1, a2, a3, bf[nt][0], bf[nt][1]);
            }
        }
        __syncthreads();
    }
}

// ---------------------------------------------------------------------------
// proj4 (q/k/v/skip) via tensor cores; q scaled at store.
// ---------------------------------------------------------------------------
__global__ void __launch_bounds__(256)
proj_mma_kernel(const float* __restrict__ A,
                const float* __restrict__ Wq, const float* __restrict__ bq,
                const float* __restrict__ Wk, const float* __restrict__ bk,
                const float* __restrict__ Wv, const float* __restrict__ bv,
                const float* __restrict__ Ws, const float* __restrict__ bs,
                int M)
{
    const float* B; const float* bias; float* C; float scale;
    switch (blockIdx.y) {
        case 0: B = Wq; bias = bq; C = g_q;  scale = QSCALE; break;
        case 1: B = Wk; bias = bk; C = g_k;  scale = 1.f;    break;
        case 2: B = Wv; bias = bv; C = g_v;  scale = 1.f;    break;
        default: B = Ws; bias = bs; C = g_xr; scale = 1.f;   break;
    }
    __shared__ float As[128][36];
    __shared__ float Bs[32][136];
    float acc[2][8][4];
    const int m0 = blockIdx.x * 128;
    mma_core(A, B, M, DIM, DIM, 0, m0, acc, As, Bs);

    const int lane = threadIdx.x & 31;
    const int wid = threadIdx.x >> 5;
    const int warp_m = wid & 3, warp_n = wid >> 2;
#pragma unroll
    for (int mt = 0; mt < 2; mt++)
#pragma unroll
        for (int h2 = 0; h2 < 2; h2++) {
            int m = m0 + warp_m * 32 + mt * 16 + (lane >> 2) + h2 * 8;
            if (m >= M) continue;
#pragma unroll
            for (int nt = 0; nt < 8; nt++) {
                int col = warp_n * 64 + nt * 8 + (lane & 3) * 2;
                float2 st;
                st.x = (acc[mt][nt][h2 * 2]     + __ldg(&bias[col]))     * scale;
                st.y = (acc[mt][nt][h2 * 2 + 1] + __ldg(&bias[col + 1])) * scale;
                *(float2*)&C[(size_t)m * DIM + col] = st;
            }
        }
}

// ---------------------------------------------------------------------------
// FF1: relu(h @ Wf1 + bf1). Nout=512, grid.y = 4.
// ---------------------------------------------------------------------------
__global__ void __launch_bounds__(256)
ff1_mma_kernel(const float* __restrict__ A, const float* __restrict__ B,
               const float* __restrict__ bias, float* __restrict__ C, int M)
{
    __shared__ float As[128][36];
    __shared__ float Bs[32][136];
    float acc[2][8][4];
    const int m0 = blockIdx.x * 128;
    const int n_base = blockIdx.y * 128;
    mma_core(A, B, M, DIM, 4 * DIM, n_base, m0, acc, As, Bs);

    const int lane = threadIdx.x & 31;
    const int wid = threadIdx.x >> 5;
    const int warp_m = wid & 3, warp_n = wid >> 2;
#pragma unroll
    for (int mt = 0; mt < 2; mt++)
#pragma unroll
        for (int h2 = 0; h2 < 2; h2++) {
            int m = m0 + warp_m * 32 + mt * 16 + (lane >> 2) + h2 * 8;
            if (m >= M) continue;
#pragma unroll
            for (int nt = 0; nt < 8; nt++) {
                int col = n_base + warp_n * 64 + nt * 8 + (lane & 3) * 2;
                float2 st;
                st.x = fmaxf(acc[mt][nt][h2 * 2]     + __ldg(&bias[col]), 0.f);
                st.y = fmaxf(acc[mt][nt][h2 * 2 + 1] + __ldg(&bias[col + 1]), 0.f);
                *(float2*)&C[(size_t)m * 4 * DIM + col] = st;
            }
        }
}

// ---------------------------------------------------------------------------
// FF2: ff1 @ Wf2 + bf2 + res, then LayerNorm(g2,b2). Nout=128.
// ---------------------------------------------------------------------------
__global__ void __launch_bounds__(256)
ff2_mma_kernel(const float* __restrict__ A, const float* __restrict__ B,
               const float* __restrict__ bias, float* __restrict__ C,
               const float* __restrict__ res,
               const float* __restrict__ gamma, const float* __restrict__ betap,
               int M)
{
    __shared__ float As[128][36];
    __shared__ float Bs[32][136];
    __shared__ float pr[128][2];
    float acc[2][8][4];
    const int m0 = blockIdx.x * 128;
    mma_core(A, B, M, 4 * DIM, DIM, 0, m0, acc, As, Bs);

    const int lane = threadIdx.x & 31;
    const int wid = threadIdx.x >> 5;
    const int warp_m = wid & 3, warp_n = wid >> 2;

    float mu[2][2];
#pragma unroll
    for (int mt = 0; mt < 2; mt++)
#pragma unroll
        for (int h2 = 0; h2 < 2; h2++) {
            int row = warp_m * 32 + mt * 16 + (lane >> 2) + h2 * 8;
            int m = m0 + row;
            float s = 0.f;
#pragma unroll
            for (int nt = 0; nt < 8; nt++) {
                int col = warp_n * 64 + nt * 8 + (lane & 3) * 2;
                float r0 = (m < M) ? res[(size_t)m * DIM + col]     : 0.f;
                float r1 = (m < M) ? res[(size_t)m * DIM + col + 1] : 0.f;
                float t0 = acc[mt][nt][h2 * 2]     + __ldg(&bias[col])     + r0;
                float t1 = acc[mt][nt][h2 * 2 + 1] + __ldg(&bias[col + 1]) + r1;
                acc[mt][nt][h2 * 2] = t0;
                acc[mt][nt][h2 * 2 + 1] = t1;
                s += t0 + t1;
            }
            s += __shfl_xor_sync(0xffffffffu, s, 1);
            s += __shfl_xor_sync(0xffffffffu, s, 2);
            if ((lane & 3) == 0) pr[row][warp_n] = s;
        }
    __syncthreads();
#pragma unroll
    for (int mt = 0; mt < 2; mt++)
#pragma unroll
        for (int h2 = 0; h2 < 2; h2++) {
            int row = warp_m * 32 + mt * 16 + (lane >> 2) + h2 * 8;
            mu[mt][h2] = (pr[row][0] + pr[row][1]) * (1.0f / 128.0f);
        }
    __syncthreads();
#pragma unroll
    for (int mt = 0; mt < 2; mt++)
#pragma unroll
        for (int h2 = 0; h2 < 2; h2++) {
            int row = warp_m * 32 + mt * 16 + (lane >> 2) + h2 * 8;
            float vs = 0.f;
#pragma unroll
            for (int nt = 0; nt < 8; nt++) {
                float d0 = acc[mt][nt][h2 * 2]     - mu[mt][h2];
                float d1 = acc[mt][nt][h2 * 2 + 1] - mu[mt][h2];
                vs += d0 * d0 + d1 * d1;
            }
            vs += __shfl_xor_sync(0xffffffffu, vs, 1);
            vs += __shfl_xor_sync(0xffffffffu, vs, 2);
            if ((lane & 3) == 0) pr[row][warp_n] = vs;
        }
    __syncthreads();
#pragma unroll
    for (int mt = 0; mt < 2; mt++)
#pragma unroll
        for (int h2 = 0; h2 < 2; h2++) {
            int row = warp_m * 32 + mt * 16 + (lane >> 2) + h2 * 8;
            int m = m0 + row;
            if (m >= M) continue;
            float var = (pr[row][0] + pr[row][1]) * (1.0f / 128.0f);
            float inv = rsqrtf(var + 1e-5f);
#pragma unroll
            for (int nt = 0; nt < 8; nt++) {
                int col = warp_n * 64 + nt * 8 + (lane & 3) * 2;
                float2 st;
                st.x = (acc[mt][nt][h2 * 2]     - mu[mt][h2]) * inv * __ldg(&gamma[col])     + __ldg(&betap[col]);
                st.y = (acc[mt][nt][h2 * 2 + 1] - mu[mt][h2]) * inv * __ldg(&gamma[col + 1]) + __ldg(&betap[col + 1]);
                *(float2*)&C[(size_t)m * DIM + col] = st;
            }
        }
}

// ---------------------------------------------------------------------------
// qwe precompute
// ---------------------------------------------------------------------------
__global__ void __launch_bounds__(256)
qwe_kernel(const float* __restrict__ We, const float* __restrict__ be, int N)
{
    __shared__ float sWe[EDIM * DIM];
    __shared__ float sq[4][DIM];
    __shared__ float sbe[DIM];
    int tid = threadIdx.x;
    for (int i = tid; i < EDIM * DIM; i += 256) sWe[i] = We[i];
    if (tid < DIM) sbe[tid] = be[tid];
    int n0 = blockIdx.x * 4;
    for (int i = tid; i < 4 * DIM; i += 256) {
        int nn = i >> 7, c = i & 127;
        sq[nn][c] = (n0 + nn < N) ? g_q[(size_t)(n0 + nn) * DIM + c] : 0.f;
    }
    __syncthreads();
    int nn = tid >> 6, r = tid & 63, h = r >> 4, i = r & 15;
    int n = n0 + nn;
    if (n >= N) return;
    float a = 0.f;
#pragma unroll
    for (int c = 0; c < 32; c++)
        a = fmaf(sq[nn][h * 32 + c], sWe[i * DIM + h * 32 + c], a);
    g_qwe[(size_t)n * 64 + h * 16 + i] = a;
    if (i == 0) {
        float qb = 0.f;
#pragma unroll
        for (int c = 0; c < 32; c++)
            qb = fmaf(sq[nn][h * 32 + c], sbe[h * 32 + c], qb);
        g_qbe[n * 4 + h] = qb;
    }
}

// ---------------------------------------------------------------------------
// Warp-per-node attention with 4-edge software pipeline + beta gate + LN1.
// ---------------------------------------------------------------------------
__global__ void __launch_bounds__(256)
node_attn_kernel(const float* __restrict__ We, const float* __restrict__ be,
                 const float* __restrict__ x,  const float* __restrict__ Wbeta,
                 const float* __restrict__ g1, const float* __restrict__ b1,
                 int N)
{
    __shared__ float sWe[EDIM][DIM];
    __shared__ float sbe[DIM];
    for (int i = threadIdx.x; i < EDIM * DIM; i += 256)
        ((float*)sWe)[i] = We[i];
    if (threadIdx.x < DIM) sbe[threadIdx.x] = be[threadIdx.x];
    __syncthreads();

    const int lane = threadIdx.x & 31;
    const int g = lane >> 3;
    const int l8 = lane & 7;
    const int ch0 = g * 32 + l8 * 4;
    const int warp = blockIdx.x * (blockDim.x >> 5) + (threadIdx.x >> 5);
    const int nwarps = gridDim.x * (blockDim.x >> 5);

    for (int n = warp; n < N; n += nwarps) {
        float4 q4 = *(const float4*)&g_q[(size_t)n * DIM + ch0];
        float2 qwe2 = *(const float2*)&g_qwe[(size_t)n * 64 + g * 16 + 2 * l8];
        float qbe = g_qbe[n * 4 + g];

        float4 acc = make_float4(0.f, 0.f, 0.f, 0.f);
        float s0 = 0.f, s1 = 0.f, den = 0.f;

        int beg = g_rowptr[n], end = g_rowptr[n + 1];
        int p = beg;
        for (; p + 4 <= end; p += 4) {
            int sA = __ldg(&g_ssrc[p]);
            int sB = __ldg(&g_ssrc[p + 1]);
            int sC = __ldg(&g_ssrc[p + 2]);
            int sD = __ldg(&g_ssrc[p + 3]);
            float4 kA = *(const float4*)&g_k[(size_t)sA * DIM + ch0];
            float4 kB = *(const float4*)&g_k[(size_t)sB * DIM + ch0];
            float4 kC = *(const float4*)&g_k[(size_t)sC * DIM + ch0];
            float4 kD = *(const float4*)&g_k[(size_t)sD * DIM + ch0];
            float4 vA = *(const float4*)&g_v[(size_t)sA * DIM + ch0];
            float4 vB = *(const float4*)&g_v[(size_t)sB * DIM + ch0];
            float4 vC = *(const float4*)&g_v[(size_t)sC * DIM + ch0];
            float4 vD = *(const float4*)&g_v[(size_t)sD * DIM + ch0];
            float2 aA = *(const float2*)&g_eperm[(size_t)p * EDIM + 2 * l8];
            float2 aB = *(const float2*)&g_eperm[(size_t)(p + 1) * EDIM + 2 * l8];
            float2 aC = *(const float2*)&g_eperm[(size_t)(p + 2) * EDIM + 2 * l8];
            float2 aD = *(const float2*)&g_eperm[(size_t)(p + 3) * EDIM + 2 * l8];

            float pA = q4.x * kA.x + q4.y * kA.y + q4.z * kA.z + q4.w * kA.w
                     + aA.x * qwe2.x + aA.y * qwe2.y;
            float pB = q4.x * kB.x + q4.y * kB.y + q4.z * kB.z + q4.w * kB.w
                     + aB.x * qwe2.x + aB.y * qwe2.y;
            float pC = q4.x * kC.x + q4.y * kC.y + q4.z * kC.z + q4.w * kC.w
                     + aC.x * qwe2.x + aC.y * qwe2.y;
            float pD = q4.x * kD.x + q4.y * kD.y + q4.z * kD.z + q4.w * kD.w
                     + aD.x * qwe2.x + aD.y * qwe2.y;
            pA += __shfl_xor_sync(0xffffffffu, pA, 1);
            pB += __shfl_xor_sync(0xffffffffu, pB, 1);
            pC += __shfl_xor_sync(0xffffffffu, pC, 1);
            pD += __shfl_xor_sync(0xffffffffu, pD, 1);
            pA += __shfl_xor_sync(0xffffffffu, pA, 2);
            pB += __shfl_xor_sync(0xffffffffu, pB, 2);
            pC += __shfl_xor_sync(0xffffffffu, pC, 2);
            pD += __shfl_xor_sync(0xffffffffu, pD, 2);
            pA += __shfl_xor_sync(0xffffffffu, pA, 4);
            pB += __shfl_xor_sync(0xffffffffu, pB, 4);
            pC += __shfl_xor_sync(0xffffffffu, pC, 4);
            pD += __shfl_xor_sync(0xffffffffu, pD, 4);
            float eA = __expf(pA + qbe);
            float eB = __expf(pB + qbe);
            float eC = __expf(pC + qbe);
            float eD = __expf(pD + qbe);
            den += eA;
            acc.x = fmaf(eA, vA.x, acc.x); acc.y = fmaf(eA, vA.y, acc.y);
            acc.z = fmaf(eA, vA.z, acc.z); acc.w = fmaf(eA, vA.w, acc.w);
            s0 = fmaf(eA, aA.x, s0); s1 = fmaf(eA, aA.y, s1);
            den += eB;
            acc.x = fmaf(eB, vB.x, acc.x); acc.y = fmaf(eB, vB.y, acc.y);
            acc.z = fmaf(eB, vB.z, acc.z); acc.w = fmaf(eB, vB.w, acc.w);
            s0 = fmaf(eB, aB.x, s0); s1 = fmaf(eB, aB.y, s1);
            den += eC;
            acc.x = fmaf(eC, vC.x, acc.x); acc.y = fmaf(eC, vC.y, acc.y);
            acc.z = fmaf(eC, vC.z, acc.z); acc.w = fmaf(eC, vC.w, acc.w);
            s0 = fmaf(eC, aC.x, s0); s1 = fmaf(eC, aC.y, s1);
            den += eD;
            acc.x = fmaf(eD, vD.x, acc.x); acc.y = fmaf(eD, vD.y, acc.y);
            acc.z = fmaf(eD, vD.z, acc.z); acc.w = fmaf(eD, vD.w, acc.w);
            s0 = fmaf(eD, aD.x, s0); s1 = fmaf(eD, aD.y, s1);
        }
        for (; p < end; p++) {
            int sA = __ldg(&g_ssrc[p]);
            float2 aA = *(const float2*)&g_eperm[(size_t)p * EDIM + 2 * l8];
            float4 kA = *(const float4*)&g_k[(size_t)sA * DIM + ch0];
            float4 vA = *(const float4*)&g_v[(size_t)sA * DIM + ch0];
            float pp = q4.x * kA.x + q4.y * kA.y + q4.z * kA.z + q4.w * kA.w
                     + aA.x * qwe2.x + aA.y * qwe2.y;
            pp += __shfl_xor_sync(0xffffffffu, pp, 1);
            pp += __shfl_xor_sync(0xffffffffu, pp, 2);
            pp += __shfl_xor_sync(0xffffffffu, pp, 4);
            float ea = __expf(pp + qbe);
            den += ea;
            acc.x = fmaf(ea, vA.x, acc.x); acc.y = fmaf(ea, vA.y, acc.y);
            acc.z = fmaf(ea, vA.z, acc.z); acc.w = fmaf(ea, vA.w, acc.w);
            s0 = fmaf(ea, aA.x, s0); s1 = fmaf(ea, aA.y, s1);
        }

        // unfactor: ev = den*be + sum_j s_j * We[j]
        float4 ev;
        ev.x = den * sbe[ch0];
        ev.y = den * sbe[ch0 + 1];
        ev.z = den * sbe[ch0 + 2];
        ev.w = den * sbe[ch0 + 3];
#pragma unroll
        for (int jj = 0; jj < 8; jj++) {
            int srcl = (g << 3) | jj;
            float sj0 = __shfl_sync(0xffffffffu, s0, srcl);
            float sj1 = __shfl_sync(0xffffffffu, s1, srcl);
            float4 w0 = *(const float4*)&sWe[2 * jj][ch0];
            float4 w1 = *(const float4*)&sWe[2 * jj + 1][ch0];
            ev.x += sj0 * w0.x + sj1 * w1.x;
            ev.y += sj0 * w0.y + sj1 * w1.y;
            ev.z += sj0 * w0.z + sj1 * w1.z;
            ev.w += sj0 * w0.w + sj1 * w1.w;
        }
        float rden = 1.0f / (den + 1e-16f);
        float o[4] = {(acc.x + ev.x) * rden, (acc.y + ev.y) * rden,
                      (acc.z + ev.z) * rden, (acc.w + ev.w) * rden};

        float4 xr4 = *(const float4*)&g_xr[(size_t)n * DIM + ch0];
        float4 wb0 = *(const float4*)&Wbeta[ch0];
        float4 wb1 = *(const float4*)&Wbeta[DIM + ch0];
        float4 wb2 = *(const float4*)&Wbeta[2 * DIM + ch0];
        float xr[4] = {xr4.x, xr4.y, xr4.z, xr4.w};
        float z = wb0.x * o[0] + wb1.x * xr[0] + wb2.x * (o[0] - xr[0])
                + wb0.y * o[1] + wb1.y * xr[1] + wb2.y * (o[1] - xr[1])
                + wb0.z * o[2] + wb1.z * xr[2] + wb2.z * (o[2] - xr[2])
                + wb0.w * o[3] + wb1.w * xr[3] + wb2.w * (o[3] - xr[3]);
        z = warpSum(z);
        float beta = 1.0f / (1.0f + __expf(-z));

        float4 xv = *(const float4*)&x[(size_t)n * DIM + ch0];
        float xx[4] = {xv.x, xv.y, xv.z, xv.w};
        float tv[4], ts = 0.f;
#pragma unroll
        for (int c = 0; c < 4; c++) {
            tv[c] = xx[c] + beta * xr[c] + (1.0f - beta) * o[c];
            ts += tv[c];
        }
        float mu = warpSum(ts) * (1.0f / 128.0f);
        float vs = 0.f;
#pragma unroll
        for (int c = 0; c < 4; c++) { tv[c] -= mu; vs += tv[c] * tv[c]; }
        float var = warpSum(vs) * (1.0f / 128.0f);
        float inv = rsqrtf(var + 1e-5f);

        float4 gg = *(const float4*)&g1[ch0];
        float4 bb = *(const float4*)&b1[ch0];
        float4 st;
        st.x = tv[0] * inv * gg.x + bb.x;
        st.y = tv[1] * inv * gg.y + bb.y;
        st.z = tv[2] * inv * gg.z + bb.z;
        st.w = tv[3] * inv * gg.w + bb.w;
        *(float4*)&g_h[(size_t)n * DIM + ch0] = st;
    }
}

// ---------------------------------------------------------------------------
// Launch (fork-join streams: CSR chain || projections)
// ---------------------------------------------------------------------------
extern "C" void kernel_launch(void* const* d_in, const int* in_sizes, int n_in,
                              void* d_out, int out_size)
{
    const float* x      = (const float*)d_in[0];
    const void*  eidx   = d_in[1];
    const float* eattr  = (const float*)d_in[2];
    const float* Wq     = (const float*)d_in[3];
    const float* bq     = (const float*)d_in[4];
    const float* Wk     = (const float*)d_in[5];
    const float* bk     = (const float*)d_in[6];
    const float* Wv     = (const float*)d_in[7];
    const float* bv     = (const float*)d_in[8];
    const float* We     = (const float*)d_in[9];
    const float* be     = (const float*)d_in[10];
    const float* Ws     = (const float*)d_in[11];
    const float* bs     = (const float*)d_in[12];
    const float* Wbeta  = (const float*)d_in[13];
    const float* g1     = (const float*)d_in[14];
    const float* b1     = (const float*)d_in[15];
    const float* Wf1    = (const float*)d_in[16];
    const float* bf1    = (const float*)d_in[17];
    const float* Wf2    = (const float*)d_in[18];
    const float* bf2    = (const float*)d_in[19];
    const float* g2     = (const float*)d_in[20];
    const float* b2     = (const float*)d_in[21];

    const int N = in_sizes[0] / DIM;
    const int E = in_sizes[1] / 2;

    float *h, *ff1;
    cudaGetSymbolAddress((void**)&h,   g_h);
    cudaGetSymbolAddress((void**)&ff1, g_ff1);

    static cudaStream_t s1 = nullptr;
    static cudaEvent_t evFork = nullptr, evCsr = nullptr;
    if (!s1) {
        cudaStreamCreate(&s1);
        cudaEventCreateWithFlags(&evFork, cudaEventDisableTiming);
        cudaEventCreateWithFlags(&evCsr, cudaEventDisableTiming);
    }

    const int nb = (N + 1023) / 1024;
    const int gm = (N + 127) / 128;

    // fork
    cudaEventRecord(evFork, 0);
    cudaStreamWaitEvent(s1, evFork, 0);

    // CSR chain + eattr permute on s1
    detect_idx_kernel<<<1, 32, 0, s1>>>((const int*)eidx);
    zero_cnt_kernel<<<(N + 255) / 256, 256, 0, s1>>>(N);
    convert_idx_kernel<<<(E + 255) / 256, 256, 0, s1>>>(eidx, E);
    scanA_kernel<<<nb, 1024, 0, s1>>>(N);
    scanB_kernel<<<1, 32, 0, s1>>>(nb, N, E);
    scanC_kernel<<<nb, 1024, 0, s1>>>(N);
    scatter_kernel<<<(E + 255) / 256, 256, 0, s1>>>(E);
    permute_eattr_kernel<<<(E * 4 + 255) / 256, 256, 0, s1>>>(eattr, E);
    cudaEventRecord(evCsr, s1);

    // projections + qwe on default stream
    dim3 gproj(gm, 4);
    proj_mma_kernel<<<gproj, 256>>>(x, Wq, bq, Wk, bk, Wv, bv, Ws, bs, N);
    qwe_kernel<<<(N + 3) / 4, 256>>>(We, be, N);

    // join
    cudaStreamWaitEvent(0, evCsr, 0);

    node_attn_kernel<<<1184, 256>>>(We, be, x, Wbeta, g1, b1, N);

    dim3 gff1(gm, 4);
    ff1_mma_kernel<<<gff1, 256>>>(h, Wf1, bf1, ff1, N);
    ff2_mma_kernel<<<gm, 256>>>(ff1, Wf2, bf2, (float*)d_out, h, g2, b2, N);
}

// round 8
// speedup vs baseline: 2.8263x; 1.0923x over previous
#include <cuda_runtime.h>
#include <cuda_bf16.h>
#include <math.h>

#define NMAX 50000
#define EMAX 800000
#define DIM  128
#define HEADS 4
#define CH   32
#define EDIM 16
#define QSCALE 0.17677669529663687f   // 1/sqrt(32)

// ---------------------------------------------------------------------------
// Scratch
// ---------------------------------------------------------------------------
__device__ float g_q[NMAX * DIM];
__device__ float g_k[NMAX * DIM];
__device__ float g_v[NMAX * DIM];
__device__ float g_xr[NMAX * DIM];
__device__ float g_h[NMAX * DIM];
__device__ float g_ff1[NMAX * 4 * DIM];
__device__ float g_qwe[(size_t)NMAX * 64];
__device__ float g_qbe[NMAX * 4];
__device__ float g_eperm[(size_t)EMAX * EDIM];
__device__ int   g_src[EMAX];
__device__ int   g_dst[EMAX];
__device__ int   g_ssrc[EMAX];
__device__ int   g_eid[EMAX];
__device__ int   g_cnt[NMAX];
__device__ int   g_rowptr[NMAX + 1];
__device__ int   g_woff[NMAX];
__device__ int   g_bsum[64];
__device__ int   g_boff[64];
__device__ int   g_idx64;

// ---------------------------------------------------------------------------
// Helpers
// ---------------------------------------------------------------------------
__device__ __forceinline__ float warpSum(float v) {
#pragma unroll
    for (int off = 16; off; off >>= 1)
        v += __shfl_xor_sync(0xffffffffu, v, off);
    return v;
}

__device__ __forceinline__ float to_tf32(float x) {
    float r;
    asm("cvt.rna.tf32.f32 %0, %1;" : "=f"(r) : "f"(x));
    return r;
}

__device__ __forceinline__ void mma_tf32(float c[4],
                                         unsigned a0, unsigned a1, unsigned a2, unsigned a3,
                                         unsigned b0, unsigned b1) {
    asm volatile(
        "mma.sync.aligned.m16n8k8.row.col.f32.tf32.tf32.f32 "
        "{%0,%1,%2,%3},{%4,%5,%6,%7},{%8,%9},{%0,%1,%2,%3};"
        : "+f"(c[0]), "+f"(c[1]), "+f"(c[2]), "+f"(c[3])
        : "r"(a0), "r"(a1), "r"(a2), "r"(a3), "r"(b0), "r"(b1));
}

// ---------------------------------------------------------------------------
// Index detect / convert (+fused histogram)
// ---------------------------------------------------------------------------
__global__ void detect_idx_kernel(const int* raw) {
    if (threadIdx.x == 0) {
        int all_hi_zero = 1, any_lo_nonzero = 0;
        for (int i = 0; i < 256; i++) {
            if (raw[2 * i + 1] != 0) all_hi_zero = 0;
            if (raw[2 * i] != 0) any_lo_nonzero = 1;
        }
        g_idx64 = (all_hi_zero && any_lo_nonzero) ? 1 : 0;
    }
}

__global__ void zero_cnt_kernel(int N) {
    int i = blockIdx.x * blockDim.x + threadIdx.x;
    if (i < N) g_cnt[i] = 0;
}

__global__ void convert_idx_kernel(const void* raw, int E) {
    int i = blockIdx.x * blockDim.x + threadIdx.x;
    if (i >= E) return;
    int s, d;
    if (g_idx64) {
        const long long* p = (const long long*)raw;
        s = (int)p[i];
        d = (int)p[E + i];
    } else {
        const int* p = (const int*)raw;
        s = p[i];
        d = p[E + i];
    }
    g_src[i] = s;
    g_dst[i] = d;
    atomicAdd(&g_cnt[d], 1);
}

// ---------------------------------------------------------------------------
// 3-phase exclusive scan
// ---------------------------------------------------------------------------
__global__ void __launch_bounds__(1024)
scanA_kernel(int N) {
    __shared__ int wsum[32];
    int t = threadIdx.x;
    int i = blockIdx.x * 1024 + t;
    int v = (i < N) ? g_cnt[i] : 0;
    int inc = v;
#pragma unroll
    for (int off = 1; off < 32; off <<= 1) {
        int u = __shfl_up_sync(0xffffffffu, inc, off);
        if ((t & 31) >= off) inc += u;
    }
    if ((t & 31) == 31) wsum[t >> 5] = inc;
    __syncthreads();
    if (t < 32) {
        int w = wsum[t];
        int wi = w;
#pragma unroll
        for (int off = 1; off < 32; off <<= 1) {
            int u = __shfl_up_sync(0xffffffffu, wi, off);
            if (t >= off) wi += u;
        }
        wsum[t] = wi - w;
    }
    __syncthreads();
    int exc = inc - v + wsum[t >> 5];
    if (i < N) g_rowptr[i] = exc;
    if (t == 1023) g_bsum[blockIdx.x] = exc + v;
}

__global__ void scanB_kernel(int nb, int N, int E) {
    int lane = threadIdx.x;
    int v0 = (lane < nb) ? g_bsum[lane] : 0;
    int v1 = (32 + lane < nb) ? g_bsum[32 + lane] : 0;
    int i0 = v0, i1 = v1;
#pragma unroll
    for (int off = 1; off < 32; off <<= 1) {
        int u = __shfl_up_sync(0xffffffffu, i0, off);
        if (lane >= off) i0 += u;
        int u2 = __shfl_up_sync(0xffffffffu, i1, off);
        if (lane >= off) i1 += u2;
    }
    int tot0 = __shfl_sync(0xffffffffu, i0, 31);
    i1 += tot0;
    g_boff[lane] = i0 - v0;
    g_boff[32 + lane] = i1 - v1;
    if (lane == 0) g_rowptr[N] = E;
}

__global__ void __launch_bounds__(1024)
scanC_kernel(int N) {
    int i = blockIdx.x * 1024 + threadIdx.x;
    if (i < N) {
        int r = g_rowptr[i] + g_boff[blockIdx.x];
        g_rowptr[i] = r;
        g_woff[i] = r;
    }
}

__global__ void scatter_kernel(int E) {
    int i = blockIdx.x * blockDim.x + threadIdx.x;
    if (i >= E) return;
    int d = g_dst[i];
    int pos = atomicAdd(&g_woff[d], 1);
    g_ssrc[pos] = g_src[i];
    g_eid[pos] = i;
}

__global__ void __launch_bounds__(256)
permute_eattr_kernel(const float* __restrict__ eattr, int E) {
    int i = blockIdx.x * blockDim.x + threadIdx.x;
    if (i >= E * 4) return;
    int p = i >> 2, q = (i & 3) * 4;
    int e = g_eid[p];
    *(float4*)&g_eperm[(size_t)p * EDIM + q] =
        *(const float4*)&eattr[(size_t)e * EDIM + q];
}

// ---------------------------------------------------------------------------
// TF32 MMA core: BK=16, double-buffered smem, ONE sync per k-tile.
// NOTE: macro loop variable renamed to _t to avoid capturing the caller's t.
// ---------------------------------------------------------------------------
__device__ __forceinline__ void mma_core(
    const float* __restrict__ A, const float* __restrict__ B,
    int M, int K, int Nout, int n_base, int m0,
    float (&acc)[2][8][4], float (&As)[2][128][20], float (&Bs)[2][16][136])
{
    const int tid = threadIdx.x;
    const int lane = tid & 31;
    const int wid = tid >> 5;
    const int warp_m = wid & 3;
    const int warp_n = wid >> 2;

#pragma unroll
    for (int i = 0; i < 2; i++)
#pragma unroll
        for (int j = 0; j < 8; j++)
#pragma unroll
            for (int c = 0; c < 4; c++) acc[i][j][c] = 0.f;

    float4 pa[2], pb[2];

#define LOAD_TILE(K0)                                                         \
    {                                                                         \
        const int k0c_ = (K0);                                                \
        _Pragma("unroll")                                                     \
        for (int _t = 0; _t < 2; _t++) {                                      \
            int j = tid + _t * 256;                                           \
            int r = j >> 2, q = (j & 3) * 4;                                  \
            pa[_t] = (m0 + r < M)                                             \
                ? *(const float4*)&A[(size_t)(m0 + r) * K + k0c_ + q]         \
                : make_float4(0.f, 0.f, 0.f, 0.f);                            \
            int br = j >> 5, c4 = (j & 31) * 4;                               \
            pb[_t] = *(const float4*)&B[(size_t)(k0c_ + br) * Nout + n_base + c4]; \
        }                                                                     \
    }

#define STORE_TILE(BUF)                                                       \
    {                                                                         \
        const int buf_ = (BUF);                                               \
        _Pragma("unroll")                                                     \
        for (int _t = 0; _t < 2; _t++) {                                      \
            int j = tid + _t * 256;                                           \
            int r = j >> 2, q = (j & 3) * 4;                                  \
            As[buf_][r][q + 0] = to_tf32(pa[_t].x);                           \
            As[buf_][r][q + 1] = to_tf32(pa[_t].y);                           \
            As[buf_][r][q + 2] = to_tf32(pa[_t].z);                           \
            As[buf_][r][q + 3] = to_tf32(pa[_t].w);                           \
            int br = j >> 5, c4 = (j & 31) * 4;                               \
            Bs[buf_][br][c4 + 0] = to_tf32(pb[_t].x);                         \
            Bs[buf_][br][c4 + 1] = to_tf32(pb[_t].y);                         \
            Bs[buf_][br][c4 + 2] = to_tf32(pb[_t].z);                         \
            Bs[buf_][br][c4 + 3] = to_tf32(pb[_t].w);                         \
        }                                                                     \
    }

    LOAD_TILE(0);
    STORE_TILE(0);
    __syncthreads();

    const int T = K >> 4;
#pragma unroll 2
    for (int t = 0; t < T; t++) {
        if (t + 1 < T) LOAD_TILE((t + 1) << 4);
        const int b = t & 1;
#pragma unroll
        for (int kk = 0; kk < 16; kk += 8) {
            unsigned bf[8][2];
#pragma unroll
            for (int nt = 0; nt < 8; nt++) {
                int n = warp_n * 64 + nt * 8 + (lane >> 2);
                bf[nt][0] = __float_as_uint(Bs[b][kk + (lane & 3)][n]);
                bf[nt][1] = __float_as_uint(Bs[b][kk + 4 + (lane & 3)][n]);
            }
#pragma unroll
            for (int mt = 0; mt < 2; mt++) {
                int r0 = warp_m * 32 + mt * 16 + (lane >> 2);
                unsigned a0 = __float_as_uint(As[b][r0][kk + (lane & 3)]);
                unsigned a1 = __float_as_uint(As[b][r0 + 8][kk + (lane & 3)]);
                unsigned a2 = __float_as_uint(As[b][r0][kk + 4 + (lane & 3)]);
                unsigned a3 = __float_as_uint(As[b][r0 + 8][kk + 4 + (lane & 3)]);
#pragma unroll
                for (int nt = 0; nt < 8; nt++)
                    mma_tf32(acc[mt][nt], a0, a1, a2, a3, bf[nt][0], bf[nt][1]);
            }
        }
        if (t + 1 < T) STORE_TILE((t + 1) & 1);
        __syncthreads();
    }
#undef LOAD_TILE
#undef STORE_TILE
}

// ---------------------------------------------------------------------------
// proj4 (q/k/v/skip) via tensor cores; q scaled at store.
// ---------------------------------------------------------------------------
__global__ void __launch_bounds__(256)
proj_mma_kernel(const float* __restrict__ A,
                const float* __restrict__ Wq, const float* __restrict__ bq,
                const float* __restrict__ Wk, const float* __restrict__ bk,
                const float* __restrict__ Wv, const float* __restrict__ bv,
                const float* __restrict__ Ws, const float* __restrict__ bs,
                int M)
{
    const float* B; const float* bias; float* C; float scale;
    switch (blockIdx.y) {
        case 0: B = Wq; bias = bq; C = g_q;  scale = QSCALE; break;
        case 1: B = Wk; bias = bk; C = g_k;  scale = 1.f;    break;
        case 2: B = Wv; bias = bv; C = g_v;  scale = 1.f;    break;
        default: B = Ws; bias = bs; C = g_xr; scale = 1.f;   break;
    }
    __shared__ float As[2][128][20];
    __shared__ float Bs[2][16][136];
    float acc[2][8][4];
    const int m0 = blockIdx.x * 128;
    mma_core(A, B, M, DIM, DIM, 0, m0, acc, As, Bs);

    const int lane = threadIdx.x & 31;
    const int wid = threadIdx.x >> 5;
    const int warp_m = wid & 3, warp_n = wid >> 2;
#pragma unroll
    for (int mt = 0; mt < 2; mt++)
#pragma unroll
        for (int h2 = 0; h2 < 2; h2++) {
            int m = m0 + warp_m * 32 + mt * 16 + (lane >> 2) + h2 * 8;
            if (m >= M) continue;
#pragma unroll
            for (int nt = 0; nt < 8; nt++) {
                int col = warp_n * 64 + nt * 8 + (lane & 3) * 2;
                float2 st;
                st.x = (acc[mt][nt][h2 * 2]     + __ldg(&bias[col]))     * scale;
                st.y = (acc[mt][nt][h2 * 2 + 1] + __ldg(&bias[col + 1])) * scale;
                *(float2*)&C[(size_t)m * DIM + col] = st;
            }
        }
}

// ---------------------------------------------------------------------------
// FF1: relu(h @ Wf1 + bf1). Nout=512, grid.y = 4.
// ---------------------------------------------------------------------------
__global__ void __launch_bounds__(256)
ff1_mma_kernel(const float* __restrict__ A, const float* __restrict__ B,
               const float* __restrict__ bias, float* __restrict__ C, int M)
{
    __shared__ float As[2][128][20];
    __shared__ float Bs[2][16][136];
    float acc[2][8][4];
    const int m0 = blockIdx.x * 128;
    const int n_base = blockIdx.y * 128;
    mma_core(A, B, M, DIM, 4 * DIM, n_base, m0, acc, As, Bs);

    const int lane = threadIdx.x & 31;
    const int wid = threadIdx.x >> 5;
    const int warp_m = wid & 3, warp_n = wid >> 2;
#pragma unroll
    for (int mt = 0; mt < 2; mt++)
#pragma unroll
        for (int h2 = 0; h2 < 2; h2++) {
            int m = m0 + warp_m * 32 + mt * 16 + (lane >> 2) + h2 * 8;
            if (m >= M) continue;
#pragma unroll
            for (int nt = 0; nt < 8; nt++) {
                int col = n_base + warp_n * 64 + nt * 8 + (lane & 3) * 2;
                float2 st;
                st.x = fmaxf(acc[mt][nt][h2 * 2]     + __ldg(&bias[col]), 0.f);
                st.y = fmaxf(acc[mt][nt][h2 * 2 + 1] + __ldg(&bias[col + 1]), 0.f);
                *(float2*)&C[(size_t)m * 4 * DIM + col] = st;
            }
        }
}

// ---------------------------------------------------------------------------
// FF2: ff1 @ Wf2 + bf2 + res, then LayerNorm(g2,b2). Nout=128.
// ---------------------------------------------------------------------------
__global__ void __launch_bounds__(256)
ff2_mma_kernel(const float* __restrict__ A, const float* __restrict__ B,
               const float* __restrict__ bias, float* __restrict__ C,
               const float* __restrict__ res,
               const float* __restrict__ gamma, const float* __restrict__ betap,
               int M)
{
    __shared__ float As[2][128][20];
    __shared__ float Bs[2][16][136];
    __shared__ float pr[128][2];
    float acc[2][8][4];
    const int m0 = blockIdx.x * 128;
    mma_core(A, B, M, 4 * DIM, DIM, 0, m0, acc, As, Bs);

    const int lane = threadIdx.x & 31;
    const int wid = threadIdx.x >> 5;
    const int warp_m = wid & 3, warp_n = wid >> 2;

    float mu[2][2];
#pragma unroll
    for (int mt = 0; mt < 2; mt++)
#pragma unroll
        for (int h2 = 0; h2 < 2; h2++) {
            int row = warp_m * 32 + mt * 16 + (lane >> 2) + h2 * 8;
            int m = m0 + row;
            float s = 0.f;
#pragma unroll
            for (int nt = 0; nt < 8; nt++) {
                int col = warp_n * 64 + nt * 8 + (lane & 3) * 2;
                float r0 = (m < M) ? res[(size_t)m * DIM + col]     : 0.f;
                float r1 = (m < M) ? res[(size_t)m * DIM + col + 1] : 0.f;
                float t0 = acc[mt][nt][h2 * 2]     + __ldg(&bias[col])     + r0;
                float t1 = acc[mt][nt][h2 * 2 + 1] + __ldg(&bias[col + 1]) + r1;
                acc[mt][nt][h2 * 2] = t0;
                acc[mt][nt][h2 * 2 + 1] = t1;
                s += t0 + t1;
            }
            s += __shfl_xor_sync(0xffffffffu, s, 1);
            s += __shfl_xor_sync(0xffffffffu, s, 2);
            if ((lane & 3) == 0) pr[row][warp_n] = s;
        }
    __syncthreads();
#pragma unroll
    for (int mt = 0; mt < 2; mt++)
#pragma unroll
        for (int h2 = 0; h2 < 2; h2++) {
            int row = warp_m * 32 + mt * 16 + (lane >> 2) + h2 * 8;
            mu[mt][h2] = (pr[row][0] + pr[row][1]) * (1.0f / 128.0f);
        }
    __syncthreads();
#pragma unroll
    for (int mt = 0; mt < 2; mt++)
#pragma unroll
        for (int h2 = 0; h2 < 2; h2++) {
            int row = warp_m * 32 + mt * 16 + (lane >> 2) + h2 * 8;
            float vs = 0.f;
#pragma unroll
            for (int nt = 0; nt < 8; nt++) {
                float d0 = acc[mt][nt][h2 * 2]     - mu[mt][h2];
                float d1 = acc[mt][nt][h2 * 2 + 1] - mu[mt][h2];
                vs += d0 * d0 + d1 * d1;
            }
            vs += __shfl_xor_sync(0xffffffffu, vs, 1);
            vs += __shfl_xor_sync(0xffffffffu, vs, 2);
            if ((lane & 3) == 0) pr[row][warp_n] = vs;
        }
    __syncthreads();
#pragma unroll
    for (int mt = 0; mt < 2; mt++)
#pragma unroll
        for (int h2 = 0; h2 < 2; h2++) {
            int row = warp_m * 32 + mt * 16 + (lane >> 2) + h2 * 8;
            int m = m0 + row;
            if (m >= M) continue;
            float var = (pr[row][0] + pr[row][1]) * (1.0f / 128.0f);
            float inv = rsqrtf(var + 1e-5f);
#pragma unroll
            for (int nt = 0; nt < 8; nt++) {
                int col = warp_n * 64 + nt * 8 + (lane & 3) * 2;
                float2 st;
                st.x = (acc[mt][nt][h2 * 2]     - mu[mt][h2]) * inv * __ldg(&gamma[col])     + __ldg(&betap[col]);
                st.y = (acc[mt][nt][h2 * 2 + 1] - mu[mt][h2]) * inv * __ldg(&gamma[col + 1]) + __ldg(&betap[col + 1]);
                *(float2*)&C[(size_t)m * DIM + col] = st;
            }
        }
}

// ---------------------------------------------------------------------------
// qwe precompute
// ---------------------------------------------------------------------------
__global__ void __launch_bounds__(256)
qwe_kernel(const float* __restrict__ We, const float* __restrict__ be, int N)
{
    __shared__ float sWe[EDIM * DIM];
    __shared__ float sq[4][DIM];
    __shared__ float sbe[DIM];
    int tid = threadIdx.x;
    for (int i = tid; i < EDIM * DIM; i += 256) sWe[i] = We[i];
    if (tid < DIM) sbe[tid] = be[tid];
    int n0 = blockIdx.x * 4;
    for (int i = tid; i < 4 * DIM; i += 256) {
        int nn = i >> 7, c = i & 127;
        sq[nn][c] = (n0 + nn < N) ? g_q[(size_t)(n0 + nn) * DIM + c] : 0.f;
    }
    __syncthreads();
    int nn = tid >> 6, r = tid & 63, h = r >> 4, i = r & 15;
    int n = n0 + nn;
    if (n >= N) return;
    float a = 0.f;
#pragma unroll
    for (int c = 0; c < 32; c++)
        a = fmaf(sq[nn][h * 32 + c], sWe[i * DIM + h * 32 + c], a);
    g_qwe[(size_t)n * 64 + h * 16 + i] = a;
    if (i == 0) {
        float qb = 0.f;
#pragma unroll
        for (int c = 0; c < 32; c++)
            qb = fmaf(sq[nn][h * 32 + c], sbe[h * 32 + c], qb);
        g_qbe[n * 4 + h] = qb;
    }
}

// ---------------------------------------------------------------------------
// Warp-per-node attention with 4-edge software pipeline + beta gate + LN1.
// ---------------------------------------------------------------------------
__global__ void __launch_bounds__(256)
node_attn_kernel(const float* __restrict__ We, const float* __restrict__ be,
                 const float* __restrict__ x,  const float* __restrict__ Wbeta,
                 const float* __restrict__ g1, const float* __restrict__ b1,
                 int N)
{
    __shared__ float sWe[EDIM][DIM];
    __shared__ float sbe[DIM];
    for (int i = threadIdx.x; i < EDIM * DIM; i += 256)
        ((float*)sWe)[i] = We[i];
    if (threadIdx.x < DIM) sbe[threadIdx.x] = be[threadIdx.x];
    __syncthreads();

    const int lane = threadIdx.x & 31;
    const int g = lane >> 3;
    const int l8 = lane & 7;
    const int ch0 = g * 32 + l8 * 4;
    const int warp = blockIdx.x * (blockDim.x >> 5) + (threadIdx.x >> 5);
    const int nwarps = gridDim.x * (blockDim.x >> 5);

    for (int n = warp; n < N; n += nwarps) {
        float4 q4 = *(const float4*)&g_q[(size_t)n * DIM + ch0];
        float2 qwe2 = *(const float2*)&g_qwe[(size_t)n * 64 + g * 16 + 2 * l8];
        float qbe = g_qbe[n * 4 + g];

        float4 acc = make_float4(0.f, 0.f, 0.f, 0.f);
        float s0 = 0.f, s1 = 0.f, den = 0.f;

        int beg = g_rowptr[n], end = g_rowptr[n + 1];
        int p = beg;
        for (; p + 4 <= end; p += 4) {
            int sA = __ldg(&g_ssrc[p]);
            int sB = __ldg(&g_ssrc[p + 1]);
            int sC = __ldg(&g_ssrc[p + 2]);
            int sD = __ldg(&g_ssrc[p + 3]);
            float4 kA = *(const float4*)&g_k[(size_t)sA * DIM + ch0];
            float4 kB = *(const float4*)&g_k[(size_t)sB * DIM + ch0];
            float4 kC = *(const float4*)&g_k[(size_t)sC * DIM + ch0];
            float4 kD = *(const float4*)&g_k[(size_t)sD * DIM + ch0];
            float4 vA = *(const float4*)&g_v[(size_t)sA * DIM + ch0];
            float4 vB = *(const float4*)&g_v[(size_t)sB * DIM + ch0];
            float4 vC = *(const float4*)&g_v[(size_t)sC * DIM + ch0];
            float4 vD = *(const float4*)&g_v[(size_t)sD * DIM + ch0];
            float2 aA = *(const float2*)&g_eperm[(size_t)p * EDIM + 2 * l8];
            float2 aB = *(const float2*)&g_eperm[(size_t)(p + 1) * EDIM + 2 * l8];
            float2 aC = *(const float2*)&g_eperm[(size_t)(p + 2) * EDIM + 2 * l8];
            float2 aD = *(const float2*)&g_eperm[(size_t)(p + 3) * EDIM + 2 * l8];

            float pA = q4.x * kA.x + q4.y * kA.y + q4.z * kA.z + q4.w * kA.w
                     + aA.x * qwe2.x + aA.y * qwe2.y;
            float pB = q4.x * kB.x + q4.y * kB.y + q4.z * kB.z + q4.w * kB.w
                     + aB.x * qwe2.x + aB.y * qwe2.y;
            float pC = q4.x * kC.x + q4.y * kC.y + q4.z * kC.z + q4.w * kC.w
                     + aC.x * qwe2.x + aC.y * qwe2.y;
            float pD = q4.x * kD.x + q4.y * kD.y + q4.z * kD.z + q4.w * kD.w
                     + aD.x * qwe2.x + aD.y * qwe2.y;
            pA += __shfl_xor_sync(0xffffffffu, pA, 1);
            pB += __shfl_xor_sync(0xffffffffu, pB, 1);
            pC += __shfl_xor_sync(0xffffffffu, pC, 1);
            pD += __shfl_xor_sync(0xffffffffu, pD, 1);
            pA += __shfl_xor_sync(0xffffffffu, pA, 2);
            pB += __shfl_xor_sync(0xffffffffu, pB, 2);
            pC += __shfl_xor_sync(0xffffffffu, pC, 2);
            pD += __shfl_xor_sync(0xffffffffu, pD, 2);
            pA += __shfl_xor_sync(0xffffffffu, pA, 4);
            pB += __shfl_xor_sync(0xffffffffu, pB, 4);
            pC += __shfl_xor_sync(0xffffffffu, pC, 4);
            pD += __shfl_xor_sync(0xffffffffu, pD, 4);
            float eA = __expf(pA + qbe);
            float eB = __expf(pB + qbe);
            float eC = __expf(pC + qbe);
            float eD = __expf(pD + qbe);
            den += eA;
            acc.x = fmaf(eA, vA.x, acc.x); acc.y = fmaf(eA, vA.y, acc.y);
            acc.z = fmaf(eA, vA.z, acc.z); acc.w = fmaf(eA, vA.w, acc.w);
            s0 = fmaf(eA, aA.x, s0); s1 = fmaf(eA, aA.y, s1);
            den += eB;
            acc.x = fmaf(eB, vB.x, acc.x); acc.y = fmaf(eB, vB.y, acc.y);
            acc.z = fmaf(eB, vB.z, acc.z); acc.w = fmaf(eB, vB.w, acc.w);
            s0 = fmaf(eB, aB.x, s0); s1 = fmaf(eB, aB.y, s1);
            den += eC;
            acc.x = fmaf(eC, vC.x, acc.x); acc.y = fmaf(eC, vC.y, acc.y);
            acc.z = fmaf(eC, vC.z, acc.z); acc.w = fmaf(eC, vC.w, acc.w);
            s0 = fmaf(eC, aC.x, s0); s1 = fmaf(eC, aC.y, s1);
            den += eD;
            acc.x = fmaf(eD, vD.x, acc.x); acc.y = fmaf(eD, vD.y, acc.y);
            acc.z = fmaf(eD, vD.z, acc.z); acc.w = fmaf(eD, vD.w, acc.w);
            s0 = fmaf(eD, aD.x, s0); s1 = fmaf(eD, aD.y, s1);
        }
        for (; p < end; p++) {
            int sA = __ldg(&g_ssrc[p]);
            float2 aA = *(const float2*)&g_eperm[(size_t)p * EDIM + 2 * l8];
            float4 kA = *(const float4*)&g_k[(size_t)sA * DIM + ch0];
            float4 vA = *(const float4*)&g_v[(size_t)sA * DIM + ch0];
            float pp = q4.x * kA.x + q4.y * kA.y + q4.z * kA.z + q4.w * kA.w
                     + aA.x * qwe2.x + aA.y * qwe2.y;
            pp += __shfl_xor_sync(0xffffffffu, pp, 1);
            pp += __shfl_xor_sync(0xffffffffu, pp, 2);
            pp += __shfl_xor_sync(0xffffffffu, pp, 4);
            float ea = __expf(pp + qbe);
            den += ea;
            acc.x = fmaf(ea, vA.x, acc.x); acc.y = fmaf(ea, vA.y, acc.y);
            acc.z = fmaf(ea, vA.z, acc.z); acc.w = fmaf(ea, vA.w, acc.w);
            s0 = fmaf(ea, aA.x, s0); s1 = fmaf(ea, aA.y, s1);
        }

        float4 ev;
        ev.x = den * sbe[ch0];
        ev.y = den * sbe[ch0 + 1];
        ev.z = den * sbe[ch0 + 2];
        ev.w = den * sbe[ch0 + 3];
#pragma unroll
        for (int jj = 0; jj < 8; jj++) {
            int srcl = (g << 3) | jj;
            float sj0 = __shfl_sync(0xffffffffu, s0, srcl);
            float sj1 = __shfl_sync(0xffffffffu, s1, srcl);
            float4 w0 = *(const float4*)&sWe[2 * jj][ch0];
            float4 w1 = *(const float4*)&sWe[2 * jj + 1][ch0];
            ev.x += sj0 * w0.x + sj1 * w1.x;
            ev.y += sj0 * w0.y + sj1 * w1.y;
            ev.z += sj0 * w0.z + sj1 * w1.z;
            ev.w += sj0 * w0.w + sj1 * w1.w;
        }
        float rden = 1.0f / (den + 1e-16f);
        float o[4] = {(acc.x + ev.x) * rden, (acc.y + ev.y) * rden,
                      (acc.z + ev.z) * rden, (acc.w + ev.w) * rden};

        float4 xr4 = *(const float4*)&g_xr[(size_t)n * DIM + ch0];
        float4 wb0 = *(const float4*)&Wbeta[ch0];
        float4 wb1 = *(const float4*)&Wbeta[DIM + ch0];
        float4 wb2 = *(const float4*)&Wbeta[2 * DIM + ch0];
        float xr[4] = {xr4.x, xr4.y, xr4.z, xr4.w};
        float z = wb0.x * o[0] + wb1.x * xr[0] + wb2.x * (o[0] - xr[0])
                + wb0.y * o[1] + wb1.y * xr[1] + wb2.y * (o[1] - xr[1])
                + wb0.z * o[2] + wb1.z * xr[2] + wb2.z * (o[2] - xr[2])
                + wb0.w * o[3] + wb1.w * xr[3] + wb2.w * (o[3] - xr[3]);
        z = warpSum(z);
        float beta = 1.0f / (1.0f + __expf(-z));

        float4 xv = *(const float4*)&x[(size_t)n * DIM + ch0];
        float xx[4] = {xv.x, xv.y, xv.z, xv.w};
        float tv[4], ts = 0.f;
#pragma unroll
        for (int c = 0; c < 4; c++) {
            tv[c] = xx[c] + beta * xr[c] + (1.0f - beta) * o[c];
            ts += tv[c];
        }
        float mu = warpSum(ts) * (1.0f / 128.0f);
        float vs = 0.f;
#pragma unroll
        for (int c = 0; c < 4; c++) { tv[c] -= mu; vs += tv[c] * tv[c]; }
        float var = warpSum(vs) * (1.0f / 128.0f);
        float inv = rsqrtf(var + 1e-5f);

        float4 gg = *(const float4*)&g1[ch0];
        float4 bb = *(const float4*)&b1[ch0];
        float4 st;
        st.x = tv[0] * inv * gg.x + bb.x;
        st.y = tv[1] * inv * gg.y + bb.y;
        st.z = tv[2] * inv * gg.z + bb.z;
        st.w = tv[3] * inv * gg.w + bb.w;
        *(float4*)&g_h[(size_t)n * DIM + ch0] = st;
    }
}

// ---------------------------------------------------------------------------
// Launch — submission order puts proj_mma at launch #6 for ncu (-s 5 -c 1).
// ---------------------------------------------------------------------------
extern "C" void kernel_launch(void* const* d_in, const int* in_sizes, int n_in,
                              void* d_out, int out_size)
{
    const float* x      = (const float*)d_in[0];
    const void*  eidx   = d_in[1];
    const float* eattr  = (const float*)d_in[2];
    const float* Wq     = (const float*)d_in[3];
    const float* bq     = (const float*)d_in[4];
    const float* Wk     = (const float*)d_in[5];
    const float* bk     = (const float*)d_in[6];
    const float* Wv     = (const float*)d_in[7];
    const float* bv     = (const float*)d_in[8];
    const float* We     = (const float*)d_in[9];
    const float* be     = (const float*)d_in[10];
    const float* Ws     = (const float*)d_in[11];
    const float* bs     = (const float*)d_in[12];
    const float* Wbeta  = (const float*)d_in[13];
    const float* g1     = (const float*)d_in[14];
    const float* b1     = (const float*)d_in[15];
    const float* Wf1    = (const float*)d_in[16];
    const float* bf1    = (const float*)d_in[17];
    const float* Wf2    = (const float*)d_in[18];
    const float* bf2    = (const float*)d_in[19];
    const float* g2     = (const float*)d_in[20];
    const float* b2     = (const float*)d_in[21];

    const int N = in_sizes[0] / DIM;
    const int E = in_sizes[1] / 2;

    float *h, *ff1;
    cudaGetSymbolAddress((void**)&h,   g_h);
    cudaGetSymbolAddress((void**)&ff1, g_ff1);

    static cudaStream_t s1 = nullptr;
    static cudaEvent_t evFork = nullptr, evCsr = nullptr;
    if (!s1) {
        cudaStreamCreate(&s1);
        cudaEventCreateWithFlags(&evFork, cudaEventDisableTiming);
        cudaEventCreateWithFlags(&evCsr, cudaEventDisableTiming);
    }

    const int nb = (N + 1023) / 1024;
    const int gm = (N + 127) / 128;

    // fork
    cudaEventRecord(evFork, 0);
    cudaStreamWaitEvent(s1, evFork, 0);

    // CSR chain part 1 on s1 (launches 1-5)
    detect_idx_kernel<<<1, 32, 0, s1>>>((const int*)eidx);
    zero_cnt_kernel<<<(N + 255) / 256, 256, 0, s1>>>(N);
    convert_idx_kernel<<<(E + 255) / 256, 256, 0, s1>>>(eidx, E);
    scanA_kernel<<<nb, 1024, 0, s1>>>(N);
    scanB_kernel<<<1, 32, 0, s1>>>(nb, N, E);

    // launch #6: proj_mma (ncu target), default stream (independent of CSR)
    dim3 gproj(gm, 4);
    proj_mma_kernel<<<gproj, 256>>>(x, Wq, bq, Wk, bk, Wv, bv, Ws, bs, N);

    // CSR chain part 2 on s1
    scanC_kernel<<<nb, 1024, 0, s1>>>(N);
    scatter_kernel<<<(E + 255) / 256, 256, 0, s1>>>(E);
    permute_eattr_kernel<<<(E * 4 + 255) / 256, 256, 0, s1>>>(eattr, E);
    cudaEventRecord(evCsr, s1);

    // qwe on default stream (after proj)
    qwe_kernel<<<(N + 3) / 4, 256>>>(We, be, N);

    // join
    cudaStreamWaitEvent(0, evCsr, 0);

    node_attn_kernel<<<1184, 256>>>(We, be, x, Wbeta, g1, b1, N);

    dim3 gff1(gm, 4);
    ff1_mma_kernel<<<gff1, 256>>>(h, Wf1, bf1, ff1, N);
    ff2_mma_kernel<<<gm, 256>>>(ff1, Wf2, bf2, (float*)d_out, h, g2, b2, N);
}

// round 9
// speedup vs baseline: 2.9788x; 1.0540x over previous
#include <cuda_runtime.h>
#include <cuda_bf16.h>
#include <math.h>

#define NMAX 50000
#define EMAX 800000
#define DIM  128
#define HEADS 4
#define CH   32
#define EDIM 16
#define QSCALE 0.17677669529663687f   // 1/sqrt(32)

// ---------------------------------------------------------------------------
// Scratch
// ---------------------------------------------------------------------------
__device__ float g_q[NMAX * DIM];
__device__ float g_k[NMAX * DIM];
__device__ float g_v[NMAX * DIM];
__device__ float g_xr[NMAX * DIM];
__device__ float g_h[NMAX * DIM];
__device__ float g_qwe[(size_t)NMAX * 64];
__device__ float g_qbe[NMAX * 4];
__device__ float g_eperm[(size_t)EMAX * EDIM];
__device__ int   g_src[EMAX];
__device__ int   g_dst[EMAX];
__device__ int   g_ssrc[EMAX];
__device__ int   g_eid[EMAX];
__device__ int   g_cnt[NMAX];
__device__ int   g_rowptr[NMAX + 1];
__device__ int   g_woff[NMAX];
__device__ int   g_bsum[64];
__device__ int   g_boff[64];
__device__ int   g_idx64;

// ---------------------------------------------------------------------------
// Helpers
// ---------------------------------------------------------------------------
__device__ __forceinline__ float warpSum(float v) {
#pragma unroll
    for (int off = 16; off; off >>= 1)
        v += __shfl_xor_sync(0xffffffffu, v, off);
    return v;
}

__device__ __forceinline__ float to_tf32(float x) {
    float r;
    asm("cvt.rna.tf32.f32 %0, %1;" : "=f"(r) : "f"(x));
    return r;
}

__device__ __forceinline__ void mma_tf32(float c[4],
                                         unsigned a0, unsigned a1, unsigned a2, unsigned a3,
                                         unsigned b0, unsigned b1) {
    asm volatile(
        "mma.sync.aligned.m16n8k8.row.col.f32.tf32.tf32.f32 "
        "{%0,%1,%2,%3},{%4,%5,%6,%7},{%8,%9},{%0,%1,%2,%3};"
        : "+f"(c[0]), "+f"(c[1]), "+f"(c[2]), "+f"(c[3])
        : "r"(a0), "r"(a1), "r"(a2), "r"(a3), "r"(b0), "r"(b1));
}

// ---------------------------------------------------------------------------
// Index detect / convert (+fused histogram)
// ---------------------------------------------------------------------------
__global__ void detect_idx_kernel(const int* raw) {
    if (threadIdx.x == 0) {
        int all_hi_zero = 1, any_lo_nonzero = 0;
        for (int i = 0; i < 256; i++) {
            if (raw[2 * i + 1] != 0) all_hi_zero = 0;
            if (raw[2 * i] != 0) any_lo_nonzero = 1;
        }
        g_idx64 = (all_hi_zero && any_lo_nonzero) ? 1 : 0;
    }
}

__global__ void zero_cnt_kernel(int N) {
    int i = blockIdx.x * blockDim.x + threadIdx.x;
    if (i < N) g_cnt[i] = 0;
}

__global__ void convert_idx_kernel(const void* raw, int E) {
    int i = blockIdx.x * blockDim.x + threadIdx.x;
    if (i >= E) return;
    int s, d;
    if (g_idx64) {
        const long long* p = (const long long*)raw;
        s = (int)p[i];
        d = (int)p[E + i];
    } else {
        const int* p = (const int*)raw;
        s = p[i];
        d = p[E + i];
    }
    g_src[i] = s;
    g_dst[i] = d;
    atomicAdd(&g_cnt[d], 1);
}

// ---------------------------------------------------------------------------
// 3-phase exclusive scan
// ---------------------------------------------------------------------------
__global__ void __launch_bounds__(1024)
scanA_kernel(int N) {
    __shared__ int wsum[32];
    int t = threadIdx.x;
    int i = blockIdx.x * 1024 + t;
    int v = (i < N) ? g_cnt[i] : 0;
    int inc = v;
#pragma unroll
    for (int off = 1; off < 32; off <<= 1) {
        int u = __shfl_up_sync(0xffffffffu, inc, off);
        if ((t & 31) >= off) inc += u;
    }
    if ((t & 31) == 31) wsum[t >> 5] = inc;
    __syncthreads();
    if (t < 32) {
        int w = wsum[t];
        int wi = w;
#pragma unroll
        for (int off = 1; off < 32; off <<= 1) {
            int u = __shfl_up_sync(0xffffffffu, wi, off);
            if (t >= off) wi += u;
        }
        wsum[t] = wi - w;
    }
    __syncthreads();
    int exc = inc - v + wsum[t >> 5];
    if (i < N) g_rowptr[i] = exc;
    if (t == 1023) g_bsum[blockIdx.x] = exc + v;
}

__global__ void scanB_kernel(int nb, int N, int E) {
    int lane = threadIdx.x;
    int v0 = (lane < nb) ? g_bsum[lane] : 0;
    int v1 = (32 + lane < nb) ? g_bsum[32 + lane] : 0;
    int i0 = v0, i1 = v1;
#pragma unroll
    for (int off = 1; off < 32; off <<= 1) {
        int u = __shfl_up_sync(0xffffffffu, i0, off);
        if (lane >= off) i0 += u;
        int u2 = __shfl_up_sync(0xffffffffu, i1, off);
        if (lane >= off) i1 += u2;
    }
    int tot0 = __shfl_sync(0xffffffffu, i0, 31);
    i1 += tot0;
    g_boff[lane] = i0 - v0;
    g_boff[32 + lane] = i1 - v1;
    if (lane == 0) g_rowptr[N] = E;
}

__global__ void __launch_bounds__(1024)
scanC_kernel(int N) {
    int i = blockIdx.x * 1024 + threadIdx.x;
    if (i < N) {
        int r = g_rowptr[i] + g_boff[blockIdx.x];
        g_rowptr[i] = r;
        g_woff[i] = r;
    }
}

__global__ void scatter_kernel(int E) {
    int i = blockIdx.x * blockDim.x + threadIdx.x;
    if (i >= E) return;
    int d = g_dst[i];
    int pos = atomicAdd(&g_woff[d], 1);
    g_ssrc[pos] = g_src[i];
    g_eid[pos] = i;
}

__global__ void __launch_bounds__(256)
permute_eattr_kernel(const float* __restrict__ eattr, int E) {
    int i = blockIdx.x * blockDim.x + threadIdx.x;
    if (i >= E * 4) return;
    int p = i >> 2, q = (i & 3) * 4;
    int e = g_eid[p];
    *(float4*)&g_eperm[(size_t)p * EDIM + q] =
        *(const float4*)&eattr[(size_t)e * EDIM + q];
}

// ---------------------------------------------------------------------------
// TF32 MMA core: BK=16, double-buffered smem, ONE sync per k-tile.
// (used by proj_mma) — macro loop var _t avoids capturing caller's t.
// ---------------------------------------------------------------------------
__device__ __forceinline__ void mma_core(
    const float* __restrict__ A, const float* __restrict__ B,
    int M, int K, int Nout, int n_base, int m0,
    float (&acc)[2][8][4], float (&As)[2][128][20], float (&Bs)[2][16][136])
{
    const int tid = threadIdx.x;
    const int lane = tid & 31;
    const int wid = tid >> 5;
    const int warp_m = wid & 3;
    const int warp_n = wid >> 2;

#pragma unroll
    for (int i = 0; i < 2; i++)
#pragma unroll
        for (int j = 0; j < 8; j++)
#pragma unroll
            for (int c = 0; c < 4; c++) acc[i][j][c] = 0.f;

    float4 pa[2], pb[2];

#define LOAD_TILE(K0)                                                         \
    {                                                                         \
        const int k0c_ = (K0);                                                \
        _Pragma("unroll")                                                     \
        for (int _t = 0; _t < 2; _t++) {                                      \
            int j = tid + _t * 256;                                           \
            int r = j >> 2, q = (j & 3) * 4;                                  \
            pa[_t] = (m0 + r < M)                                             \
                ? *(const float4*)&A[(size_t)(m0 + r) * K + k0c_ + q]         \
                : make_float4(0.f, 0.f, 0.f, 0.f);                            \
            int br = j >> 5, c4 = (j & 31) * 4;                               \
            pb[_t] = *(const float4*)&B[(size_t)(k0c_ + br) * Nout + n_base + c4]; \
        }                                                                     \
    }

#define STORE_TILE(BUF)                                                       \
    {                                                                         \
        const int buf_ = (BUF);                                               \
        _Pragma("unroll")                                                     \
        for (int _t = 0; _t < 2; _t++) {                                      \
            int j = tid + _t * 256;                                           \
            int r = j >> 2, q = (j & 3) * 4;                                  \
            As[buf_][r][q + 0] = to_tf32(pa[_t].x);                           \
            As[buf_][r][q + 1] = to_tf32(pa[_t].y);                           \
            As[buf_][r][q + 2] = to_tf32(pa[_t].z);                           \
            As[buf_][r][q + 3] = to_tf32(pa[_t].w);                           \
            int br = j >> 5, c4 = (j & 31) * 4;                               \
            Bs[buf_][br][c4 + 0] = to_tf32(pb[_t].x);                         \
            Bs[buf_][br][c4 + 1] = to_tf32(pb[_t].y);                         \
            Bs[buf_][br][c4 + 2] = to_tf32(pb[_t].z);                         \
            Bs[buf_][br][c4 + 3] = to_tf32(pb[_t].w);                         \
        }                                                                     \
    }

    LOAD_TILE(0);
    STORE_TILE(0);
    __syncthreads();

    const int T = K >> 4;
#pragma unroll 2
    for (int t = 0; t < T; t++) {
        if (t + 1 < T) LOAD_TILE((t + 1) << 4);
        const int b = t & 1;
#pragma unroll
        for (int kk = 0; kk < 16; kk += 8) {
            unsigned bf[8][2];
#pragma unroll
            for (int nt = 0; nt < 8; nt++) {
                int n = warp_n * 64 + nt * 8 + (lane >> 2);
                bf[nt][0] = __float_as_uint(Bs[b][kk + (lane & 3)][n]);
                bf[nt][1] = __float_as_uint(Bs[b][kk + 4 + (lane & 3)][n]);
            }
#pragma unroll
            for (int mt = 0; mt < 2; mt++) {
                int r0 = warp_m * 32 + mt * 16 + (lane >> 2);
                unsigned a0 = __float_as_uint(As[b][r0][kk + (lane & 3)]);
                unsigned a1 = __float_as_uint(As[b][r0 + 8][kk + (lane & 3)]);
                unsigned a2 = __float_as_uint(As[b][r0][kk + 4 + (lane & 3)]);
                unsigned a3 = __float_as_uint(As[b][r0 + 8][kk + 4 + (lane & 3)]);
#pragma unroll
                for (int nt = 0; nt < 8; nt++)
                    mma_tf32(acc[mt][nt], a0, a1, a2, a3, bf[nt][0], bf[nt][1]);
            }
        }
        if (t + 1 < T) STORE_TILE((t + 1) & 1);
        __syncthreads();
    }
#undef LOAD_TILE
#undef STORE_TILE
}

// ---------------------------------------------------------------------------
// proj4 (q/k/v/skip) via tensor cores; q scaled at store.
// ---------------------------------------------------------------------------
__global__ void __launch_bounds__(256)
proj_mma_kernel(const float* __restrict__ A,
                const float* __restrict__ Wq, const float* __restrict__ bq,
                const float* __restrict__ Wk, const float* __restrict__ bk,
                const float* __restrict__ Wv, const float* __restrict__ bv,
                const float* __restrict__ Ws, const float* __restrict__ bs,
                int M)
{
    const float* B; const float* bias; float* C; float scale;
    switch (blockIdx.y) {
        case 0: B = Wq; bias = bq; C = g_q;  scale = QSCALE; break;
        case 1: B = Wk; bias = bk; C = g_k;  scale = 1.f;    break;
        case 2: B = Wv; bias = bv; C = g_v;  scale = 1.f;    break;
        default: B = Ws; bias = bs; C = g_xr; scale = 1.f;   break;
    }
    __shared__ float As[2][128][20];
    __shared__ float Bs[2][16][136];
    float acc[2][8][4];
    const int m0 = blockIdx.x * 128;
    mma_core(A, B, M, DIM, DIM, 0, m0, acc, As, Bs);

    const int lane = threadIdx.x & 31;
    const int wid = threadIdx.x >> 5;
    const int warp_m = wid & 3, warp_n = wid >> 2;
#pragma unroll
    for (int mt = 0; mt < 2; mt++)
#pragma unroll
        for (int h2 = 0; h2 < 2; h2++) {
            int m = m0 + warp_m * 32 + mt * 16 + (lane >> 2) + h2 * 8;
            if (m >= M) continue;
#pragma unroll
            for (int nt = 0; nt < 8; nt++) {
                int col = warp_n * 64 + nt * 8 + (lane & 3) * 2;
                float2 st;
                st.x = (acc[mt][nt][h2 * 2]     + __ldg(&bias[col]))     * scale;
                st.y = (acc[mt][nt][h2 * 2 + 1] + __ldg(&bias[col + 1])) * scale;
                *(float2*)&C[(size_t)m * DIM + col] = st;
            }
        }
}

// ---------------------------------------------------------------------------
// Fused FFN: out = LN( h + relu(h@Wf1+bf1)@Wf2 + bf2 ; g2,b2 )
// Per block: 128 rows. H tile staged once; T = intermediate chunk in smem.
// Dynamic smem: H[128][132] + T[128][132] + Bs[2][16][136]  (~149 KB)
// ---------------------------------------------------------------------------
#define FFN_SMEM_FLOATS (2 * 128 * 132 + 2 * 16 * 136)

__global__ void __launch_bounds__(256)
ffn_fused_kernel(const float* __restrict__ A, const float* __restrict__ Wf1,
                 const float* __restrict__ bf1, const float* __restrict__ Wf2,
                 const float* __restrict__ bf2, float* __restrict__ C,
                 const float* __restrict__ gamma, const float* __restrict__ betap,
                 int M)
{
    extern __shared__ float sm[];
    float (*H)[132] = (float(*)[132])sm;
    float (*T)[132] = (float(*)[132])(sm + 128 * 132);
    float (*Bs)[16][136] = (float(*)[16][136])(sm + 2 * 128 * 132);

    const int tid = threadIdx.x;
    const int lane = tid & 31;
    const int wid = tid >> 5;
    const int warp_m = wid & 3;
    const int warp_n = wid >> 2;
    const int m0 = blockIdx.x * 128;

    // stage H tile once (tf32-rounded): also serves as residual source later
#pragma unroll
    for (int t = 0; t < 16; t++) {
        int j = tid + t * 256;
        int r = j >> 5, c4 = (j & 31) * 4;
        float4 v = (m0 + r < M) ? *(const float4*)&A[(size_t)(m0 + r) * DIM + c4]
                                : make_float4(0.f, 0.f, 0.f, 0.f);
        H[r][c4 + 0] = to_tf32(v.x);
        H[r][c4 + 1] = to_tf32(v.y);
        H[r][c4 + 2] = to_tf32(v.z);
        H[r][c4 + 3] = to_tf32(v.w);
    }
    __syncthreads();

    float acc2[2][8][4];
#pragma unroll
    for (int i = 0; i < 2; i++)
#pragma unroll
        for (int j = 0; j < 8; j++)
#pragma unroll
            for (int c = 0; c < 4; c++) acc2[i][j][c] = 0.f;

    float4 pbv[2];

#define LOADB1(CH_, T0)                                                       \
    {                                                                         \
        _Pragma("unroll")                                                     \
        for (int _t = 0; _t < 2; _t++) {                                      \
            int j = tid + _t * 256;                                           \
            int br = j >> 5, c4 = (j & 31) * 4;                               \
            pbv[_t] = *(const float4*)&Wf1[(size_t)((T0) * 16 + br) * 512     \
                                           + (CH_) * 128 + c4];               \
        }                                                                     \
    }
#define LOADB2(CH_, T0)                                                       \
    {                                                                         \
        _Pragma("unroll")                                                     \
        for (int _t = 0; _t < 2; _t++) {                                      \
            int j = tid + _t * 256;                                           \
            int br = j >> 5, c4 = (j & 31) * 4;                               \
            pbv[_t] = *(const float4*)&Wf2[(size_t)((CH_) * 128 + (T0) * 16 + br) * 128 + c4]; \
        }                                                                     \
    }
#define STOREB(BUF)                                                           \
    {                                                                         \
        const int buf_ = (BUF);                                               \
        _Pragma("unroll")                                                     \
        for (int _t = 0; _t < 2; _t++) {                                      \
            int j = tid + _t * 256;                                           \
            int br = j >> 5, c4 = (j & 31) * 4;                               \
            Bs[buf_][br][c4 + 0] = to_tf32(pbv[_t].x);                        \
            Bs[buf_][br][c4 + 1] = to_tf32(pbv[_t].y);                        \
            Bs[buf_][br][c4 + 2] = to_tf32(pbv[_t].z);                        \
            Bs[buf_][br][c4 + 3] = to_tf32(pbv[_t].w);                        \
        }                                                                     \
    }

#define GEMM_STEP(ACC, ASRC, B_, KGLOB)                                       \
    {                                                                         \
        _Pragma("unroll")                                                     \
        for (int kk0 = 0; kk0 < 16; kk0 += 8) {                               \
            int kk = (KGLOB) + kk0;                                           \
            unsigned bf[8][2];                                                \
            _Pragma("unroll")                                                 \
            for (int nt = 0; nt < 8; nt++) {                                  \
                int n = warp_n * 64 + nt * 8 + (lane >> 2);                   \
                bf[nt][0] = __float_as_uint(Bs[B_][kk0 + (lane & 3)][n]);     \
                bf[nt][1] = __float_as_uint(Bs[B_][kk0 + 4 + (lane & 3)][n]); \
            }                                                                 \
            _Pragma("unroll")                                                 \
            for (int mt = 0; mt < 2; mt++) {                                  \
                int r0 = warp_m * 32 + mt * 16 + (lane >> 2);                 \
                unsigned a0 = __float_as_uint(ASRC[r0][kk + (lane & 3)]);     \
                unsigned a1 = __float_as_uint(ASRC[r0 + 8][kk + (lane & 3)]); \
                unsigned a2 = __float_as_uint(ASRC[r0][kk + 4 + (lane & 3)]); \
                unsigned a3 = __float_as_uint(ASRC[r0 + 8][kk + 4 + (lane & 3)]); \
                _Pragma("unroll")                                             \
                for (int nt = 0; nt < 8; nt++)                                \
                    mma_tf32(ACC[mt][nt], a0, a1, a2, a3, bf[nt][0], bf[nt][1]); \
            }                                                                 \
        }                                                                     \
    }

#pragma unroll 1
    for (int c = 0; c < 4; c++) {
        // ---- GEMM1: acc1 = H @ Wf1[:, c*128 : c*128+128]
        float acc1[2][8][4];
#pragma unroll
        for (int i = 0; i < 2; i++)
#pragma unroll
            for (int j = 0; j < 8; j++)
#pragma unroll
                for (int cc = 0; cc < 4; cc++) acc1[i][j][cc] = 0.f;

        LOADB1(c, 0);
        STOREB(0);
        __syncthreads();
#pragma unroll
        for (int t = 0; t < 8; t++) {
            if (t < 7) LOADB1(c, t + 1);
            GEMM_STEP(acc1, H, t & 1, t * 16);
            if (t < 7) STOREB((t + 1) & 1);
            __syncthreads();
        }

        // ---- epilogue: T = tf32(relu(acc1 + bf1[c*128+..]))
#pragma unroll
        for (int mt = 0; mt < 2; mt++)
#pragma unroll
            for (int h2 = 0; h2 < 2; h2++) {
                int row = warp_m * 32 + mt * 16 + (lane >> 2) + h2 * 8;
#pragma unroll
                for (int nt = 0; nt < 8; nt++) {
                    int col = warp_n * 64 + nt * 8 + (lane & 3) * 2;
                    int gcol = c * 128 + col;
                    float t0 = fmaxf(acc1[mt][nt][h2 * 2]     + __ldg(&bf1[gcol]), 0.f);
                    float t1 = fmaxf(acc1[mt][nt][h2 * 2 + 1] + __ldg(&bf1[gcol + 1]), 0.f);
                    T[row][col]     = to_tf32(t0);
                    T[row][col + 1] = to_tf32(t1);
                }
            }

        // ---- GEMM2: acc2 += T @ Wf2[c*128 : c*128+128, :]
        LOADB2(c, 0);
        STOREB(0);
        __syncthreads();   // covers T stores too
#pragma unroll
        for (int t = 0; t < 8; t++) {
            if (t < 7) LOADB2(c, t + 1);
            GEMM_STEP(acc2, T, t & 1, t * 16);
            if (t < 7) STOREB((t + 1) & 1);
            __syncthreads();
        }
    }
#undef LOADB1
#undef LOADB2
#undef STOREB
#undef GEMM_STEP

    // ---- LN epilogue: tv = acc2 + bf2 + h(residual, from H smem pre-rounding ok?
    //      use global A for exact residual); LN(g2,b2) -> C
    float (*pr)[2] = (float(*)[2])H;   // alias (H no longer needed)
    // NOTE: residual read from global A (exact fp32, not tf32-rounded H)
    float mu[2][2];
#pragma unroll
    for (int mt = 0; mt < 2; mt++)
#pragma unroll
        for (int h2 = 0; h2 < 2; h2++) {
            int row = warp_m * 32 + mt * 16 + (lane >> 2) + h2 * 8;
            int m = m0 + row;
            float s = 0.f;
#pragma unroll
            for (int nt = 0; nt < 8; nt++) {
                int col = warp_n * 64 + nt * 8 + (lane & 3) * 2;
                float r0 = (m < M) ? __ldg(&A[(size_t)m * DIM + col])     : 0.f;
                float r1 = (m < M) ? __ldg(&A[(size_t)m * DIM + col + 1]) : 0.f;
                float t0 = acc2[mt][nt][h2 * 2]     + __ldg(&bf2[col])     + r0;
                float t1 = acc2[mt][nt][h2 * 2 + 1] + __ldg(&bf2[col + 1]) + r1;
                acc2[mt][nt][h2 * 2] = t0;
                acc2[mt][nt][h2 * 2 + 1] = t1;
                s += t0 + t1;
            }
            s += __shfl_xor_sync(0xffffffffu, s, 1);
            s += __shfl_xor_sync(0xffffffffu, s, 2);
            if ((lane & 3) == 0) pr[row][warp_n] = s;
        }
    __syncthreads();
#pragma unroll
    for (int mt = 0; mt < 2; mt++)
#pragma unroll
        for (int h2 = 0; h2 < 2; h2++) {
            int row = warp_m * 32 + mt * 16 + (lane >> 2) + h2 * 8;
            mu[mt][h2] = (pr[row][0] + pr[row][1]) * (1.0f / 128.0f);
        }
    __syncthreads();
#pragma unroll
    for (int mt = 0; mt < 2; mt++)
#pragma unroll
        for (int h2 = 0; h2 < 2; h2++) {
            int row = warp_m * 32 + mt * 16 + (lane >> 2) + h2 * 8;
            float vs = 0.f;
#pragma unroll
            for (int nt = 0; nt < 8; nt++) {
                float d0 = acc2[mt][nt][h2 * 2]     - mu[mt][h2];
                float d1 = acc2[mt][nt][h2 * 2 + 1] - mu[mt][h2];
                vs += d0 * d0 + d1 * d1;
            }
            vs += __shfl_xor_sync(0xffffffffu, vs, 1);
            vs += __shfl_xor_sync(0xffffffffu, vs, 2);
            if ((lane & 3) == 0) pr[row][warp_n] = vs;
        }
    __syncthreads();
#pragma unroll
    for (int mt = 0; mt < 2; mt++)
#pragma unroll
        for (int h2 = 0; h2 < 2; h2++) {
            int row = warp_m * 32 + mt * 16 + (lane >> 2) + h2 * 8;
            int m = m0 + row;
            if (m >= M) continue;
            float var = (pr[row][0] + pr[row][1]) * (1.0f / 128.0f);
            float inv = rsqrtf(var + 1e-5f);
#pragma unroll
            for (int nt = 0; nt < 8; nt++) {
                int col = warp_n * 64 + nt * 8 + (lane & 3) * 2;
                float2 st;
                st.x = (acc2[mt][nt][h2 * 2]     - mu[mt][h2]) * inv * __ldg(&gamma[col])     + __ldg(&betap[col]);
                st.y = (acc2[mt][nt][h2 * 2 + 1] - mu[mt][h2]) * inv * __ldg(&gamma[col + 1]) + __ldg(&betap[col + 1]);
                *(float2*)&C[(size_t)m * DIM + col] = st;
            }
        }
}

// ---------------------------------------------------------------------------
// qwe precompute
// ---------------------------------------------------------------------------
__global__ void __launch_bounds__(256)
qwe_kernel(const float* __restrict__ We, const float* __restrict__ be, int N)
{
    __shared__ float sWe[EDIM * DIM];
    __shared__ float sq[4][DIM];
    __shared__ float sbe[DIM];
    int tid = threadIdx.x;
    for (int i = tid; i < EDIM * DIM; i += 256) sWe[i] = We[i];
    if (tid < DIM) sbe[tid] = be[tid];
    int n0 = blockIdx.x * 4;
    for (int i = tid; i < 4 * DIM; i += 256) {
        int nn = i >> 7, c = i & 127;
        sq[nn][c] = (n0 + nn < N) ? g_q[(size_t)(n0 + nn) * DIM + c] : 0.f;
    }
    __syncthreads();
    int nn = tid >> 6, r = tid & 63, h = r >> 4, i = r & 15;
    int n = n0 + nn;
    if (n >= N) return;
    float a = 0.f;
#pragma unroll
    for (int c = 0; c < 32; c++)
        a = fmaf(sq[nn][h * 32 + c], sWe[i * DIM + h * 32 + c], a);
    g_qwe[(size_t)n * 64 + h * 16 + i] = a;
    if (i == 0) {
        float qb = 0.f;
#pragma unroll
        for (int c = 0; c < 32; c++)
            qb = fmaf(sq[nn][h * 32 + c], sbe[h * 32 + c], qb);
        g_qbe[n * 4 + h] = qb;
    }
}

// ---------------------------------------------------------------------------
// Warp-per-node attention with 4-edge software pipeline + beta gate + LN1.
// ---------------------------------------------------------------------------
__global__ void __launch_bounds__(256)
node_attn_kernel(const float* __restrict__ We, const float* __restrict__ be,
                 const float* __restrict__ x,  const float* __restrict__ Wbeta,
                 const float* __restrict__ g1, const float* __restrict__ b1,
                 int N)
{
    __shared__ float sWe[EDIM][DIM];
    __shared__ float sbe[DIM];
    for (int i = threadIdx.x; i < EDIM * DIM; i += 256)
        ((float*)sWe)[i] = We[i];
    if (threadIdx.x < DIM) sbe[threadIdx.x] = be[threadIdx.x];
    __syncthreads();

    const int lane = threadIdx.x & 31;
    const int g = lane >> 3;
    const int l8 = lane & 7;
    const int ch0 = g * 32 + l8 * 4;
    const int warp = blockIdx.x * (blockDim.x >> 5) + (threadIdx.x >> 5);
    const int nwarps = gridDim.x * (blockDim.x >> 5);

    for (int n = warp; n < N; n += nwarps) {
        float4 q4 = *(const float4*)&g_q[(size_t)n * DIM + ch0];
        float2 qwe2 = *(const float2*)&g_qwe[(size_t)n * 64 + g * 16 + 2 * l8];
        float qbe = g_qbe[n * 4 + g];

        float4 acc = make_float4(0.f, 0.f, 0.f, 0.f);
        float s0 = 0.f, s1 = 0.f, den = 0.f;

        int beg = g_rowptr[n], end = g_rowptr[n + 1];
        int p = beg;
        for (; p + 4 <= end; p += 4) {
            int sA = __ldg(&g_ssrc[p]);
            int sB = __ldg(&g_ssrc[p + 1]);
            int sC = __ldg(&g_ssrc[p + 2]);
            int sD = __ldg(&g_ssrc[p + 3]);
            float4 kA = *(const float4*)&g_k[(size_t)sA * DIM + ch0];
            float4 kB = *(const float4*)&g_k[(size_t)sB * DIM + ch0];
            float4 kC = *(const float4*)&g_k[(size_t)sC * DIM + ch0];
            float4 kD = *(const float4*)&g_k[(size_t)sD * DIM + ch0];
            float4 vA = *(const float4*)&g_v[(size_t)sA * DIM + ch0];
            float4 vB = *(const float4*)&g_v[(size_t)sB * DIM + ch0];
            float4 vC = *(const float4*)&g_v[(size_t)sC * DIM + ch0];
            float4 vD = *(const float4*)&g_v[(size_t)sD * DIM + ch0];
            float2 aA = *(const float2*)&g_eperm[(size_t)p * EDIM + 2 * l8];
            float2 aB = *(const float2*)&g_eperm[(size_t)(p + 1) * EDIM + 2 * l8];
            float2 aC = *(const float2*)&g_eperm[(size_t)(p + 2) * EDIM + 2 * l8];
            float2 aD = *(const float2*)&g_eperm[(size_t)(p + 3) * EDIM + 2 * l8];

            float pA = q4.x * kA.x + q4.y * kA.y + q4.z * kA.z + q4.w * kA.w
                     + aA.x * qwe2.x + aA.y * qwe2.y;
            float pB = q4.x * kB.x + q4.y * kB.y + q4.z * kB.z + q4.w * kB.w
                     + aB.x * qwe2.x + aB.y * qwe2.y;
            float pC = q4.x * kC.x + q4.y * kC.y + q4.z * kC.z + q4.w * kC.w
                     + aC.x * qwe2.x + aC.y * qwe2.y;
            float pD = q4.x * kD.x + q4.y * kD.y + q4.z * kD.z + q4.w * kD.w
                     + aD.x * qwe2.x + aD.y * qwe2.y;
            pA += __shfl_xor_sync(0xffffffffu, pA, 1);
            pB += __shfl_xor_sync(0xffffffffu, pB, 1);
            pC += __shfl_xor_sync(0xffffffffu, pC, 1);
            pD += __shfl_xor_sync(0xffffffffu, pD, 1);
            pA += __shfl_xor_sync(0xffffffffu, pA, 2);
            pB += __shfl_xor_sync(0xffffffffu, pB, 2);
            pC += __shfl_xor_sync(0xffffffffu, pC, 2);
            pD += __shfl_xor_sync(0xffffffffu, pD, 2);
            pA += __shfl_xor_sync(0xffffffffu, pA, 4);
            pB += __shfl_xor_sync(0xffffffffu, pB, 4);
            pC += __shfl_xor_sync(0xffffffffu, pC, 4);
            pD += __shfl_xor_sync(0xffffffffu, pD, 4);
            float eA = __expf(pA + qbe);
            float eB = __expf(pB + qbe);
            float eC = __expf(pC + qbe);
            float eD = __expf(pD + qbe);
            den += eA;
            acc.x = fmaf(eA, vA.x, acc.x); acc.y = fmaf(eA, vA.y, acc.y);
            acc.z = fmaf(eA, vA.z, acc.z); acc.w = fmaf(eA, vA.w, acc.w);
            s0 = fmaf(eA, aA.x, s0); s1 = fmaf(eA, aA.y, s1);
            den += eB;
            acc.x = fmaf(eB, vB.x, acc.x); acc.y = fmaf(eB, vB.y, acc.y);
            acc.z = fmaf(eB, vB.z, acc.z); acc.w = fmaf(eB, vB.w, acc.w);
            s0 = fmaf(eB, aB.x, s0); s1 = fmaf(eB, aB.y, s1);
            den += eC;
            acc.x = fmaf(eC, vC.x, acc.x); acc.y = fmaf(eC, vC.y, acc.y);
            acc.z = fmaf(eC, vC.z, acc.z); acc.w = fmaf(eC, vC.w, acc.w);
            s0 = fmaf(eC, aC.x, s0); s1 = fmaf(eC, aC.y, s1);
            den += eD;
            acc.x = fmaf(eD, vD.x, acc.x); acc.y = fmaf(eD, vD.y, acc.y);
            acc.z = fmaf(eD, vD.z, acc.z); acc.w = fmaf(eD, vD.w, acc.w);
            s0 = fmaf(eD, aD.x, s0); s1 = fmaf(eD, aD.y, s1);
        }
        for (; p < end; p++) {
            int sA = __ldg(&g_ssrc[p]);
            float2 aA = *(const float2*)&g_eperm[(size_t)p * EDIM + 2 * l8];
            float4 kA = *(const float4*)&g_k[(size_t)sA * DIM + ch0];
            float4 vA = *(const float4*)&g_v[(size_t)sA * DIM + ch0];
            float pp = q4.x * kA.x + q4.y * kA.y + q4.z * kA.z + q4.w * kA.w
                     + aA.x * qwe2.x + aA.y * qwe2.y;
            pp += __shfl_xor_sync(0xffffffffu, pp, 1);
            pp += __shfl_xor_sync(0xffffffffu, pp, 2);
            pp += __shfl_xor_sync(0xffffffffu, pp, 4);
            float ea = __expf(pp + qbe);
            den += ea;
            acc.x = fmaf(ea, vA.x, acc.x); acc.y = fmaf(ea, vA.y, acc.y);
            acc.z = fmaf(ea, vA.z, acc.z); acc.w = fmaf(ea, vA.w, acc.w);
            s0 = fmaf(ea, aA.x, s0); s1 = fmaf(ea, aA.y, s1);
        }

        float4 ev;
        ev.x = den * sbe[ch0];
        ev.y = den * sbe[ch0 + 1];
        ev.z = den * sbe[ch0 + 2];
        ev.w = den * sbe[ch0 + 3];
#pragma unroll
        for (int jj = 0; jj < 8; jj++) {
            int srcl = (g << 3) | jj;
            float sj0 = __shfl_sync(0xffffffffu, s0, srcl);
            float sj1 = __shfl_sync(0xffffffffu, s1, srcl);
            float4 w0 = *(const float4*)&sWe[2 * jj][ch0];
            float4 w1 = *(const float4*)&sWe[2 * jj + 1][ch0];
            ev.x += sj0 * w0.x + sj1 * w1.x;
            ev.y += sj0 * w0.y + sj1 * w1.y;
            ev.z += sj0 * w0.z + sj1 * w1.z;
            ev.w += sj0 * w0.w + sj1 * w1.w;
        }
        float rden = 1.0f / (den + 1e-16f);
        float o[4] = {(acc.x + ev.x) * rden, (acc.y + ev.y) * rden,
                      (acc.z + ev.z) * rden, (acc.w + ev.w) * rden};

        float4 xr4 = *(const float4*)&g_xr[(size_t)n * DIM + ch0];
        float4 wb0 = *(const float4*)&Wbeta[ch0];
        float4 wb1 = *(const float4*)&Wbeta[DIM + ch0];
        float4 wb2 = *(const float4*)&Wbeta[2 * DIM + ch0];
        float xr[4] = {xr4.x, xr4.y, xr4.z, xr4.w};
        float z = wb0.x * o[0] + wb1.x * xr[0] + wb2.x * (o[0] - xr[0])
                + wb0.y * o[1] + wb1.y * xr[1] + wb2.y * (o[1] - xr[1])
                + wb0.z * o[2] + wb1.z * xr[2] + wb2.z * (o[2] - xr[2])
                + wb0.w * o[3] + wb1.w * xr[3] + wb2.w * (o[3] - xr[3]);
        z = warpSum(z);
        float beta = 1.0f / (1.0f + __expf(-z));

        float4 xv = *(const float4*)&x[(size_t)n * DIM + ch0];
        float xx[4] = {xv.x, xv.y, xv.z, xv.w};
        float tv[4], ts = 0.f;
#pragma unroll
        for (int c = 0; c < 4; c++) {
            tv[c] = xx[c] + beta * xr[c] + (1.0f - beta) * o[c];
            ts += tv[c];
        }
        float mu = warpSum(ts) * (1.0f / 128.0f);
        float vs = 0.f;
#pragma unroll
        for (int c = 0; c < 4; c++) { tv[c] -= mu; vs += tv[c] * tv[c]; }
        float var = warpSum(vs) * (1.0f / 128.0f);
        float inv = rsqrtf(var + 1e-5f);

        float4 gg = *(const float4*)&g1[ch0];
        float4 bb = *(const float4*)&b1[ch0];
        float4 st;
        st.x = tv[0] * inv * gg.x + bb.x;
        st.y = tv[1] * inv * gg.y + bb.y;
        st.z = tv[2] * inv * gg.z + bb.z;
        st.w = tv[3] * inv * gg.w + bb.w;
        *(float4*)&g_h[(size_t)n * DIM + ch0] = st;
    }
}

// ---------------------------------------------------------------------------
// Launch (fork-join streams: CSR chain || projections; fused FFN)
// ---------------------------------------------------------------------------
extern "C" void kernel_launch(void* const* d_in, const int* in_sizes, int n_in,
                              void* d_out, int out_size)
{
    const float* x      = (const float*)d_in[0];
    const void*  eidx   = d_in[1];
    const float* eattr  = (const float*)d_in[2];
    const float* Wq     = (const float*)d_in[3];
    const float* bq     = (const float*)d_in[4];
    const float* Wk     = (const float*)d_in[5];
    const float* bk     = (const float*)d_in[6];
    const float* Wv     = (const float*)d_in[7];
    const float* bv     = (const float*)d_in[8];
    const float* We     = (const float*)d_in[9];
    const float* be     = (const float*)d_in[10];
    const float* Ws     = (const float*)d_in[11];
    const float* bs     = (const float*)d_in[12];
    const float* Wbeta  = (const float*)d_in[13];
    const float* g1     = (const float*)d_in[14];
    const float* b1     = (const float*)d_in[15];
    const float* Wf1    = (const float*)d_in[16];
    const float* bf1    = (const float*)d_in[17];
    const float* Wf2    = (const float*)d_in[18];
    const float* bf2    = (const float*)d_in[19];
    const float* g2     = (const float*)d_in[20];
    const float* b2     = (const float*)d_in[21];

    const int N = in_sizes[0] / DIM;
    const int E = in_sizes[1] / 2;

    float* h;
    cudaGetSymbolAddress((void**)&h, g_h);

    static cudaStream_t s1 = nullptr;
    static cudaEvent_t evFork = nullptr, evCsr = nullptr;
    if (!s1) {
        cudaStreamCreate(&s1);
        cudaEventCreateWithFlags(&evFork, cudaEventDisableTiming);
        cudaEventCreateWithFlags(&evCsr, cudaEventDisableTiming);
        cudaFuncSetAttribute(ffn_fused_kernel,
                             cudaFuncAttributeMaxDynamicSharedMemorySize,
                             FFN_SMEM_FLOATS * 4);
    }

    const int nb = (N + 1023) / 1024;
    const int gm = (N + 127) / 128;

    // fork
    cudaEventRecord(evFork, 0);
    cudaStreamWaitEvent(s1, evFork, 0);

    // CSR chain on s1
    detect_idx_kernel<<<1, 32, 0, s1>>>((const int*)eidx);
    zero_cnt_kernel<<<(N + 255) / 256, 256, 0, s1>>>(N);
    convert_idx_kernel<<<(E + 255) / 256, 256, 0, s1>>>(eidx, E);
    scanA_kernel<<<nb, 1024, 0, s1>>>(N);
    scanB_kernel<<<1, 32, 0, s1>>>(nb, N, E);
    scanC_kernel<<<nb, 1024, 0, s1>>>(N);
    scatter_kernel<<<(E + 255) / 256, 256, 0, s1>>>(E);
    permute_eattr_kernel<<<(E * 4 + 255) / 256, 256, 0, s1>>>(eattr, E);
    cudaEventRecord(evCsr, s1);

    // projections + qwe on default stream
    dim3 gproj(gm, 4);
    proj_mma_kernel<<<gproj, 256>>>(x, Wq, bq, Wk, bk, Wv, bv, Ws, bs, N);
    qwe_kernel<<<(N + 3) / 4, 256>>>(We, be, N);

    // join
    cudaStreamWaitEvent(0, evCsr, 0);

    node_attn_kernel<<<1184, 256>>>(We, be, x, Wbeta, g1, b1, N);

    // fused FFN + residual + LN2
    ffn_fused_kernel<<<gm, 256, FFN_SMEM_FLOATS * 4>>>(
        h, Wf1, bf1, Wf2, bf2, (float*)d_out, g2, b2, N);
}